// round 7
// baseline (speedup 1.0000x reference)
#include <cuda_runtime.h>
#include <cuda_bf16.h>
#include <cstdint>

#define DIM   768
#define NH    12
#define HD    64
#define GH    48           // grid H = W
#define HW    2304         // 48*48
#define RANK  32
#define QK_SCALE 0.125f    // 64^-0.5
#define FACT_S 1.0f
#define NT    36           // kv tiles of 64

typedef unsigned long long u64;

// ---------------- packed helpers --------------------------------------------
__device__ __forceinline__ u64 pack2f(float a, float b) {
    u64 r;
    asm("mov.b64 %0, {%1, %2};" : "=l"(r)
        : "r"(__float_as_uint(a)), "r"(__float_as_uint(b)));
    return r;
}
__device__ __forceinline__ void unpack2f(u64 v, float& a, float& b) {
    unsigned x, y;
    asm("mov.b64 {%0, %1}, %2;" : "=r"(x), "=r"(y) : "l"(v));
    a = __uint_as_float(x);
    b = __uint_as_float(y);
}
__device__ __forceinline__ void ffma2(u64& d, u64 a, u64 b) {
    asm("fma.rn.f32x2 %0, %1, %2, %0;" : "+l"(d) : "l"(a), "l"(b));
}
__device__ __forceinline__ uint32_t cvt_bf16x2(float a, float b) {
    uint32_t r;
    asm("cvt.rn.bf16x2.f32 %0, %1, %2;" : "=r"(r) : "f"(b), "f"(a));
    return r;
}
__device__ __forceinline__ void split2(float a, float b, uint32_t& hi, uint32_t& lo) {
    uint32_t h = cvt_bf16x2(a, b);
    float ra = __uint_as_float(h << 16);
    float rb = __uint_as_float(h & 0xffff0000u);
    hi = h;
    lo = cvt_bf16x2(a - ra, b - rb);
}

// ---------------- mma / ldmatrix / cp.async helpers --------------------------
__device__ __forceinline__ void mma16816(float c[4], const uint32_t a[4],
                                         uint32_t b0, uint32_t b1) {
    asm volatile(
        "mma.sync.aligned.m16n8k16.row.col.f32.bf16.bf16.f32 "
        "{%0,%1,%2,%3}, {%4,%5,%6,%7}, {%8,%9}, {%0,%1,%2,%3};"
        : "+f"(c[0]), "+f"(c[1]), "+f"(c[2]), "+f"(c[3])
        : "r"(a[0]), "r"(a[1]), "r"(a[2]), "r"(a[3]), "r"(b0), "r"(b1));
}
__device__ __forceinline__ void ldsm2(uint32_t& r0, uint32_t& r1, uint32_t addr) {
    asm volatile("ldmatrix.sync.aligned.m8n8.x2.shared.b16 {%0,%1}, [%2];"
                 : "=r"(r0), "=r"(r1) : "r"(addr));
}
__device__ __forceinline__ void ldsm4(uint32_t r[4], uint32_t addr) {
    asm volatile("ldmatrix.sync.aligned.m8n8.x4.shared.b16 {%0,%1,%2,%3}, [%4];"
                 : "=r"(r[0]), "=r"(r[1]), "=r"(r[2]), "=r"(r[3]) : "r"(addr));
}
__device__ __forceinline__ uint32_t smem_to_u32(const void* smem_ptr) {
    uint32_t addr;
    asm("{ .reg .u64 tmp; cvta.to.shared.u64 tmp, %1; cvt.u32.u64 %0, tmp; }"
        : "=r"(addr) : "l"(smem_ptr));
    return addr;
}
__device__ __forceinline__ void cp16(uint32_t dst, const void* src) {
    asm volatile("cp.async.cg.shared.global [%0], [%1], 16;"
                 :: "r"(dst), "l"(src));
}
#define CP_COMMIT() asm volatile("cp.async.commit_group;" ::: "memory")
#define CP_WAIT0()  asm volatile("cp.async.wait_group 0;" ::: "memory")

// ---------------- device scratch (no allocations allowed) ------------------
__device__ float g_A1[DIM * RANK];
__device__ float g_A2[DIM * RANK];
__device__ float g_qkv[HW * 3 * DIM];
__device__ float g_relh[NH * HW * GH];
__device__ float g_relw[NH * HW * GH];
// pre-split inputs / intermediates
__device__ __align__(16) __nv_bfloat16 g_xh[HW * DIM];
__device__ __align__(16) __nv_bfloat16 g_xl[HW * DIM];
__device__ __align__(16) __nv_bfloat16 g_oph[HW * DIM];
__device__ __align__(16) __nv_bfloat16 g_opl[HW * DIM];
// pre-split transposed weights: [N][K] bf16 hi/lo
__device__ __align__(16) __nv_bfloat16 g_wqkvT_h[3 * DIM * DIM];
__device__ __align__(16) __nv_bfloat16 g_wqkvT_l[3 * DIM * DIM];
__device__ __align__(16) __nv_bfloat16 g_wprojT_h[DIM * DIM];
__device__ __align__(16) __nv_bfloat16 g_wprojT_l[DIM * DIM];
// bf16 split K [head][key][dim] and transposed V [head][dim][key]
__device__ __align__(16) __nv_bfloat16 g_kh[NH * HW * HD];
__device__ __align__(16) __nv_bfloat16 g_kl[NH * HW * HD];
__device__ __align__(16) __nv_bfloat16 g_vh[NH * HD * HW];
__device__ __align__(16) __nv_bfloat16 g_vl[NH * HD * HW];

// ---------------- K0: A1 = FacTu @ q_FacTs, A2 = FacTu @ v_FacTs -----------
__global__ void fact_small_kernel(const float* __restrict__ FacTu,
                                  const float* __restrict__ qF,
                                  const float* __restrict__ vF) {
    int idx = blockIdx.x * 256 + threadIdx.x;
    if (idx >= DIM * RANK * 2) return;
    int which = idx / (DIM * RANK);
    int rem = idx - which * (DIM * RANK);
    int i = rem / RANK, r = rem - (rem / RANK) * RANK;
    const float* F = which ? vF : qF;
    float s = 0.f;
#pragma unroll
    for (int k = 0; k < RANK; k++) s += FacTu[i * RANK + k] * F[k * RANK + r];
    (which ? g_A2 : g_A1)[i * RANK + r] = s;
}

// ---------------- K0b: split x into bf16 hi/lo ------------------------------
__global__ void __launch_bounds__(256) xsplit_kernel(const float* __restrict__ x) {
    int idx = blockIdx.x * 256 + threadIdx.x;
    if (idx >= HW * DIM / 4) return;
    float4 v = *(const float4*)&x[idx * 4];
    uint32_t h0, l0, h1, l1;
    split2(v.x, v.y, h0, l0);
    split2(v.z, v.w, h1, l1);
    *(uint2*)&g_xh[idx * 4] = make_uint2(h0, h1);
    *(uint2*)&g_xl[idx * 4] = make_uint2(l0, l1);
}

// ---------------- K1: transpose + low-rank fold + bf16 split ---------------
__global__ void __launch_bounds__(256)
wsplit_kernel(const float* __restrict__ W, const float* __restrict__ FacTv,
              __nv_bfloat16* __restrict__ WTh, __nv_bfloat16* __restrict__ WTl,
              int NJ, int mode) {
    __shared__ float tile[32 * 33];
    const int tid = threadIdx.x;
    const int j0 = blockIdx.x * 32;
    const int i0 = blockIdx.y * 32;

    {
        const int j = tid & 31;
        const int ib = tid >> 5;
        const float* Aarr = nullptr;
        int jj = j0 + j;
        if (mode) {
            if (jj < DIM) Aarr = g_A1;
            else if (jj >= 2 * DIM) { Aarr = g_A2; jj -= 2 * DIM; }
        }
#pragma unroll
        for (int it = 0; it < 4; it++) {
            int il = ib + it * 8;
            int i = i0 + il;
            float w = W[(size_t)i * NJ + j0 + j];
            if (Aarr) {
                float s = 0.f;
#pragma unroll
                for (int r = 0; r < RANK; r++)
                    s += Aarr[i * RANK + r] * FacTv[r * DIM + jj];
                w += FACT_S * s;
            }
            tile[il * 33 + j] = w;
        }
    }
    __syncthreads();
    {
        const int i = tid & 31;
        const int jb = tid >> 5;
#pragma unroll
        for (int it = 0; it < 4; it++) {
            int jl = jb + it * 8;
            float v = tile[i * 33 + jl];
            __nv_bfloat16 h = __float2bfloat16(v);
            size_t o = (size_t)(j0 + jl) * DIM + i0 + i;
            WTh[o] = h;
            WTl[o] = __float2bfloat16(v - __bfloat162float(h));
        }
    }
}

// ---------------- K2: HMMA GEMM (all-bf16, cp.async, 2 CTA/SM) --------------
#define GS 40                 // smem row stride in bf16 (80B)
#define GARR 10240
#define GBUF 40960
__global__ void __launch_bounds__(256, 2)
hgemm_bf16(const __nv_bfloat16* __restrict__ Ah_,
           const __nv_bfloat16* __restrict__ Al_,
           const __nv_bfloat16* __restrict__ Bh_,
           const __nv_bfloat16* __restrict__ Bl_,
           const float* __restrict__ bias, float* __restrict__ C,
           int M, int N, int K) {
    extern __shared__ __align__(16) char gsm[];
    const uint32_t smb = smem_to_u32(gsm);
    const int tid = threadIdx.x, lane = tid & 31, warp = tid >> 5;
    const int wm = (warp >> 2) * 64, wn = (warp & 3) * 32;
    const int bm = blockIdx.y * 128, bn = blockIdx.x * 128;

#define GB_ISSUE(k0) do { \
        _Pragma("unroll") \
        for (int t = 0; t < 8; t++) { \
            int i = tid + t * 256; \
            int arr = i >> 9, j = i & 511; \
            int row = j >> 2, c = j & 3; \
            const __nv_bfloat16* gptr = (arr == 0) ? Ah_ : (arr == 1) ? Al_ \
                                        : (arr == 2) ? Bh_ : Bl_; \
            int grow = (arr < 2 ? bm : bn) + row; \
            const char* src = (const char*)&gptr[(size_t)grow * K + (k0)] + c * 16; \
            cp16(sb + arr * GARR + row * 80 + c * 16, src); \
        } \
        CP_COMMIT(); \
    } while (0)

    float acc[4][4][4];
#pragma unroll
    for (int a = 0; a < 4; a++)
#pragma unroll
        for (int b = 0; b < 4; b++)
#pragma unroll
            for (int c = 0; c < 4; c++) acc[a][b][c] = 0.f;

    {
        uint32_t sb = smb;
        GB_ISSUE(0);
    }

    const uint32_t aoff = (uint32_t)((lane & 15) * GS + ((lane >> 4) << 3)) * 2;
    const uint32_t boff = (uint32_t)(((lane & 7) + ((lane & 16) >> 1)) * GS + (lane & 8)) * 2;

    const int NKT = K / 32;
    for (int kt = 0; kt < NKT; kt++) {
        CP_WAIT0();
        __syncthreads();
        if (kt + 1 < NKT) {
            uint32_t sb = smb + (uint32_t)((kt + 1) & 1) * GBUF;
            GB_ISSUE((kt + 1) * 32);
        }
        const uint32_t cb = smb + (uint32_t)(kt & 1) * GBUF;
        const uint32_t sAh = cb, sAl = cb + GARR, sBh = cb + 2 * GARR, sBl = cb + 3 * GARR;

#pragma unroll
        for (int ks = 0; ks < 2; ks++) {
            uint32_t ah[4][4], al[4][4];
#pragma unroll
            for (int mt = 0; mt < 4; mt++) {
                uint32_t off = (uint32_t)(wm + mt * 16) * (GS * 2) + (uint32_t)ks * 32 + aoff;
                ldsm4(ah[mt], sAh + off);
                ldsm4(al[mt], sAl + off);
            }
            uint32_t bh[2][4], bl[2][4];
#pragma unroll
            for (int nt = 0; nt < 2; nt++) {
                uint32_t off = (uint32_t)(wn + nt * 16) * (GS * 2) + (uint32_t)ks * 32 + boff;
                ldsm4(bh[nt], sBh + off);
                ldsm4(bl[nt], sBl + off);
            }
#pragma unroll
            for (int mt = 0; mt < 4; mt++)
#pragma unroll
                for (int nt = 0; nt < 4; nt++) {
                    uint32_t b0h = bh[nt >> 1][(nt & 1) * 2];
                    uint32_t b1h = bh[nt >> 1][(nt & 1) * 2 + 1];
                    uint32_t b0l = bl[nt >> 1][(nt & 1) * 2];
                    uint32_t b1l = bl[nt >> 1][(nt & 1) * 2 + 1];
                    mma16816(acc[mt][nt], ah[mt], b0h, b1h);
                    mma16816(acc[mt][nt], al[mt], b0h, b1h);
                    mma16816(acc[mt][nt], ah[mt], b0l, b1l);
                }
        }
        __syncthreads();
    }

    const int gid = lane >> 2, tig = lane & 3;
#pragma unroll
    for (int mt = 0; mt < 4; mt++) {
        int m0 = bm + wm + mt * 16 + gid;
#pragma unroll
        for (int nt = 0; nt < 4; nt++) {
            int n0 = bn + wn + nt * 8 + 2 * tig;
            float bx = bias ? bias[n0] : 0.f;
            float by = bias ? bias[n0 + 1] : 0.f;
            *(float2*)&C[(size_t)m0 * N + n0] =
                make_float2(acc[mt][nt][0] + bx, acc[mt][nt][1] + by);
            *(float2*)&C[(size_t)(m0 + 8) * N + n0] =
                make_float2(acc[mt][nt][2] + bx, acc[mt][nt][3] + by);
        }
    }
}
#define HG_SMEM (2 * GBUF)

// ---------------- K3: rel bias tables ---------------------------------------
__global__ void __launch_bounds__(256) rel_tab2_kernel(const float* __restrict__ rph,
                                                       const float* __restrict__ rpw) {
    __shared__ float Qs[GH * 68];
    __shared__ float Rs[GH * 68];
    const int pos = blockIdx.x;
    const int head = blockIdx.y;
    const int which = blockIdx.z;
    const int tid = threadIdx.x;

    for (int i = tid; i < GH * HD; i += 256) {
        int r = i >> 6, c = i & 63;
        int t = which ? (r * GH + pos) : (pos * GH + r);
        Qs[r * 68 + c] = g_qkv[(size_t)t * (3 * DIM) + head * HD + c];
    }
    const float* rp = which ? rpw : rph;
    for (int i = tid; i < GH * HD; i += 256) {
        int k = i >> 6, c = i & 63;
        Rs[k * 68 + c] = rp[(pos - k + GH - 1) * HD + c];
    }
    __syncthreads();

    const int tx = tid & 15, ty = tid >> 4;
    u64 acc[3][3];
#pragma unroll
    for (int i = 0; i < 3; i++)
#pragma unroll
        for (int j = 0; j < 3; j++) acc[i][j] = 0ull;

    for (int c = 0; c < HD; c += 4) {
        ulonglong2 q[3], r[3];
#pragma unroll
        for (int i = 0; i < 3; i++) q[i] = *(const ulonglong2*)&Qs[(ty * 3 + i) * 68 + c];
#pragma unroll
        for (int j = 0; j < 3; j++) r[j] = *(const ulonglong2*)&Rs[(tx * 3 + j) * 68 + c];
#pragma unroll
        for (int i = 0; i < 3; i++)
#pragma unroll
            for (int j = 0; j < 3; j++) {
                ffma2(acc[i][j], q[i].x, r[j].x);
                ffma2(acc[i][j], q[i].y, r[j].y);
            }
    }

    float* outp = which ? g_relw : g_relh;
#pragma unroll
    for (int i = 0; i < 3; i++) {
        int row = ty * 3 + i;
        int t = which ? (row * GH + pos) : (pos * GH + row);
#pragma unroll
        for (int j = 0; j < 3; j++) {
            float lo, hi;
            unpack2f(acc[i][j], lo, hi);
            outp[((size_t)head * HW + t) * GH + tx * 3 + j] = lo + hi;
        }
    }
}

// ---------------- K3b: split K and transposed V into bf16 hi/lo -------------
__global__ void __launch_bounds__(256) kv_prep_kernel() {
    __shared__ float vs[64 * 65];
    const int kt0 = blockIdx.x * 64;
    const int head = blockIdx.y;
    const int tid = threadIdx.x;

    for (int i = tid; i < 64 * 64; i += 256) {
        int r = i >> 6, c = i & 63;
        const float* src = &g_qkv[(size_t)(kt0 + r) * (3 * DIM) + head * HD + c];
        float kv = src[DIM];
        __nv_bfloat16 kh = __float2bfloat16(kv);
        size_t ko = ((size_t)head * HW + kt0 + r) * HD + c;
        g_kh[ko] = kh;
        g_kl[ko] = __float2bfloat16(kv - __bfloat162float(kh));
        vs[r * 65 + c] = src[2 * DIM];
    }
    __syncthreads();
    for (int i = tid; i < 64 * 64; i += 256) {
        int d = i >> 6, k = i & 63;
        float v = vs[k * 65 + d];
        __nv_bfloat16 vh = __float2bfloat16(v);
        size_t vo = ((size_t)head * HD + d) * HW + kt0 + k;
        g_vh[vo] = vh;
        g_vl[vo] = __float2bfloat16(v - __bfloat162float(vh));
    }
}

// ---------------- K4: mma.sync flash attention (64-row tiles, 2 CTA/SM) -----
#define ROWB   144            // 72 bf16 = 144 bytes per padded row
#define ARR_SZ (64 * ROWB)    // 9216
#define SB_KLO ARR_SZ
#define SB_V   (2 * ARR_SZ)
#define SB_VLO (3 * ARR_SZ)
#define BUF_SZ (4 * ARR_SZ)   // 36864
#define SM_RH  (2 * BUF_SZ)                 // 73728
#define SM_RW  (SM_RH + 64 * GH * 4)        // +12288
#define SM_TOT (SM_RW + 64 * GH * 4)        // 98304 (96KB) -> 2 CTA/SM

__device__ __forceinline__ void copy_kv_async(uint32_t dstb, int head, int kt0) {
    const int tid = threadIdx.x;   // 128 threads
    const char* khb = (const char*)(g_kh + ((size_t)head * HW + kt0) * HD);
    const char* klb = (const char*)(g_kl + ((size_t)head * HW + kt0) * HD);
#pragma unroll
    for (int it = 0; it < 4; it++) {
        int i = tid + it * 128;
        int r = i >> 3, c = i & 7;
        uint32_t d = r * ROWB + c * 16;
        cp16(dstb + d, khb + i * 16);
        cp16(dstb + SB_KLO + d, klb + i * 16);
    }
    const char* vhb = (const char*)(g_vh + (size_t)head * HD * HW + kt0);
    const char* vlb = (const char*)(g_vl + (size_t)head * HD * HW + kt0);
#pragma unroll
    for (int it = 0; it < 4; it++) {
        int i = tid + it * 128;
        int dr = i >> 3, c = i & 7;
        uint32_t d = dr * ROWB + c * 16;
        size_t go = (size_t)dr * (HW * 2) + c * 16;
        cp16(dstb + SB_V + d, vhb + go);
        cp16(dstb + SB_VLO + d, vlb + go);
    }
    CP_COMMIT();
}

__global__ void __launch_bounds__(128) attn_mma_kernel() {
    extern __shared__ char smc[];
    const uint32_t smb = smem_to_u32(smc);
    const int tid = threadIdx.x, lane = tid & 31, warp = tid >> 5;   // 4 warps
    const int gid = lane >> 2, tig = lane & 3;
    const int head = blockIdx.y;
    const int qt0 = blockIdx.x * 64;

    copy_kv_async(smb, head, 0);

    float* Rh = (float*)(smc + SM_RH);
    float* Rw = (float*)(smc + SM_RW);
    {
        const float4* sH = (const float4*)&g_relh[((size_t)head * HW + qt0) * GH];
        const float4* sW = (const float4*)&g_relw[((size_t)head * HW + qt0) * GH];
        float4* dH = (float4*)Rh;
        float4* dW = (float4*)Rw;
        for (int i = tid; i < 64 * GH / 4; i += 128) { dH[i] = sH[i]; dW[i] = sW[i]; }
    }

    uint32_t qhi[4][4], qlo[4][4];
    {
        const float* q0 = &g_qkv[(size_t)(qt0 + warp * 16 + gid) * (3 * DIM) + head * HD];
        const float* q1 = q0 + (size_t)8 * (3 * DIM);
#pragma unroll
        for (int s = 0; s < 4; s++) {
            int c = 16 * s + 2 * tig;
            float2 v;
            v = *(const float2*)&q0[c];
            split2(QK_SCALE * v.x, QK_SCALE * v.y, qhi[s][0], qlo[s][0]);
            v = *(const float2*)&q1[c];
            split2(QK_SCALE * v.x, QK_SCALE * v.y, qhi[s][1], qlo[s][1]);
            v = *(const float2*)&q0[c + 8];
            split2(QK_SCALE * v.x, QK_SCALE * v.y, qhi[s][2], qlo[s][2]);
            v = *(const float2*)&q1[c + 8];
            split2(QK_SCALE * v.x, QK_SCALE * v.y, qhi[s][3], qlo[s][3]);
        }
    }

    CP_WAIT0();
    __syncthreads();

    float Oacc[8][4];
#pragma unroll
    for (int j = 0; j < 8; j++)
#pragma unroll
        for (int i = 0; i < 4; i++) Oacc[j][i] = 0.f;
    float rs0 = 0.f, rs1 = 0.f;

    const float* rh0 = &Rh[(warp * 16 + gid) * GH];
    const float* rh1 = rh0 + 8 * GH;
    const float* rw0 = &Rw[(warp * 16 + gid) * GH];
    const float* rw1 = rw0 + 8 * GH;
    const uint32_t lmoff = (uint32_t)((lane & 7) * ROWB + (lane & 8) * 2);

    for (int t = 0; t < NT; t++) {
        const int kt0 = t * 64;
        const uint32_t kb = smb + (uint32_t)(t & 1) * BUF_SZ;
        if (t + 1 < NT)
            copy_kv_async(smb + (uint32_t)((t + 1) & 1) * BUF_SZ, head, kt0 + 64);

        float Sacc[8][4];
#pragma unroll
        for (int j = 0; j < 8; j++)
#pragma unroll
            for (int i = 0; i < 4; i++) Sacc[j][i] = 0.f;

#pragma unroll
        for (int j = 0; j < 8; j++) {
            uint32_t base = kb + (uint32_t)j * (8 * ROWB) + lmoff;
#pragma unroll
            for (int s = 0; s < 4; s++) {
                uint32_t bh0, bh1, bl0, bl1;
                ldsm2(bh0, bh1, base + s * 32);
                ldsm2(bl0, bl1, base + SB_KLO + s * 32);
                mma16816(Sacc[j], qhi[s], bh0, bh1);
                mma16816(Sacc[j], qlo[s], bh0, bh1);
                mma16816(Sacc[j], qhi[s], bl0, bl1);
            }
        }

#pragma unroll
        for (int j = 0; j < 8; j++) {
            int k0 = kt0 + 8 * j + 2 * tig;
            int hk0 = k0 / GH, wk0 = k0 - hk0 * GH;
            int k1 = k0 + 1;
            int hk1 = k1 / GH, wk1 = k1 - hk1 * GH;
            float e0 = __expf(Sacc[j][0] + rh0[hk0] + rw0[wk0]);
            float e1 = __expf(Sacc[j][1] + rh0[hk1] + rw0[wk1]);
            float e2 = __expf(Sacc[j][2] + rh1[hk0] + rw1[wk0]);
            float e3 = __expf(Sacc[j][3] + rh1[hk1] + rw1[wk1]);
            rs0 += e0 + e1;
            rs1 += e2 + e3;
            Sacc[j][0] = e0; Sacc[j][1] = e1; Sacc[j][2] = e2; Sacc[j][3] = e3;
        }

        uint32_t phi[4][4], plo[4][4];
#pragma unroll
        for (int s = 0; s < 4; s++) {
            split2(Sacc[2 * s][0],     Sacc[2 * s][1],     phi[s][0], plo[s][0]);
            split2(Sacc[2 * s][2],     Sacc[2 * s][3],     phi[s][1], plo[s][1]);
            split2(Sacc[2 * s + 1][0], Sacc[2 * s + 1][1], phi[s][2], plo[s][2]);
            split2(Sacc[2 * s + 1][2], Sacc[2 * s + 1][3], phi[s][3], plo[s][3]);
        }

#pragma unroll
        for (int j = 0; j < 8; j++) {
            uint32_t base = kb + SB_V + (uint32_t)j * (8 * ROWB) + lmoff;
#pragma unroll
            for (int s = 0; s < 4; s++) {
                uint32_t vh0, vh1, vl0, vl1;
                ldsm2(vh0, vh1, base + s * 32);
                ldsm2(vl0, vl1, base + ARR_SZ + s * 32);
                mma16816(Oacc[j], phi[s], vh0, vh1);
                mma16816(Oacc[j], plo[s], vh0, vh1);
                mma16816(Oacc[j], phi[s], vl0, vl1);
            }
        }
        CP_WAIT0();
        __syncthreads();
    }

    rs0 += __shfl_xor_sync(0xffffffffu, rs0, 1);
    rs0 += __shfl_xor_sync(0xffffffffu, rs0, 2);
    rs1 += __shfl_xor_sync(0xffffffffu, rs1, 1);
    rs1 += __shfl_xor_sync(0xffffffffu, rs1, 2);
    const float inv0 = 1.f / rs0, inv1 = 1.f / rs1;

    const size_t r0 = (size_t)(qt0 + warp * 16 + gid) * DIM + head * HD;
    const size_t r1 = r0 + (size_t)8 * DIM;
#pragma unroll
    for (int j = 0; j < 8; j++) {
        int c = 8 * j + 2 * tig;
        uint32_t h, l;
        split2(Oacc[j][0] * inv0, Oacc[j][1] * inv0, h, l);
        *(uint32_t*)&g_oph[r0 + c] = h;
        *(uint32_t*)&g_opl[r0 + c] = l;
        split2(Oacc[j][2] * inv1, Oacc[j][3] * inv1, h, l);
        *(uint32_t*)&g_oph[r1 + c] = h;
        *(uint32_t*)&g_opl[r1 + c] = l;
    }
}

// ---------------- launch -----------------------------------------------------
extern "C" void kernel_launch(void* const* d_in, const int* in_sizes, int n_in,
                              void* d_out, int out_size) {
    const float* x     = (const float*)d_in[0];
    const float* Wqkv  = (const float*)d_in[1];
    const float* bqkv  = (const float*)d_in[2];
    const float* FacTu = (const float*)d_in[3];
    const float* FacTv = (const float*)d_in[4];
    const float* qF    = (const float*)d_in[5];
    const float* vF    = (const float*)d_in[6];
    const float* rph   = (const float*)d_in[7];
    const float* rpw   = (const float*)d_in[8];
    const float* Wproj = (const float*)d_in[9];
    const float* bproj = (const float*)d_in[10];
    float* out = (float*)d_out;

    void *pQkv, *pXh, *pXl, *pOph, *pOpl, *pWqT_h, *pWqT_l, *pWpT_h, *pWpT_l;
    cudaGetSymbolAddress(&pQkv, g_qkv);
    cudaGetSymbolAddress(&pXh, g_xh);
    cudaGetSymbolAddress(&pXl, g_xl);
    cudaGetSymbolAddress(&pOph, g_oph);
    cudaGetSymbolAddress(&pOpl, g_opl);
    cudaGetSymbolAddress(&pWqT_h, g_wqkvT_h);
    cudaGetSymbolAddress(&pWqT_l, g_wqkvT_l);
    cudaGetSymbolAddress(&pWpT_h, g_wprojT_h);
    cudaGetSymbolAddress(&pWpT_l, g_wprojT_l);

    cudaFuncSetAttribute(attn_mma_kernel,
                         cudaFuncAttributeMaxDynamicSharedMemorySize, (int)SM_TOT);
    cudaFuncSetAttribute(hgemm_bf16,
                         cudaFuncAttributeMaxDynamicSharedMemorySize, (int)HG_SMEM);

    fact_small_kernel<<<(DIM * RANK * 2 + 255) / 256, 256>>>(FacTu, qF, vF);
    xsplit_kernel<<<(HW * DIM / 4 + 255) / 256, 256>>>(x);

    {   // Wqkv (+delta) -> transposed split
        dim3 grid((3 * DIM) / 32, DIM / 32);
        wsplit_kernel<<<grid, 256>>>(Wqkv, FacTv,
                                     (__nv_bfloat16*)pWqT_h, (__nv_bfloat16*)pWqT_l,
                                     3 * DIM, 1);
    }
    {   // Wproj -> transposed split
        dim3 grid(DIM / 32, DIM / 32);
        wsplit_kernel<<<grid, 256>>>(Wproj, FacTv,
                                     (__nv_bfloat16*)pWpT_h, (__nv_bfloat16*)pWpT_l,
                                     DIM, 0);
    }
    {   // qkv = x @ Weff + bqkv (HMMA, all-bf16)
        dim3 grid((3 * DIM) / 128, HW / 128);
        hgemm_bf16<<<grid, 256, HG_SMEM>>>((const __nv_bfloat16*)pXh,
                                           (const __nv_bfloat16*)pXl,
                                           (const __nv_bfloat16*)pWqT_h,
                                           (const __nv_bfloat16*)pWqT_l,
                                           bqkv, (float*)pQkv, HW, 3 * DIM, DIM);
    }
    {   // rel-pos tables
        dim3 grid(GH, NH, 2);
        rel_tab2_kernel<<<grid, 256>>>(rph, rpw);
    }
    {   // bf16 split K / transposed V
        dim3 grid(HW / 64, NH);
        kv_prep_kernel<<<grid, 256>>>();
    }
    {   // tensor-core attention (64-row q tiles, 2 CTA/SM)
        dim3 grid(HW / 64, NH);
        attn_mma_kernel<<<grid, 128, SM_TOT>>>();
    }
    {   // out = opre @ Wproj + bproj (HMMA, all-bf16)
        dim3 grid(DIM / 128, HW / 128);
        hgemm_bf16<<<grid, 256, HG_SMEM>>>((const __nv_bfloat16*)pOph,
                                           (const __nv_bfloat16*)pOpl,
                                           (const __nv_bfloat16*)pWpT_h,
                                           (const __nv_bfloat16*)pWpT_l,
                                           bproj, out, HW, DIM, DIM);
    }
}

// round 8
// speedup vs baseline: 1.0901x; 1.0901x over previous
#include <cuda_runtime.h>
#include <cuda_bf16.h>
#include <cstdint>

#define DIM   768
#define NH    12
#define HD    64
#define GH    48           // grid H = W
#define HW    2304         // 48*48
#define RANK  32
#define QK_SCALE 0.125f    // 64^-0.5
#define FACT_S 1.0f
#define NT    36           // kv tiles of 64

typedef unsigned long long u64;

// ---------------- packed helpers --------------------------------------------
__device__ __forceinline__ u64 pack2f(float a, float b) {
    u64 r;
    asm("mov.b64 %0, {%1, %2};" : "=l"(r)
        : "r"(__float_as_uint(a)), "r"(__float_as_uint(b)));
    return r;
}
__device__ __forceinline__ void unpack2f(u64 v, float& a, float& b) {
    unsigned x, y;
    asm("mov.b64 {%0, %1}, %2;" : "=r"(x), "=r"(y) : "l"(v));
    a = __uint_as_float(x);
    b = __uint_as_float(y);
}
__device__ __forceinline__ void ffma2(u64& d, u64 a, u64 b) {
    asm("fma.rn.f32x2 %0, %1, %2, %0;" : "+l"(d) : "l"(a), "l"(b));
}
__device__ __forceinline__ uint32_t cvt_bf16x2(float a, float b) {
    uint32_t r;
    asm("cvt.rn.bf16x2.f32 %0, %1, %2;" : "=r"(r) : "f"(b), "f"(a));
    return r;
}
__device__ __forceinline__ void split2(float a, float b, uint32_t& hi, uint32_t& lo) {
    uint32_t h = cvt_bf16x2(a, b);
    float ra = __uint_as_float(h << 16);
    float rb = __uint_as_float(h & 0xffff0000u);
    hi = h;
    lo = cvt_bf16x2(a - ra, b - rb);
}

// ---------------- mma / ldmatrix / cp.async helpers --------------------------
__device__ __forceinline__ void mma16816(float c[4], const uint32_t a[4],
                                         uint32_t b0, uint32_t b1) {
    asm volatile(
        "mma.sync.aligned.m16n8k16.row.col.f32.bf16.bf16.f32 "
        "{%0,%1,%2,%3}, {%4,%5,%6,%7}, {%8,%9}, {%0,%1,%2,%3};"
        : "+f"(c[0]), "+f"(c[1]), "+f"(c[2]), "+f"(c[3])
        : "r"(a[0]), "r"(a[1]), "r"(a[2]), "r"(a[3]), "r"(b0), "r"(b1));
}
__device__ __forceinline__ void ldsm2(uint32_t& r0, uint32_t& r1, uint32_t addr) {
    asm volatile("ldmatrix.sync.aligned.m8n8.x2.shared.b16 {%0,%1}, [%2];"
                 : "=r"(r0), "=r"(r1) : "r"(addr));
}
__device__ __forceinline__ void ldsm4(uint32_t r[4], uint32_t addr) {
    asm volatile("ldmatrix.sync.aligned.m8n8.x4.shared.b16 {%0,%1,%2,%3}, [%4];"
                 : "=r"(r[0]), "=r"(r[1]), "=r"(r[2]), "=r"(r[3]) : "r"(addr));
}
__device__ __forceinline__ uint32_t smem_to_u32(const void* smem_ptr) {
    uint32_t addr;
    asm("{ .reg .u64 tmp; cvta.to.shared.u64 tmp, %1; cvt.u32.u64 %0, tmp; }"
        : "=r"(addr) : "l"(smem_ptr));
    return addr;
}
__device__ __forceinline__ void cp16(uint32_t dst, const void* src) {
    asm volatile("cp.async.cg.shared.global [%0], [%1], 16;"
                 :: "r"(dst), "l"(src));
}
#define CP_COMMIT() asm volatile("cp.async.commit_group;" ::: "memory")
#define CP_WAIT0()  asm volatile("cp.async.wait_group 0;" ::: "memory")
#define CP_WAIT1()  asm volatile("cp.async.wait_group 1;" ::: "memory")

// ---------------- device scratch (no allocations allowed) ------------------
__device__ float g_A1[DIM * RANK];
__device__ float g_A2[DIM * RANK];
__device__ float g_qkv[HW * 3 * DIM];
__device__ float g_relh[NH * HW * GH];
__device__ float g_relw[NH * HW * GH];
// pre-split inputs / intermediates
__device__ __align__(16) __nv_bfloat16 g_xh[HW * DIM];
__device__ __align__(16) __nv_bfloat16 g_xl[HW * DIM];
__device__ __align__(16) __nv_bfloat16 g_oph[HW * DIM];
__device__ __align__(16) __nv_bfloat16 g_opl[HW * DIM];
// pre-split transposed weights: [N][K] bf16 hi/lo
__device__ __align__(16) __nv_bfloat16 g_wqkvT_h[3 * DIM * DIM];
__device__ __align__(16) __nv_bfloat16 g_wqkvT_l[3 * DIM * DIM];
__device__ __align__(16) __nv_bfloat16 g_wprojT_h[DIM * DIM];
__device__ __align__(16) __nv_bfloat16 g_wprojT_l[DIM * DIM];
// bf16 split K [head][key][dim] and transposed V [head][dim][key]
__device__ __align__(16) __nv_bfloat16 g_kh[NH * HW * HD];
__device__ __align__(16) __nv_bfloat16 g_kl[NH * HW * HD];
__device__ __align__(16) __nv_bfloat16 g_vh[NH * HD * HW];
__device__ __align__(16) __nv_bfloat16 g_vl[NH * HD * HW];

// ---------------- K0: A1 = FacTu @ q_FacTs, A2 = FacTu @ v_FacTs -----------
__global__ void fact_small_kernel(const float* __restrict__ FacTu,
                                  const float* __restrict__ qF,
                                  const float* __restrict__ vF) {
    int idx = blockIdx.x * 256 + threadIdx.x;
    if (idx >= DIM * RANK * 2) return;
    int which = idx / (DIM * RANK);
    int rem = idx - which * (DIM * RANK);
    int i = rem / RANK, r = rem - (rem / RANK) * RANK;
    const float* F = which ? vF : qF;
    float s = 0.f;
#pragma unroll
    for (int k = 0; k < RANK; k++) s += FacTu[i * RANK + k] * F[k * RANK + r];
    (which ? g_A2 : g_A1)[i * RANK + r] = s;
}

// ---------------- K0b: split x into bf16 hi/lo ------------------------------
__global__ void __launch_bounds__(256) xsplit_kernel(const float* __restrict__ x) {
    int idx = blockIdx.x * 256 + threadIdx.x;
    if (idx >= HW * DIM / 4) return;
    float4 v = *(const float4*)&x[idx * 4];
    uint32_t h0, l0, h1, l1;
    split2(v.x, v.y, h0, l0);
    split2(v.z, v.w, h1, l1);
    *(uint2*)&g_xh[idx * 4] = make_uint2(h0, h1);
    *(uint2*)&g_xl[idx * 4] = make_uint2(l0, l1);
}

// ---------------- K1: transpose + low-rank fold + bf16 split ---------------
__global__ void __launch_bounds__(256)
wsplit_kernel(const float* __restrict__ W, const float* __restrict__ FacTv,
              __nv_bfloat16* __restrict__ WTh, __nv_bfloat16* __restrict__ WTl,
              int NJ, int mode) {
    __shared__ float tile[32 * 33];
    const int tid = threadIdx.x;
    const int j0 = blockIdx.x * 32;
    const int i0 = blockIdx.y * 32;

    {
        const int j = tid & 31;
        const int ib = tid >> 5;
        const float* Aarr = nullptr;
        int jj = j0 + j;
        if (mode) {
            if (jj < DIM) Aarr = g_A1;
            else if (jj >= 2 * DIM) { Aarr = g_A2; jj -= 2 * DIM; }
        }
#pragma unroll
        for (int it = 0; it < 4; it++) {
            int il = ib + it * 8;
            int i = i0 + il;
            float w = W[(size_t)i * NJ + j0 + j];
            if (Aarr) {
                float s = 0.f;
#pragma unroll
                for (int r = 0; r < RANK; r++)
                    s += Aarr[i * RANK + r] * FacTv[r * DIM + jj];
                w += FACT_S * s;
            }
            tile[il * 33 + j] = w;
        }
    }
    __syncthreads();
    {
        const int i = tid & 31;
        const int jb = tid >> 5;
#pragma unroll
        for (int it = 0; it < 4; it++) {
            int jl = jb + it * 8;
            float v = tile[i * 33 + jl];
            __nv_bfloat16 h = __float2bfloat16(v);
            size_t o = (size_t)(j0 + jl) * DIM + i0 + i;
            WTh[o] = h;
            WTl[o] = __float2bfloat16(v - __bfloat162float(h));
        }
    }
}

// ---------------- K2: HMMA GEMM (all-bf16, cp.async double buffer) ----------
#define GS 40                 // smem row stride in bf16 (80B)
#define GARR 10240
#define GBUF 40960
__global__ void __launch_bounds__(256)
hgemm_bf16(const __nv_bfloat16* __restrict__ Ah_,
           const __nv_bfloat16* __restrict__ Al_,
           const __nv_bfloat16* __restrict__ Bh_,
           const __nv_bfloat16* __restrict__ Bl_,
           const float* __restrict__ bias, float* __restrict__ C,
           int M, int N, int K) {
    extern __shared__ __align__(16) char gsm[];
    const uint32_t smb = smem_to_u32(gsm);
    const int tid = threadIdx.x, lane = tid & 31, warp = tid >> 5;
    const int wm = (warp >> 2) * 64, wn = (warp & 3) * 32;
    const int bm = blockIdx.y * 128, bn = blockIdx.x * 128;

#define GB_ISSUE(k0) do { \
        _Pragma("unroll") \
        for (int t = 0; t < 8; t++) { \
            int i = tid + t * 256; \
            int arr = i >> 9, j = i & 511; \
            int row = j >> 2, c = j & 3; \
            const __nv_bfloat16* gptr = (arr == 0) ? Ah_ : (arr == 1) ? Al_ \
                                        : (arr == 2) ? Bh_ : Bl_; \
            int grow = (arr < 2 ? bm : bn) + row; \
            const char* src = (const char*)&gptr[(size_t)grow * K + (k0)] + c * 16; \
            cp16(sb + arr * GARR + row * 80 + c * 16, src); \
        } \
        CP_COMMIT(); \
    } while (0)

    float acc[4][4][4];
#pragma unroll
    for (int a = 0; a < 4; a++)
#pragma unroll
        for (int b = 0; b < 4; b++)
#pragma unroll
            for (int c = 0; c < 4; c++) acc[a][b][c] = 0.f;

    {
        uint32_t sb = smb;
        GB_ISSUE(0);
    }

    const uint32_t aoff = (uint32_t)((lane & 15) * GS + ((lane >> 4) << 3)) * 2;
    const uint32_t boff = (uint32_t)(((lane & 7) + ((lane & 16) >> 1)) * GS + (lane & 8)) * 2;

    const int NKT = K / 32;
    for (int kt = 0; kt < NKT; kt++) {
        CP_WAIT0();
        __syncthreads();
        if (kt + 1 < NKT) {
            uint32_t sb = smb + (uint32_t)((kt + 1) & 1) * GBUF;
            GB_ISSUE((kt + 1) * 32);
        }
        const uint32_t cb = smb + (uint32_t)(kt & 1) * GBUF;
        const uint32_t sAh = cb, sAl = cb + GARR, sBh = cb + 2 * GARR, sBl = cb + 3 * GARR;

#pragma unroll
        for (int ks = 0; ks < 2; ks++) {
            uint32_t ah[4][4], al[4][4];
#pragma unroll
            for (int mt = 0; mt < 4; mt++) {
                uint32_t off = (uint32_t)(wm + mt * 16) * (GS * 2) + (uint32_t)ks * 32 + aoff;
                ldsm4(ah[mt], sAh + off);
                ldsm4(al[mt], sAl + off);
            }
            uint32_t bh[2][4], bl[2][4];
#pragma unroll
            for (int nt = 0; nt < 2; nt++) {
                uint32_t off = (uint32_t)(wn + nt * 16) * (GS * 2) + (uint32_t)ks * 32 + boff;
                ldsm4(bh[nt], sBh + off);
                ldsm4(bl[nt], sBl + off);
            }
#pragma unroll
            for (int mt = 0; mt < 4; mt++)
#pragma unroll
                for (int nt = 0; nt < 4; nt++) {
                    uint32_t b0h = bh[nt >> 1][(nt & 1) * 2];
                    uint32_t b1h = bh[nt >> 1][(nt & 1) * 2 + 1];
                    uint32_t b0l = bl[nt >> 1][(nt & 1) * 2];
                    uint32_t b1l = bl[nt >> 1][(nt & 1) * 2 + 1];
                    mma16816(acc[mt][nt], ah[mt], b0h, b1h);
                    mma16816(acc[mt][nt], al[mt], b0h, b1h);
                    mma16816(acc[mt][nt], ah[mt], b0l, b1l);
                }
        }
        __syncthreads();
    }

    const int gid = lane >> 2, tig = lane & 3;
#pragma unroll
    for (int mt = 0; mt < 4; mt++) {
        int m0 = bm + wm + mt * 16 + gid;
#pragma unroll
        for (int nt = 0; nt < 4; nt++) {
            int n0 = bn + wn + nt * 8 + 2 * tig;
            float bx = bias ? bias[n0] : 0.f;
            float by = bias ? bias[n0 + 1] : 0.f;
            *(float2*)&C[(size_t)m0 * N + n0] =
                make_float2(acc[mt][nt][0] + bx, acc[mt][nt][1] + by);
            *(float2*)&C[(size_t)(m0 + 8) * N + n0] =
                make_float2(acc[mt][nt][2] + bx, acc[mt][nt][3] + by);
        }
    }
}
#define HG_SMEM (2 * GBUF)

// ---------------- K3: rel bias tables ---------------------------------------
__global__ void __launch_bounds__(256) rel_tab2_kernel(const float* __restrict__ rph,
                                                       const float* __restrict__ rpw) {
    __shared__ float Qs[GH * 68];
    __shared__ float Rs[GH * 68];
    const int pos = blockIdx.x;
    const int head = blockIdx.y;
    const int which = blockIdx.z;
    const int tid = threadIdx.x;

    for (int i = tid; i < GH * HD; i += 256) {
        int r = i >> 6, c = i & 63;
        int t = which ? (r * GH + pos) : (pos * GH + r);
        Qs[r * 68 + c] = g_qkv[(size_t)t * (3 * DIM) + head * HD + c];
    }
    const float* rp = which ? rpw : rph;
    for (int i = tid; i < GH * HD; i += 256) {
        int k = i >> 6, c = i & 63;
        Rs[k * 68 + c] = rp[(pos - k + GH - 1) * HD + c];
    }
    __syncthreads();

    const int tx = tid & 15, ty = tid >> 4;
    u64 acc[3][3];
#pragma unroll
    for (int i = 0; i < 3; i++)
#pragma unroll
        for (int j = 0; j < 3; j++) acc[i][j] = 0ull;

    for (int c = 0; c < HD; c += 4) {
        ulonglong2 q[3], r[3];
#pragma unroll
        for (int i = 0; i < 3; i++) q[i] = *(const ulonglong2*)&Qs[(ty * 3 + i) * 68 + c];
#pragma unroll
        for (int j = 0; j < 3; j++) r[j] = *(const ulonglong2*)&Rs[(tx * 3 + j) * 68 + c];
#pragma unroll
        for (int i = 0; i < 3; i++)
#pragma unroll
            for (int j = 0; j < 3; j++) {
                ffma2(acc[i][j], q[i].x, r[j].x);
                ffma2(acc[i][j], q[i].y, r[j].y);
            }
    }

    float* outp = which ? g_relw : g_relh;
#pragma unroll
    for (int i = 0; i < 3; i++) {
        int row = ty * 3 + i;
        int t = which ? (row * GH + pos) : (pos * GH + row);
#pragma unroll
        for (int j = 0; j < 3; j++) {
            float lo, hi;
            unpack2f(acc[i][j], lo, hi);
            outp[((size_t)head * HW + t) * GH + tx * 3 + j] = lo + hi;
        }
    }
}

// ---------------- K3b: split K and transposed V into bf16 hi/lo -------------
__global__ void __launch_bounds__(256) kv_prep_kernel() {
    __shared__ float vs[64 * 65];
    const int kt0 = blockIdx.x * 64;
    const int head = blockIdx.y;
    const int tid = threadIdx.x;

    for (int i = tid; i < 64 * 64; i += 256) {
        int r = i >> 6, c = i & 63;
        const float* src = &g_qkv[(size_t)(kt0 + r) * (3 * DIM) + head * HD + c];
        float kv = src[DIM];
        __nv_bfloat16 kh = __float2bfloat16(kv);
        size_t ko = ((size_t)head * HW + kt0 + r) * HD + c;
        g_kh[ko] = kh;
        g_kl[ko] = __float2bfloat16(kv - __bfloat162float(kh));
        vs[r * 65 + c] = src[2 * DIM];
    }
    __syncthreads();
    for (int i = tid; i < 64 * 64; i += 256) {
        int d = i >> 6, k = i & 63;
        float v = vs[k * 65 + d];
        __nv_bfloat16 vh = __float2bfloat16(v);
        size_t vo = ((size_t)head * HD + d) * HW + kt0 + k;
        g_vh[vo] = vh;
        g_vl[vo] = __float2bfloat16(v - __bfloat162float(vh));
    }
}

// ---------------- K4: pipelined mma.sync flash attention --------------------
// 128 q-rows per CTA, 256 threads, triple-buffered KV, S computed 1 tile ahead.
#define ROWB   144            // 72 bf16 = 144 bytes per padded row
#define ARR_SZ (64 * ROWB)    // 9216
#define SB_KLO ARR_SZ
#define SB_V   (2 * ARR_SZ)
#define SB_VLO (3 * ARR_SZ)
#define BUF_SZ (4 * ARR_SZ)   // 36864
#define SM_RH  (3 * BUF_SZ)                 // 110592
#define SM_RW  (SM_RH + 128 * GH * 4)       // +24576
#define SM_TOT (SM_RW + 128 * GH * 4)       // 159744 (156KB) -> 1 CTA/SM

__device__ __forceinline__ void copy_kv_async(uint32_t dstb, int head, int kt0) {
    const int tid = threadIdx.x;   // 256 threads
    const char* khb = (const char*)(g_kh + ((size_t)head * HW + kt0) * HD);
    const char* klb = (const char*)(g_kl + ((size_t)head * HW + kt0) * HD);
#pragma unroll
    for (int it = 0; it < 2; it++) {
        int i = tid + it * 256;
        int r = i >> 3, c = i & 7;
        uint32_t d = r * ROWB + c * 16;
        cp16(dstb + d, khb + i * 16);
        cp16(dstb + SB_KLO + d, klb + i * 16);
    }
    const char* vhb = (const char*)(g_vh + (size_t)head * HD * HW + kt0);
    const char* vlb = (const char*)(g_vl + (size_t)head * HD * HW + kt0);
#pragma unroll
    for (int it = 0; it < 2; it++) {
        int i = tid + it * 256;
        int dr = i >> 3, c = i & 7;
        uint32_t d = dr * ROWB + c * 16;
        size_t go = (size_t)dr * (HW * 2) + c * 16;
        cp16(dstb + SB_V + d, vhb + go);
        cp16(dstb + SB_VLO + d, vlb + go);
    }
    CP_COMMIT();
}

__device__ __forceinline__ void s_mma_tile(float S[8][4], uint32_t kb,
                                           const uint32_t qhi[4][4],
                                           const uint32_t qlo[4][4],
                                           uint32_t lmoff) {
#pragma unroll
    for (int j = 0; j < 8; j++) {
#pragma unroll
        for (int i = 0; i < 4; i++) S[j][i] = 0.f;
        uint32_t base = kb + (uint32_t)j * (8 * ROWB) + lmoff;
#pragma unroll
        for (int s = 0; s < 4; s++) {
            uint32_t bh0, bh1, bl0, bl1;
            ldsm2(bh0, bh1, base + s * 32);
            ldsm2(bl0, bl1, base + SB_KLO + s * 32);
            mma16816(S[j], qhi[s], bh0, bh1);
            mma16816(S[j], qlo[s], bh0, bh1);
            mma16816(S[j], qhi[s], bl0, bl1);
        }
    }
}

__global__ void __launch_bounds__(256) attn_mma_kernel() {
    extern __shared__ char smc[];
    const uint32_t smb = smem_to_u32(smc);
    const int tid = threadIdx.x, lane = tid & 31, warp = tid >> 5;   // 8 warps
    const int gid = lane >> 2, tig = lane & 3;
    const int head = blockIdx.y;
    const int qt0 = blockIdx.x * 128;

    copy_kv_async(smb, head, 0);
    copy_kv_async(smb + BUF_SZ, head, 64);

    float* Rh = (float*)(smc + SM_RH);
    float* Rw = (float*)(smc + SM_RW);
    {
        const float4* sH = (const float4*)&g_relh[((size_t)head * HW + qt0) * GH];
        const float4* sW = (const float4*)&g_relw[((size_t)head * HW + qt0) * GH];
        float4* dH = (float4*)Rh;
        float4* dW = (float4*)Rw;
        for (int i = tid; i < 128 * GH / 4; i += 256) { dH[i] = sH[i]; dW[i] = sW[i]; }
    }

    uint32_t qhi[4][4], qlo[4][4];
    {
        const float* q0 = &g_qkv[(size_t)(qt0 + warp * 16 + gid) * (3 * DIM) + head * HD];
        const float* q1 = q0 + (size_t)8 * (3 * DIM);
#pragma unroll
        for (int s = 0; s < 4; s++) {
            int c = 16 * s + 2 * tig;
            float2 v;
            v = *(const float2*)&q0[c];
            split2(QK_SCALE * v.x, QK_SCALE * v.y, qhi[s][0], qlo[s][0]);
            v = *(const float2*)&q1[c];
            split2(QK_SCALE * v.x, QK_SCALE * v.y, qhi[s][1], qlo[s][1]);
            v = *(const float2*)&q0[c + 8];
            split2(QK_SCALE * v.x, QK_SCALE * v.y, qhi[s][2], qlo[s][2]);
            v = *(const float2*)&q1[c + 8];
            split2(QK_SCALE * v.x, QK_SCALE * v.y, qhi[s][3], qlo[s][3]);
        }
    }

    const uint32_t lmoff = (uint32_t)((lane & 7) * ROWB + (lane & 8) * 2);

    CP_WAIT1();            // buf0 complete (buf1 in flight)
    __syncthreads();

    float Scur[8][4], Snext[8][4];
    s_mma_tile(Scur, smb, qhi, qlo, lmoff);

    float Oacc[8][4];
#pragma unroll
    for (int j = 0; j < 8; j++)
#pragma unroll
        for (int i = 0; i < 4; i++) Oacc[j][i] = 0.f;
    float rs0 = 0.f, rs1 = 0.f;

    const float* rh0 = &Rh[(warp * 16 + gid) * GH];
    const float* rh1 = rh0 + 8 * GH;
    const float* rw0 = &Rw[(warp * 16 + gid) * GH];
    const float* rw1 = rw0 + 8 * GH;

    for (int t = 0; t < NT; t++) {
        const int kt0 = t * 64;
        __syncthreads();   // all warps done reading buf((t-1)%3) from PV(t-1)
        if (t + 2 < NT)
            copy_kv_async(smb + (uint32_t)((t + 2) % 3) * BUF_SZ, head, (t + 2) * 64);
        if (t + 1 < NT) {
            if (t + 2 < NT) { CP_WAIT1(); } else { CP_WAIT0(); }
            __syncthreads();   // buf(t+1) visible to all warps
            s_mma_tile(Snext, smb + (uint32_t)((t + 1) % 3) * BUF_SZ, qhi, qlo, lmoff);
        }

        // softmax on Scur (tile t) — results are a full iteration old
#pragma unroll
        for (int j = 0; j < 8; j++) {
            int k0 = kt0 + 8 * j + 2 * tig;
            int hk0 = k0 / GH, wk0 = k0 - hk0 * GH;
            int k1 = k0 + 1;
            int hk1 = k1 / GH, wk1 = k1 - hk1 * GH;
            float e0 = __expf(Scur[j][0] + rh0[hk0] + rw0[wk0]);
            float e1 = __expf(Scur[j][1] + rh0[hk1] + rw0[wk1]);
            float e2 = __expf(Scur[j][2] + rh1[hk0] + rw1[wk0]);
            float e3 = __expf(Scur[j][3] + rh1[hk1] + rw1[wk1]);
            rs0 += e0 + e1;
            rs1 += e2 + e3;
            Scur[j][0] = e0; Scur[j][1] = e1; Scur[j][2] = e2; Scur[j][3] = e3;
        }

        uint32_t phi[4][4], plo[4][4];
#pragma unroll
        for (int s = 0; s < 4; s++) {
            split2(Scur[2 * s][0],     Scur[2 * s][1],     phi[s][0], plo[s][0]);
            split2(Scur[2 * s][2],     Scur[2 * s][3],     phi[s][1], plo[s][1]);
            split2(Scur[2 * s + 1][0], Scur[2 * s + 1][1], phi[s][2], plo[s][2]);
            split2(Scur[2 * s + 1][2], Scur[2 * s + 1][3], phi[s][3], plo[s][3]);
        }

        const uint32_t vb = smb + (uint32_t)(t % 3) * BUF_SZ + SB_V;
#pragma unroll
        for (int j = 0; j < 8; j++) {
            uint32_t base = vb + (uint32_t)j * (8 * ROWB) + lmoff;
#pragma unroll
            for (int s = 0; s < 4; s++) {
                uint32_t vh0, vh1, vl0, vl1;
                ldsm2(vh0, vh1, base + s * 32);
                ldsm2(vl0, vl1, base + ARR_SZ + s * 32);
                mma16816(Oacc[j], phi[s], vh0, vh1);
                mma16816(Oacc[j], plo[s], vh0, vh1);
                mma16816(Oacc[j], phi[s], vl0, vl1);
            }
        }

        if (t + 1 < NT) {
#pragma unroll
            for (int j = 0; j < 8; j++)
#pragma unroll
                for (int i = 0; i < 4; i++) Scur[j][i] = Snext[j][i];
        }
    }

    rs0 += __shfl_xor_sync(0xffffffffu, rs0, 1);
    rs0 += __shfl_xor_sync(0xffffffffu, rs0, 2);
    rs1 += __shfl_xor_sync(0xffffffffu, rs1, 1);
    rs1 += __shfl_xor_sync(0xffffffffu, rs1, 2);
    const float inv0 = 1.f / rs0, inv1 = 1.f / rs1;

    const size_t r0 = (size_t)(qt0 + warp * 16 + gid) * DIM + head * HD;
    const size_t r1 = r0 + (size_t)8 * DIM;
#pragma unroll
    for (int j = 0; j < 8; j++) {
        int c = 8 * j + 2 * tig;
        uint32_t h, l;
        split2(Oacc[j][0] * inv0, Oacc[j][1] * inv0, h, l);
        *(uint32_t*)&g_oph[r0 + c] = h;
        *(uint32_t*)&g_opl[r0 + c] = l;
        split2(Oacc[j][2] * inv1, Oacc[j][3] * inv1, h, l);
        *(uint32_t*)&g_oph[r1 + c] = h;
        *(uint32_t*)&g_opl[r1 + c] = l;
    }
}

// ---------------- launch -----------------------------------------------------
extern "C" void kernel_launch(void* const* d_in, const int* in_sizes, int n_in,
                              void* d_out, int out_size) {
    const float* x     = (const float*)d_in[0];
    const float* Wqkv  = (const float*)d_in[1];
    const float* bqkv  = (const float*)d_in[2];
    const float* FacTu = (const float*)d_in[3];
    const float* FacTv = (const float*)d_in[4];
    const float* qF    = (const float*)d_in[5];
    const float* vF    = (const float*)d_in[6];
    const float* rph   = (const float*)d_in[7];
    const float* rpw   = (const float*)d_in[8];
    const float* Wproj = (const float*)d_in[9];
    const float* bproj = (const float*)d_in[10];
    float* out = (float*)d_out;

    void *pQkv, *pXh, *pXl, *pOph, *pOpl, *pWqT_h, *pWqT_l, *pWpT_h, *pWpT_l;
    cudaGetSymbolAddress(&pQkv, g_qkv);
    cudaGetSymbolAddress(&pXh, g_xh);
    cudaGetSymbolAddress(&pXl, g_xl);
    cudaGetSymbolAddress(&pOph, g_oph);
    cudaGetSymbolAddress(&pOpl, g_opl);
    cudaGetSymbolAddress(&pWqT_h, g_wqkvT_h);
    cudaGetSymbolAddress(&pWqT_l, g_wqkvT_l);
    cudaGetSymbolAddress(&pWpT_h, g_wprojT_h);
    cudaGetSymbolAddress(&pWpT_l, g_wprojT_l);

    cudaFuncSetAttribute(attn_mma_kernel,
                         cudaFuncAttributeMaxDynamicSharedMemorySize, (int)SM_TOT);
    cudaFuncSetAttribute(hgemm_bf16,
                         cudaFuncAttributeMaxDynamicSharedMemorySize, (int)HG_SMEM);

    fact_small_kernel<<<(DIM * RANK * 2 + 255) / 256, 256>>>(FacTu, qF, vF);
    xsplit_kernel<<<(HW * DIM / 4 + 255) / 256, 256>>>(x);

    {   // Wqkv (+delta) -> transposed split
        dim3 grid((3 * DIM) / 32, DIM / 32);
        wsplit_kernel<<<grid, 256>>>(Wqkv, FacTv,
                                     (__nv_bfloat16*)pWqT_h, (__nv_bfloat16*)pWqT_l,
                                     3 * DIM, 1);
    }
    {   // Wproj -> transposed split
        dim3 grid(DIM / 32, DIM / 32);
        wsplit_kernel<<<grid, 256>>>(Wproj, FacTv,
                                     (__nv_bfloat16*)pWpT_h, (__nv_bfloat16*)pWpT_l,
                                     DIM, 0);
    }
    {   // qkv = x @ Weff + bqkv (HMMA, all-bf16)
        dim3 grid((3 * DIM) / 128, HW / 128);
        hgemm_bf16<<<grid, 256, HG_SMEM>>>((const __nv_bfloat16*)pXh,
                                           (const __nv_bfloat16*)pXl,
                                           (const __nv_bfloat16*)pWqT_h,
                                           (const __nv_bfloat16*)pWqT_l,
                                           bqkv, (float*)pQkv, HW, 3 * DIM, DIM);
    }
    {   // rel-pos tables
        dim3 grid(GH, NH, 2);
        rel_tab2_kernel<<<grid, 256>>>(rph, rpw);
    }
    {   // bf16 split K / transposed V
        dim3 grid(HW / 64, NH);
        kv_prep_kernel<<<grid, 256>>>();
    }
    {   // pipelined tensor-core attention
        dim3 grid(HW / 128, NH);
        attn_mma_kernel<<<grid, 256, SM_TOT>>>();
    }
    {   // out = opre @ Wproj + bproj (HMMA, all-bf16)
        dim3 grid(DIM / 128, HW / 128);
        hgemm_bf16<<<grid, 256, HG_SMEM>>>((const __nv_bfloat16*)pOph,
                                           (const __nv_bfloat16*)pOpl,
                                           (const __nv_bfloat16*)pWpT_h,
                                           (const __nv_bfloat16*)pWpT_l,
                                           bproj, out, HW, DIM, DIM);
    }
}

// round 9
// speedup vs baseline: 1.2052x; 1.1056x over previous
#include <cuda_runtime.h>
#include <cuda_bf16.h>
#include <cstdint>

#define DIM   768
#define NH    12
#define HD    64
#define GH    48           // grid H = W
#define HW    2304         // 48*48
#define RANK  32
#define QK_SCALE 0.125f    // 64^-0.5
#define FACT_S 1.0f
#define NT    36           // kv tiles of 64
#define KSPLIT 2
#define NTT   (NT / KSPLIT)  // 18 tiles per split

typedef unsigned long long u64;

// ---------------- packed helpers --------------------------------------------
__device__ __forceinline__ u64 pack2f(float a, float b) {
    u64 r;
    asm("mov.b64 %0, {%1, %2};" : "=l"(r)
        : "r"(__float_as_uint(a)), "r"(__float_as_uint(b)));
    return r;
}
__device__ __forceinline__ void unpack2f(u64 v, float& a, float& b) {
    unsigned x, y;
    asm("mov.b64 {%0, %1}, %2;" : "=r"(x), "=r"(y) : "l"(v));
    a = __uint_as_float(x);
    b = __uint_as_float(y);
}
__device__ __forceinline__ void ffma2(u64& d, u64 a, u64 b) {
    asm("fma.rn.f32x2 %0, %1, %2, %0;" : "+l"(d) : "l"(a), "l"(b));
}
__device__ __forceinline__ uint32_t cvt_bf16x2(float a, float b) {
    uint32_t r;
    asm("cvt.rn.bf16x2.f32 %0, %1, %2;" : "=r"(r) : "f"(b), "f"(a));
    return r;
}
__device__ __forceinline__ void split2(float a, float b, uint32_t& hi, uint32_t& lo) {
    uint32_t h = cvt_bf16x2(a, b);
    float ra = __uint_as_float(h << 16);
    float rb = __uint_as_float(h & 0xffff0000u);
    hi = h;
    lo = cvt_bf16x2(a - ra, b - rb);
}

// ---------------- mma / ldmatrix / cp.async helpers --------------------------
__device__ __forceinline__ void mma16816(float c[4], const uint32_t a[4],
                                         uint32_t b0, uint32_t b1) {
    asm volatile(
        "mma.sync.aligned.m16n8k16.row.col.f32.bf16.bf16.f32 "
        "{%0,%1,%2,%3}, {%4,%5,%6,%7}, {%8,%9}, {%0,%1,%2,%3};"
        : "+f"(c[0]), "+f"(c[1]), "+f"(c[2]), "+f"(c[3])
        : "r"(a[0]), "r"(a[1]), "r"(a[2]), "r"(a[3]), "r"(b0), "r"(b1));
}
__device__ __forceinline__ void ldsm2(uint32_t& r0, uint32_t& r1, uint32_t addr) {
    asm volatile("ldmatrix.sync.aligned.m8n8.x2.shared.b16 {%0,%1}, [%2];"
                 : "=r"(r0), "=r"(r1) : "r"(addr));
}
__device__ __forceinline__ void ldsm4(uint32_t r[4], uint32_t addr) {
    asm volatile("ldmatrix.sync.aligned.m8n8.x4.shared.b16 {%0,%1,%2,%3}, [%4];"
                 : "=r"(r[0]), "=r"(r[1]), "=r"(r[2]), "=r"(r[3]) : "r"(addr));
}
__device__ __forceinline__ uint32_t smem_to_u32(const void* smem_ptr) {
    uint32_t addr;
    asm("{ .reg .u64 tmp; cvta.to.shared.u64 tmp, %1; cvt.u32.u64 %0, tmp; }"
        : "=r"(addr) : "l"(smem_ptr));
    return addr;
}
__device__ __forceinline__ void cp16(uint32_t dst, const void* src) {
    asm volatile("cp.async.cg.shared.global [%0], [%1], 16;"
                 :: "r"(dst), "l"(src));
}
#define CP_COMMIT() asm volatile("cp.async.commit_group;" ::: "memory")
#define CP_WAIT0()  asm volatile("cp.async.wait_group 0;" ::: "memory")
#define CP_WAIT1()  asm volatile("cp.async.wait_group 1;" ::: "memory")

// ---------------- device scratch (no allocations allowed) ------------------
__device__ float g_A1[DIM * RANK];
__device__ float g_A2[DIM * RANK];
__device__ float g_qkv[HW * 3 * DIM];
__device__ float g_relh[NH * HW * GH];
__device__ float g_relw[NH * HW * GH];
// split-KV partials
__device__ __align__(16) float g_opart[KSPLIT * HW * DIM];
__device__ float g_lpart[KSPLIT * NH * HW];
// pre-split inputs / intermediates
__device__ __align__(16) __nv_bfloat16 g_xh[HW * DIM];
__device__ __align__(16) __nv_bfloat16 g_xl[HW * DIM];
__device__ __align__(16) __nv_bfloat16 g_oph[HW * DIM];
__device__ __align__(16) __nv_bfloat16 g_opl[HW * DIM];
// pre-split transposed weights: [N][K] bf16 hi/lo
__device__ __align__(16) __nv_bfloat16 g_wqkvT_h[3 * DIM * DIM];
__device__ __align__(16) __nv_bfloat16 g_wqkvT_l[3 * DIM * DIM];
__device__ __align__(16) __nv_bfloat16 g_wprojT_h[DIM * DIM];
__device__ __align__(16) __nv_bfloat16 g_wprojT_l[DIM * DIM];
// bf16 split K [head][key][dim] and transposed V [head][dim][key]
__device__ __align__(16) __nv_bfloat16 g_kh[NH * HW * HD];
__device__ __align__(16) __nv_bfloat16 g_kl[NH * HW * HD];
__device__ __align__(16) __nv_bfloat16 g_vh[NH * HD * HW];
__device__ __align__(16) __nv_bfloat16 g_vl[NH * HD * HW];

// ---------------- K0: A1 = FacTu @ q_FacTs, A2 = FacTu @ v_FacTs -----------
__global__ void fact_small_kernel(const float* __restrict__ FacTu,
                                  const float* __restrict__ qF,
                                  const float* __restrict__ vF) {
    int idx = blockIdx.x * 256 + threadIdx.x;
    if (idx >= DIM * RANK * 2) return;
    int which = idx / (DIM * RANK);
    int rem = idx - which * (DIM * RANK);
    int i = rem / RANK, r = rem - (rem / RANK) * RANK;
    const float* F = which ? vF : qF;
    float s = 0.f;
#pragma unroll
    for (int k = 0; k < RANK; k++) s += FacTu[i * RANK + k] * F[k * RANK + r];
    (which ? g_A2 : g_A1)[i * RANK + r] = s;
}

// ---------------- K0b: split x into bf16 hi/lo ------------------------------
__global__ void __launch_bounds__(256) xsplit_kernel(const float* __restrict__ x) {
    int idx = blockIdx.x * 256 + threadIdx.x;
    if (idx >= HW * DIM / 4) return;
    float4 v = *(const float4*)&x[idx * 4];
    uint32_t h0, l0, h1, l1;
    split2(v.x, v.y, h0, l0);
    split2(v.z, v.w, h1, l1);
    *(uint2*)&g_xh[idx * 4] = make_uint2(h0, h1);
    *(uint2*)&g_xl[idx * 4] = make_uint2(l0, l1);
}

// ---------------- K1: transpose + low-rank fold + bf16 split ---------------
__global__ void __launch_bounds__(256)
wsplit_kernel(const float* __restrict__ W, const float* __restrict__ FacTv,
              __nv_bfloat16* __restrict__ WTh, __nv_bfloat16* __restrict__ WTl,
              int NJ, int mode) {
    __shared__ float tile[32 * 33];
    const int tid = threadIdx.x;
    const int j0 = blockIdx.x * 32;
    const int i0 = blockIdx.y * 32;

    {
        const int j = tid & 31;
        const int ib = tid >> 5;
        const float* Aarr = nullptr;
        int jj = j0 + j;
        if (mode) {
            if (jj < DIM) Aarr = g_A1;
            else if (jj >= 2 * DIM) { Aarr = g_A2; jj -= 2 * DIM; }
        }
#pragma unroll
        for (int it = 0; it < 4; it++) {
            int il = ib + it * 8;
            int i = i0 + il;
            float w = W[(size_t)i * NJ + j0 + j];
            if (Aarr) {
                float s = 0.f;
#pragma unroll
                for (int r = 0; r < RANK; r++)
                    s += Aarr[i * RANK + r] * FacTv[r * DIM + jj];
                w += FACT_S * s;
            }
            tile[il * 33 + j] = w;
        }
    }
    __syncthreads();
    {
        const int i = tid & 31;
        const int jb = tid >> 5;
#pragma unroll
        for (int it = 0; it < 4; it++) {
            int jl = jb + it * 8;
            float v = tile[i * 33 + jl];
            __nv_bfloat16 h = __float2bfloat16(v);
            size_t o = (size_t)(j0 + jl) * DIM + i0 + i;
            WTh[o] = h;
            WTl[o] = __float2bfloat16(v - __bfloat162float(h));
        }
    }
}

// ---------------- K2: HMMA GEMM (all-bf16, cp.async double buffer) ----------
#define GS 40                 // smem row stride in bf16 (80B)
#define GARR 10240
#define GBUF 40960
__global__ void __launch_bounds__(256)
hgemm_bf16(const __nv_bfloat16* __restrict__ Ah_,
           const __nv_bfloat16* __restrict__ Al_,
           const __nv_bfloat16* __restrict__ Bh_,
           const __nv_bfloat16* __restrict__ Bl_,
           const float* __restrict__ bias, float* __restrict__ C,
           int M, int N, int K) {
    extern __shared__ __align__(16) char gsm[];
    const uint32_t smb = smem_to_u32(gsm);
    const int tid = threadIdx.x, lane = tid & 31, warp = tid >> 5;
    const int wm = (warp >> 2) * 64, wn = (warp & 3) * 32;
    const int bm = blockIdx.y * 128, bn = blockIdx.x * 128;

#define GB_ISSUE(k0) do { \
        _Pragma("unroll") \
        for (int t = 0; t < 8; t++) { \
            int i = tid + t * 256; \
            int arr = i >> 9, j = i & 511; \
            int row = j >> 2, c = j & 3; \
            const __nv_bfloat16* gptr = (arr == 0) ? Ah_ : (arr == 1) ? Al_ \
                                        : (arr == 2) ? Bh_ : Bl_; \
            int grow = (arr < 2 ? bm : bn) + row; \
            const char* src = (const char*)&gptr[(size_t)grow * K + (k0)] + c * 16; \
            cp16(sb + arr * GARR + row * 80 + c * 16, src); \
        } \
        CP_COMMIT(); \
    } while (0)

    float acc[4][4][4];
#pragma unroll
    for (int a = 0; a < 4; a++)
#pragma unroll
        for (int b = 0; b < 4; b++)
#pragma unroll
            for (int c = 0; c < 4; c++) acc[a][b][c] = 0.f;

    {
        uint32_t sb = smb;
        GB_ISSUE(0);
    }

    const uint32_t aoff = (uint32_t)((lane & 15) * GS + ((lane >> 4) << 3)) * 2;
    const uint32_t boff = (uint32_t)(((lane & 7) + ((lane & 16) >> 1)) * GS + (lane & 8)) * 2;

    const int NKT = K / 32;
    for (int kt = 0; kt < NKT; kt++) {
        CP_WAIT0();
        __syncthreads();
        if (kt + 1 < NKT) {
            uint32_t sb = smb + (uint32_t)((kt + 1) & 1) * GBUF;
            GB_ISSUE((kt + 1) * 32);
        }
        const uint32_t cb = smb + (uint32_t)(kt & 1) * GBUF;
        const uint32_t sAh = cb, sAl = cb + GARR, sBh = cb + 2 * GARR, sBl = cb + 3 * GARR;

#pragma unroll
        for (int ks = 0; ks < 2; ks++) {
            uint32_t ah[4][4], al[4][4];
#pragma unroll
            for (int mt = 0; mt < 4; mt++) {
                uint32_t off = (uint32_t)(wm + mt * 16) * (GS * 2) + (uint32_t)ks * 32 + aoff;
                ldsm4(ah[mt], sAh + off);
                ldsm4(al[mt], sAl + off);
            }
            uint32_t bh[2][4], bl[2][4];
#pragma unroll
            for (int nt = 0; nt < 2; nt++) {
                uint32_t off = (uint32_t)(wn + nt * 16) * (GS * 2) + (uint32_t)ks * 32 + boff;
                ldsm4(bh[nt], sBh + off);
                ldsm4(bl[nt], sBl + off);
            }
#pragma unroll
            for (int mt = 0; mt < 4; mt++)
#pragma unroll
                for (int nt = 0; nt < 4; nt++) {
                    uint32_t b0h = bh[nt >> 1][(nt & 1) * 2];
                    uint32_t b1h = bh[nt >> 1][(nt & 1) * 2 + 1];
                    uint32_t b0l = bl[nt >> 1][(nt & 1) * 2];
                    uint32_t b1l = bl[nt >> 1][(nt & 1) * 2 + 1];
                    mma16816(acc[mt][nt], ah[mt], b0h, b1h);
                    mma16816(acc[mt][nt], al[mt], b0h, b1h);
                    mma16816(acc[mt][nt], ah[mt], b0l, b1l);
                }
        }
        __syncthreads();
    }

    const int gid = lane >> 2, tig = lane & 3;
#pragma unroll
    for (int mt = 0; mt < 4; mt++) {
        int m0 = bm + wm + mt * 16 + gid;
#pragma unroll
        for (int nt = 0; nt < 4; nt++) {
            int n0 = bn + wn + nt * 8 + 2 * tig;
            float bx = bias ? bias[n0] : 0.f;
            float by = bias ? bias[n0 + 1] : 0.f;
            *(float2*)&C[(size_t)m0 * N + n0] =
                make_float2(acc[mt][nt][0] + bx, acc[mt][nt][1] + by);
            *(float2*)&C[(size_t)(m0 + 8) * N + n0] =
                make_float2(acc[mt][nt][2] + bx, acc[mt][nt][3] + by);
        }
    }
}
#define HG_SMEM (2 * GBUF)

// ---------------- K3: rel bias tables ---------------------------------------
__global__ void __launch_bounds__(256) rel_tab2_kernel(const float* __restrict__ rph,
                                                       const float* __restrict__ rpw) {
    __shared__ float Qs[GH * 68];
    __shared__ float Rs[GH * 68];
    const int pos = blockIdx.x;
    const int head = blockIdx.y;
    const int which = blockIdx.z;
    const int tid = threadIdx.x;

    for (int i = tid; i < GH * HD; i += 256) {
        int r = i >> 6, c = i & 63;
        int t = which ? (r * GH + pos) : (pos * GH + r);
        Qs[r * 68 + c] = g_qkv[(size_t)t * (3 * DIM) + head * HD + c];
    }
    const float* rp = which ? rpw : rph;
    for (int i = tid; i < GH * HD; i += 256) {
        int k = i >> 6, c = i & 63;
        Rs[k * 68 + c] = rp[(pos - k + GH - 1) * HD + c];
    }
    __syncthreads();

    const int tx = tid & 15, ty = tid >> 4;
    u64 acc[3][3];
#pragma unroll
    for (int i = 0; i < 3; i++)
#pragma unroll
        for (int j = 0; j < 3; j++) acc[i][j] = 0ull;

    for (int c = 0; c < HD; c += 4) {
        ulonglong2 q[3], r[3];
#pragma unroll
        for (int i = 0; i < 3; i++) q[i] = *(const ulonglong2*)&Qs[(ty * 3 + i) * 68 + c];
#pragma unroll
        for (int j = 0; j < 3; j++) r[j] = *(const ulonglong2*)&Rs[(tx * 3 + j) * 68 + c];
#pragma unroll
        for (int i = 0; i < 3; i++)
#pragma unroll
            for (int j = 0; j < 3; j++) {
                ffma2(acc[i][j], q[i].x, r[j].x);
                ffma2(acc[i][j], q[i].y, r[j].y);
            }
    }

    float* outp = which ? g_relw : g_relh;
#pragma unroll
    for (int i = 0; i < 3; i++) {
        int row = ty * 3 + i;
        int t = which ? (row * GH + pos) : (pos * GH + row);
#pragma unroll
        for (int j = 0; j < 3; j++) {
            float lo, hi;
            unpack2f(acc[i][j], lo, hi);
            outp[((size_t)head * HW + t) * GH + tx * 3 + j] = lo + hi;
        }
    }
}

// ---------------- K3b: split K and transposed V into bf16 hi/lo -------------
__global__ void __launch_bounds__(256) kv_prep_kernel() {
    __shared__ float vs[64 * 65];
    const int kt0 = blockIdx.x * 64;
    const int head = blockIdx.y;
    const int tid = threadIdx.x;

    for (int i = tid; i < 64 * 64; i += 256) {
        int r = i >> 6, c = i & 63;
        const float* src = &g_qkv[(size_t)(kt0 + r) * (3 * DIM) + head * HD + c];
        float kv = src[DIM];
        __nv_bfloat16 kh = __float2bfloat16(kv);
        size_t ko = ((size_t)head * HW + kt0 + r) * HD + c;
        g_kh[ko] = kh;
        g_kl[ko] = __float2bfloat16(kv - __bfloat162float(kh));
        vs[r * 65 + c] = src[2 * DIM];
    }
    __syncthreads();
    for (int i = tid; i < 64 * 64; i += 256) {
        int d = i >> 6, k = i & 63;
        float v = vs[k * 65 + d];
        __nv_bfloat16 vh = __float2bfloat16(v);
        size_t vo = ((size_t)head * HD + d) * HW + kt0 + k;
        g_vh[vo] = vh;
        g_vl[vo] = __float2bfloat16(v - __bfloat162float(vh));
    }
}

// ---------------- K4: pipelined split-KV mma.sync flash attention -----------
#define ROWB   144            // 72 bf16 = 144 bytes per padded row
#define ARR_SZ (64 * ROWB)    // 9216
#define SB_KLO ARR_SZ
#define SB_V   (2 * ARR_SZ)
#define SB_VLO (3 * ARR_SZ)
#define BUF_SZ (4 * ARR_SZ)   // 36864
#define SM_RH  (3 * BUF_SZ)                 // 110592
#define SM_RW  (SM_RH + 128 * GH * 4)       // +24576
#define SM_TOT (SM_RW + 128 * GH * 4)       // 159744 (156KB) -> 1 CTA/SM

__device__ __forceinline__ void copy_kv_async(uint32_t dstb, int head, int kt0) {
    const int tid = threadIdx.x;   // 256 threads
    const char* khb = (const char*)(g_kh + ((size_t)head * HW + kt0) * HD);
    const char* klb = (const char*)(g_kl + ((size_t)head * HW + kt0) * HD);
#pragma unroll
    for (int it = 0; it < 2; it++) {
        int i = tid + it * 256;
        int r = i >> 3, c = i & 7;
        uint32_t d = r * ROWB + c * 16;
        cp16(dstb + d, khb + i * 16);
        cp16(dstb + SB_KLO + d, klb + i * 16);
    }
    const char* vhb = (const char*)(g_vh + (size_t)head * HD * HW + kt0);
    const char* vlb = (const char*)(g_vl + (size_t)head * HD * HW + kt0);
#pragma unroll
    for (int it = 0; it < 2; it++) {
        int i = tid + it * 256;
        int dr = i >> 3, c = i & 7;
        uint32_t d = dr * ROWB + c * 16;
        size_t go = (size_t)dr * (HW * 2) + c * 16;
        cp16(dstb + SB_V + d, vhb + go);
        cp16(dstb + SB_VLO + d, vlb + go);
    }
    CP_COMMIT();
}

__device__ __forceinline__ void s_mma_tile(float S[8][4], uint32_t kb,
                                           const uint32_t qhi[4][4],
                                           const uint32_t qlo[4][4],
                                           uint32_t lmoff) {
#pragma unroll
    for (int j = 0; j < 8; j++) {
#pragma unroll
        for (int i = 0; i < 4; i++) S[j][i] = 0.f;
        uint32_t base = kb + (uint32_t)j * (8 * ROWB) + lmoff;
#pragma unroll
        for (int s = 0; s < 4; s++) {
            uint32_t bh0, bh1, bl0, bl1;
            ldsm2(bh0, bh1, base + s * 32);
            ldsm2(bl0, bl1, base + SB_KLO + s * 32);
            mma16816(S[j], qhi[s], bh0, bh1);
            mma16816(S[j], qlo[s], bh0, bh1);
            mma16816(S[j], qhi[s], bl0, bl1);
        }
    }
}

__global__ void __launch_bounds__(256) attn_mma_kernel() {
    extern __shared__ char smc[];
    const uint32_t smb = smem_to_u32(smc);
    const int tid = threadIdx.x, lane = tid & 31, warp = tid >> 5;   // 8 warps
    const int gid = lane >> 2, tig = lane & 3;
    const int head = blockIdx.y;
    const int qt0 = blockIdx.x * 128;
    const int zs = blockIdx.z;
    const int T0 = zs * NTT;

    copy_kv_async(smb, head, T0 * 64);
    copy_kv_async(smb + BUF_SZ, head, (T0 + 1) * 64);

    float* Rh = (float*)(smc + SM_RH);
    float* Rw = (float*)(smc + SM_RW);
    {
        const float4* sH = (const float4*)&g_relh[((size_t)head * HW + qt0) * GH];
        const float4* sW = (const float4*)&g_relw[((size_t)head * HW + qt0) * GH];
        float4* dH = (float4*)Rh;
        float4* dW = (float4*)Rw;
        for (int i = tid; i < 128 * GH / 4; i += 256) { dH[i] = sH[i]; dW[i] = sW[i]; }
    }

    uint32_t qhi[4][4], qlo[4][4];
    {
        const float* q0 = &g_qkv[(size_t)(qt0 + warp * 16 + gid) * (3 * DIM) + head * HD];
        const float* q1 = q0 + (size_t)8 * (3 * DIM);
#pragma unroll
        for (int s = 0; s < 4; s++) {
            int c = 16 * s + 2 * tig;
            float2 v;
            v = *(const float2*)&q0[c];
            split2(QK_SCALE * v.x, QK_SCALE * v.y, qhi[s][0], qlo[s][0]);
            v = *(const float2*)&q1[c];
            split2(QK_SCALE * v.x, QK_SCALE * v.y, qhi[s][1], qlo[s][1]);
            v = *(const float2*)&q0[c + 8];
            split2(QK_SCALE * v.x, QK_SCALE * v.y, qhi[s][2], qlo[s][2]);
            v = *(const float2*)&q1[c + 8];
            split2(QK_SCALE * v.x, QK_SCALE * v.y, qhi[s][3], qlo[s][3]);
        }
    }

    const uint32_t lmoff = (uint32_t)((lane & 7) * ROWB + (lane & 8) * 2);

    CP_WAIT1();            // buf0 complete (buf1 in flight)
    __syncthreads();

    float Scur[8][4], Snext[8][4];
    s_mma_tile(Scur, smb, qhi, qlo, lmoff);

    float Oacc[8][4];
#pragma unroll
    for (int j = 0; j < 8; j++)
#pragma unroll
        for (int i = 0; i < 4; i++) Oacc[j][i] = 0.f;
    float rs0 = 0.f, rs1 = 0.f;

    const float* rh0 = &Rh[(warp * 16 + gid) * GH];
    const float* rh1 = rh0 + 8 * GH;
    const float* rw0 = &Rw[(warp * 16 + gid) * GH];
    const float* rw1 = rw0 + 8 * GH;

    for (int tt = 0; tt < NTT; tt++) {
        const int kt0 = (T0 + tt) * 64;
        __syncthreads();   // all warps done reading buf((tt-1)%3) from PV(tt-1)
        if (tt + 2 < NTT)
            copy_kv_async(smb + (uint32_t)((tt + 2) % 3) * BUF_SZ, head, (T0 + tt + 2) * 64);
        if (tt + 1 < NTT) {
            if (tt + 2 < NTT) { CP_WAIT1(); } else { CP_WAIT0(); }
            __syncthreads();   // buf(tt+1) visible to all warps
            s_mma_tile(Snext, smb + (uint32_t)((tt + 1) % 3) * BUF_SZ, qhi, qlo, lmoff);
        }

        // softmax on Scur (tile tt) — results are a full iteration old
#pragma unroll
        for (int j = 0; j < 8; j++) {
            int k0 = kt0 + 8 * j + 2 * tig;
            int hk0 = k0 / GH, wk0 = k0 - hk0 * GH;
            int k1 = k0 + 1;
            int hk1 = k1 / GH, wk1 = k1 - hk1 * GH;
            float e0 = __expf(Scur[j][0] + rh0[hk0] + rw0[wk0]);
            float e1 = __expf(Scur[j][1] + rh0[hk1] + rw0[wk1]);
            float e2 = __expf(Scur[j][2] + rh1[hk0] + rw1[wk0]);
            float e3 = __expf(Scur[j][3] + rh1[hk1] + rw1[wk1]);
            rs0 += e0 + e1;
            rs1 += e2 + e3;
            Scur[j][0] = e0; Scur[j][1] = e1; Scur[j][2] = e2; Scur[j][3] = e3;
        }

        uint32_t phi[4][4], plo[4][4];
#pragma unroll
        for (int s = 0; s < 4; s++) {
            split2(Scur[2 * s][0],     Scur[2 * s][1],     phi[s][0], plo[s][0]);
            split2(Scur[2 * s][2],     Scur[2 * s][3],     phi[s][1], plo[s][1]);
            split2(Scur[2 * s + 1][0], Scur[2 * s + 1][1], phi[s][2], plo[s][2]);
            split2(Scur[2 * s + 1][2], Scur[2 * s + 1][3], phi[s][3], plo[s][3]);
        }

        const uint32_t vb = smb + (uint32_t)(tt % 3) * BUF_SZ + SB_V;
#pragma unroll
        for (int j = 0; j < 8; j++) {
            uint32_t base = vb + (uint32_t)j * (8 * ROWB) + lmoff;
#pragma unroll
            for (int s = 0; s < 4; s++) {
                uint32_t vh0, vh1, vl0, vl1;
                ldsm2(vh0, vh1, base + s * 32);
                ldsm2(vl0, vl1, base + ARR_SZ + s * 32);
                mma16816(Oacc[j], phi[s], vh0, vh1);
                mma16816(Oacc[j], plo[s], vh0, vh1);
                mma16816(Oacc[j], phi[s], vl0, vl1);
            }
        }

        if (tt + 1 < NTT) {
#pragma unroll
            for (int j = 0; j < 8; j++)
#pragma unroll
                for (int i = 0; i < 4; i++) Scur[j][i] = Snext[j][i];
        }
    }

    // partial row-sums + unnormalized partial O to gmem
    rs0 += __shfl_xor_sync(0xffffffffu, rs0, 1);
    rs0 += __shfl_xor_sync(0xffffffffu, rs0, 2);
    rs1 += __shfl_xor_sync(0xffffffffu, rs1, 1);
    rs1 += __shfl_xor_sync(0xffffffffu, rs1, 2);

    const int row0 = qt0 + warp * 16 + gid;
    if (tig == 0) {
        g_lpart[(size_t)zs * NH * HW + (size_t)head * HW + row0] = rs0;
        g_lpart[(size_t)zs * NH * HW + (size_t)head * HW + row0 + 8] = rs1;
    }
    float* op = g_opart + (size_t)zs * HW * DIM;
    const size_t r0 = (size_t)row0 * DIM + head * HD;
    const size_t r1 = r0 + (size_t)8 * DIM;
#pragma unroll
    for (int j = 0; j < 8; j++) {
        int c = 8 * j + 2 * tig;
        *(float2*)&op[r0 + c] = make_float2(Oacc[j][0], Oacc[j][1]);
        *(float2*)&op[r1 + c] = make_float2(Oacc[j][2], Oacc[j][3]);
    }
}

// ---------------- K4b: combine split-KV partials -> bf16 hi/lo --------------
__global__ void __launch_bounds__(256) combine_kernel() {
    int idx = blockIdx.x * 256 + threadIdx.x;   // 2 cols per thread
    if (idx >= HW * DIM / 2) return;
    int row = idx / (DIM / 2);
    int cc = (idx - row * (DIM / 2)) * 2;
    int head = cc >> 6;
    float l = g_lpart[(size_t)head * HW + row]
            + g_lpart[(size_t)NH * HW + (size_t)head * HW + row];
    float inv = 1.f / l;
    size_t o = (size_t)row * DIM + cc;
    float2 o0 = *(const float2*)&g_opart[o];
    float2 o1 = *(const float2*)&g_opart[(size_t)HW * DIM + o];
    uint32_t h, lo;
    split2((o0.x + o1.x) * inv, (o0.y + o1.y) * inv, h, lo);
    *(uint32_t*)&g_oph[o] = h;
    *(uint32_t*)&g_opl[o] = lo;
}

// ---------------- launch -----------------------------------------------------
extern "C" void kernel_launch(void* const* d_in, const int* in_sizes, int n_in,
                              void* d_out, int out_size) {
    const float* x     = (const float*)d_in[0];
    const float* Wqkv  = (const float*)d_in[1];
    const float* bqkv  = (const float*)d_in[2];
    const float* FacTu = (const float*)d_in[3];
    const float* FacTv = (const float*)d_in[4];
    const float* qF    = (const float*)d_in[5];
    const float* vF    = (const float*)d_in[6];
    const float* rph   = (const float*)d_in[7];
    const float* rpw   = (const float*)d_in[8];
    const float* Wproj = (const float*)d_in[9];
    const float* bproj = (const float*)d_in[10];
    float* out = (float*)d_out;

    void *pQkv, *pXh, *pXl, *pOph, *pOpl, *pWqT_h, *pWqT_l, *pWpT_h, *pWpT_l;
    cudaGetSymbolAddress(&pQkv, g_qkv);
    cudaGetSymbolAddress(&pXh, g_xh);
    cudaGetSymbolAddress(&pXl, g_xl);
    cudaGetSymbolAddress(&pOph, g_oph);
    cudaGetSymbolAddress(&pOpl, g_opl);
    cudaGetSymbolAddress(&pWqT_h, g_wqkvT_h);
    cudaGetSymbolAddress(&pWqT_l, g_wqkvT_l);
    cudaGetSymbolAddress(&pWpT_h, g_wprojT_h);
    cudaGetSymbolAddress(&pWpT_l, g_wprojT_l);

    cudaFuncSetAttribute(attn_mma_kernel,
                         cudaFuncAttributeMaxDynamicSharedMemorySize, (int)SM_TOT);
    cudaFuncSetAttribute(hgemm_bf16,
                         cudaFuncAttributeMaxDynamicSharedMemorySize, (int)HG_SMEM);

    fact_small_kernel<<<(DIM * RANK * 2 + 255) / 256, 256>>>(FacTu, qF, vF);
    xsplit_kernel<<<(HW * DIM / 4 + 255) / 256, 256>>>(x);

    {   // Wqkv (+delta) -> transposed split
        dim3 grid((3 * DIM) / 32, DIM / 32);
        wsplit_kernel<<<grid, 256>>>(Wqkv, FacTv,
                                     (__nv_bfloat16*)pWqT_h, (__nv_bfloat16*)pWqT_l,
                                     3 * DIM, 1);
    }
    {   // Wproj -> transposed split
        dim3 grid(DIM / 32, DIM / 32);
        wsplit_kernel<<<grid, 256>>>(Wproj, FacTv,
                                     (__nv_bfloat16*)pWpT_h, (__nv_bfloat16*)pWpT_l,
                                     DIM, 0);
    }
    {   // qkv = x @ Weff + bqkv (HMMA, all-bf16)
        dim3 grid((3 * DIM) / 128, HW / 128);
        hgemm_bf16<<<grid, 256, HG_SMEM>>>((const __nv_bfloat16*)pXh,
                                           (const __nv_bfloat16*)pXl,
                                           (const __nv_bfloat16*)pWqT_h,
                                           (const __nv_bfloat16*)pWqT_l,
                                           bqkv, (float*)pQkv, HW, 3 * DIM, DIM);
    }
    {   // rel-pos tables
        dim3 grid(GH, NH, 2);
        rel_tab2_kernel<<<grid, 256>>>(rph, rpw);
    }
    {   // bf16 split K / transposed V
        dim3 grid(HW / 64, NH);
        kv_prep_kernel<<<grid, 256>>>();
    }
    {   // pipelined split-KV tensor-core attention
        dim3 grid(HW / 128, NH, KSPLIT);
        attn_mma_kernel<<<grid, 256, SM_TOT>>>();
    }
    {   // combine partials
        combine_kernel<<<(HW * DIM / 2 + 255) / 256, 256>>>();
    }
    {   // out = opre @ Wproj + bproj (HMMA, all-bf16)
        dim3 grid(DIM / 128, HW / 128);
        hgemm_bf16<<<grid, 256, HG_SMEM>>>((const __nv_bfloat16*)pOph,
                                           (const __nv_bfloat16*)pOpl,
                                           (const __nv_bfloat16*)pWpT_h,
                                           (const __nv_bfloat16*)pWpT_l,
                                           bproj, out, HW, DIM, DIM);
    }
}

// round 10
// speedup vs baseline: 1.2908x; 1.0710x over previous
#include <cuda_runtime.h>
#include <cuda_bf16.h>
#include <cstdint>

#define DIM   768
#define NH    12
#define HD    64
#define GH    48           // grid H = W
#define HW    2304         // 48*48
#define RANK  32
#define QK_SCALE 0.125f    // 64^-0.5
#define FACT_S 1.0f
#define NT    36           // kv tiles of 64
#define KSPLIT 2
#define NTT   (NT / KSPLIT)  // 18 tiles per split

typedef unsigned long long u64;

// ---------------- packed helpers --------------------------------------------
__device__ __forceinline__ u64 pack2f(float a, float b) {
    u64 r;
    asm("mov.b64 %0, {%1, %2};" : "=l"(r)
        : "r"(__float_as_uint(a)), "r"(__float_as_uint(b)));
    return r;
}
__device__ __forceinline__ void unpack2f(u64 v, float& a, float& b) {
    unsigned x, y;
    asm("mov.b64 {%0, %1}, %2;" : "=r"(x), "=r"(y) : "l"(v));
    a = __uint_as_float(x);
    b = __uint_as_float(y);
}
__device__ __forceinline__ void ffma2(u64& d, u64 a, u64 b) {
    asm("fma.rn.f32x2 %0, %1, %2, %0;" : "+l"(d) : "l"(a), "l"(b));
}
__device__ __forceinline__ uint32_t cvt_bf16x2(float a, float b) {
    uint32_t r;
    asm("cvt.rn.bf16x2.f32 %0, %1, %2;" : "=r"(r) : "f"(b), "f"(a));
    return r;
}
__device__ __forceinline__ void split2(float a, float b, uint32_t& hi, uint32_t& lo) {
    uint32_t h = cvt_bf16x2(a, b);
    float ra = __uint_as_float(h << 16);
    float rb = __uint_as_float(h & 0xffff0000u);
    hi = h;
    lo = cvt_bf16x2(a - ra, b - rb);
}

// ---------------- mma / ldmatrix / cp.async helpers --------------------------
__device__ __forceinline__ void mma16816(float c[4], const uint32_t a[4],
                                         uint32_t b0, uint32_t b1) {
    asm volatile(
        "mma.sync.aligned.m16n8k16.row.col.f32.bf16.bf16.f32 "
        "{%0,%1,%2,%3}, {%4,%5,%6,%7}, {%8,%9}, {%0,%1,%2,%3};"
        : "+f"(c[0]), "+f"(c[1]), "+f"(c[2]), "+f"(c[3])
        : "r"(a[0]), "r"(a[1]), "r"(a[2]), "r"(a[3]), "r"(b0), "r"(b1));
}
__device__ __forceinline__ void ldsm2(uint32_t& r0, uint32_t& r1, uint32_t addr) {
    asm volatile("ldmatrix.sync.aligned.m8n8.x2.shared.b16 {%0,%1}, [%2];"
                 : "=r"(r0), "=r"(r1) : "r"(addr));
}
__device__ __forceinline__ void ldsm4(uint32_t r[4], uint32_t addr) {
    asm volatile("ldmatrix.sync.aligned.m8n8.x4.shared.b16 {%0,%1,%2,%3}, [%4];"
                 : "=r"(r[0]), "=r"(r[1]), "=r"(r[2]), "=r"(r[3]) : "r"(addr));
}
__device__ __forceinline__ uint32_t smem_to_u32(const void* smem_ptr) {
    uint32_t addr;
    asm("{ .reg .u64 tmp; cvta.to.shared.u64 tmp, %1; cvt.u32.u64 %0, tmp; }"
        : "=r"(addr) : "l"(smem_ptr));
    return addr;
}
__device__ __forceinline__ void cp16(uint32_t dst, const void* src) {
    asm volatile("cp.async.cg.shared.global [%0], [%1], 16;"
                 :: "r"(dst), "l"(src));
}
#define CP_COMMIT() asm volatile("cp.async.commit_group;" ::: "memory")
#define CP_WAIT0()  asm volatile("cp.async.wait_group 0;" ::: "memory")
#define CP_WAIT1()  asm volatile("cp.async.wait_group 1;" ::: "memory")

// ---------------- device scratch (no allocations allowed) ------------------
__device__ float g_A1[DIM * RANK];
__device__ float g_A2[DIM * RANK];
__device__ float g_qkv[HW * 3 * DIM];
__device__ float g_relh[NH * HW * GH];
__device__ float g_relw[NH * HW * GH];
// split-KV partials
__device__ __align__(16) float g_opart[KSPLIT * HW * DIM];
__device__ float g_lpart[KSPLIT * NH * HW];
// pre-split inputs / intermediates
__device__ __align__(16) __nv_bfloat16 g_xh[HW * DIM];
__device__ __align__(16) __nv_bfloat16 g_xl[HW * DIM];
__device__ __align__(16) __nv_bfloat16 g_oph[HW * DIM];
__device__ __align__(16) __nv_bfloat16 g_opl[HW * DIM];
// pre-split transposed weights: [N][K] bf16 hi/lo
__device__ __align__(16) __nv_bfloat16 g_wqkvT_h[3 * DIM * DIM];
__device__ __align__(16) __nv_bfloat16 g_wqkvT_l[3 * DIM * DIM];
__device__ __align__(16) __nv_bfloat16 g_wprojT_h[DIM * DIM];
__device__ __align__(16) __nv_bfloat16 g_wprojT_l[DIM * DIM];
// bf16 split K [head][key][dim] and transposed V [head][dim][key]
__device__ __align__(16) __nv_bfloat16 g_kh[NH * HW * HD];
__device__ __align__(16) __nv_bfloat16 g_kl[NH * HW * HD];
__device__ __align__(16) __nv_bfloat16 g_vh[NH * HD * HW];
__device__ __align__(16) __nv_bfloat16 g_vl[NH * HD * HW];

// ---------------- K0: A1 = FacTu @ q_FacTs, A2 = FacTu @ v_FacTs -----------
__global__ void fact_small_kernel(const float* __restrict__ FacTu,
                                  const float* __restrict__ qF,
                                  const float* __restrict__ vF) {
    int idx = blockIdx.x * 256 + threadIdx.x;
    if (idx >= DIM * RANK * 2) return;
    int which = idx / (DIM * RANK);
    int rem = idx - which * (DIM * RANK);
    int i = rem / RANK, r = rem - (rem / RANK) * RANK;
    const float* F = which ? vF : qF;
    float s = 0.f;
#pragma unroll
    for (int k = 0; k < RANK; k++) s += FacTu[i * RANK + k] * F[k * RANK + r];
    (which ? g_A2 : g_A1)[i * RANK + r] = s;
}

// ---------------- K0b: split x into bf16 hi/lo ------------------------------
__global__ void __launch_bounds__(256) xsplit_kernel(const float* __restrict__ x) {
    int idx = blockIdx.x * 256 + threadIdx.x;
    if (idx >= HW * DIM / 4) return;
    float4 v = *(const float4*)&x[idx * 4];
    uint32_t h0, l0, h1, l1;
    split2(v.x, v.y, h0, l0);
    split2(v.z, v.w, h1, l1);
    *(uint2*)&g_xh[idx * 4] = make_uint2(h0, h1);
    *(uint2*)&g_xl[idx * 4] = make_uint2(l0, l1);
}

// ---------------- K1: transpose + low-rank fold + bf16 split ---------------
__global__ void __launch_bounds__(256)
wsplit_kernel(const float* __restrict__ W, const float* __restrict__ FacTv,
              __nv_bfloat16* __restrict__ WTh, __nv_bfloat16* __restrict__ WTl,
              int NJ, int mode) {
    __shared__ float tile[32 * 33];
    const int tid = threadIdx.x;
    const int j0 = blockIdx.x * 32;
    const int i0 = blockIdx.y * 32;

    {
        const int j = tid & 31;
        const int ib = tid >> 5;
        const float* Aarr = nullptr;
        int jj = j0 + j;
        if (mode) {
            if (jj < DIM) Aarr = g_A1;
            else if (jj >= 2 * DIM) { Aarr = g_A2; jj -= 2 * DIM; }
        }
#pragma unroll
        for (int it = 0; it < 4; it++) {
            int il = ib + it * 8;
            int i = i0 + il;
            float w = W[(size_t)i * NJ + j0 + j];
            if (Aarr) {
                float s = 0.f;
#pragma unroll
                for (int r = 0; r < RANK; r++)
                    s += Aarr[i * RANK + r] * FacTv[r * DIM + jj];
                w += FACT_S * s;
            }
            tile[il * 33 + j] = w;
        }
    }
    __syncthreads();
    {
        const int i = tid & 31;
        const int jb = tid >> 5;
#pragma unroll
        for (int it = 0; it < 4; it++) {
            int jl = jb + it * 8;
            float v = tile[i * 33 + jl];
            __nv_bfloat16 h = __float2bfloat16(v);
            size_t o = (size_t)(j0 + jl) * DIM + i0 + i;
            WTh[o] = h;
            WTl[o] = __float2bfloat16(v - __bfloat162float(h));
        }
    }
}

// ---------------- K2: HMMA GEMM (96x128 tile, all-bf16, cp.async) -----------
// C[M][N] = Apair @ Bpair^T + bias.  A hi/lo [M][K], B hi/lo [N][K]. K%32==0.
// M % 96 == 0, N % 128 == 0.
#define GS 40                 // smem row stride in bf16 (80B)
#define A_CH 384              // cp16 chunks per A array (96 rows * 4)
#define B_CH 512              // cp16 chunks per B array (128 rows * 4)
#define AARR 7680             // bytes per A array (96*80)
#define BARR 10240            // bytes per B array (128*80)
#define STG  35840            // bytes per stage (2*AARR + 2*BARR)
__global__ void __launch_bounds__(256)
hgemm_bf16(const __nv_bfloat16* __restrict__ Ah_,
           const __nv_bfloat16* __restrict__ Al_,
           const __nv_bfloat16* __restrict__ Bh_,
           const __nv_bfloat16* __restrict__ Bl_,
           const float* __restrict__ bias, float* __restrict__ C,
           int M, int N, int K) {
    extern __shared__ __align__(16) char gsm[];
    const uint32_t smb = smem_to_u32(gsm);
    const int tid = threadIdx.x, lane = tid & 31, warp = tid >> 5;
    const int wm = (warp >> 2) * 48, wn = (warp & 3) * 32;
    const int bm = blockIdx.y * 96, bn = blockIdx.x * 128;

#define GB_ISSUE(k0) do { \
        _Pragma("unroll") \
        for (int t = 0; t < 7; t++) { \
            int i = tid + t * 256; \
            const __nv_bfloat16* gptr; uint32_t soff; int j, grow; \
            if (i < A_CH) { gptr = Ah_; soff = 0; j = i; grow = bm; } \
            else if (i < 2 * A_CH) { gptr = Al_; soff = AARR; j = i - A_CH; grow = bm; } \
            else if (i < 2 * A_CH + B_CH) { gptr = Bh_; soff = 2 * AARR; j = i - 2 * A_CH; grow = bn; } \
            else { gptr = Bl_; soff = 2 * AARR + BARR; j = i - 2 * A_CH - B_CH; grow = bn; } \
            int row = j >> 2, c = j & 3; \
            grow += row; \
            const char* src = (const char*)&gptr[(size_t)grow * K + (k0)] + c * 16; \
            cp16(sb + soff + row * 80 + c * 16, src); \
        } \
        CP_COMMIT(); \
    } while (0)

    float acc[3][4][4];
#pragma unroll
    for (int a = 0; a < 3; a++)
#pragma unroll
        for (int b = 0; b < 4; b++)
#pragma unroll
            for (int c = 0; c < 4; c++) acc[a][b][c] = 0.f;

    {
        uint32_t sb = smb;
        GB_ISSUE(0);
    }

    const uint32_t aoff = (uint32_t)((lane & 15) * GS + ((lane >> 4) << 3)) * 2;
    const uint32_t boff = (uint32_t)(((lane & 7) + ((lane & 16) >> 1)) * GS + (lane & 8)) * 2;

    const int NKT = K / 32;
    for (int kt = 0; kt < NKT; kt++) {
        CP_WAIT0();
        __syncthreads();
        if (kt + 1 < NKT) {
            uint32_t sb = smb + (uint32_t)((kt + 1) & 1) * STG;
            GB_ISSUE((kt + 1) * 32);
        }
        const uint32_t cb = smb + (uint32_t)(kt & 1) * STG;
        const uint32_t sAh = cb, sAl = cb + AARR;
        const uint32_t sBh = cb + 2 * AARR, sBl = cb + 2 * AARR + BARR;

#pragma unroll
        for (int ks = 0; ks < 2; ks++) {
            uint32_t ah[3][4], al[3][4];
#pragma unroll
            for (int mt = 0; mt < 3; mt++) {
                uint32_t off = (uint32_t)(wm + mt * 16) * (GS * 2) + (uint32_t)ks * 32 + aoff;
                ldsm4(ah[mt], sAh + off);
                ldsm4(al[mt], sAl + off);
            }
            uint32_t bh[2][4], bl[2][4];
#pragma unroll
            for (int nt = 0; nt < 2; nt++) {
                uint32_t off = (uint32_t)(wn + nt * 16) * (GS * 2) + (uint32_t)ks * 32 + boff;
                ldsm4(bh[nt], sBh + off);
                ldsm4(bl[nt], sBl + off);
            }
#pragma unroll
            for (int mt = 0; mt < 3; mt++)
#pragma unroll
                for (int nt = 0; nt < 4; nt++) {
                    uint32_t b0h = bh[nt >> 1][(nt & 1) * 2];
                    uint32_t b1h = bh[nt >> 1][(nt & 1) * 2 + 1];
                    uint32_t b0l = bl[nt >> 1][(nt & 1) * 2];
                    uint32_t b1l = bl[nt >> 1][(nt & 1) * 2 + 1];
                    mma16816(acc[mt][nt], ah[mt], b0h, b1h);
                    mma16816(acc[mt][nt], al[mt], b0h, b1h);
                    mma16816(acc[mt][nt], ah[mt], b0l, b1l);
                }
        }
        __syncthreads();
    }

    const int gid = lane >> 2, tig = lane & 3;
#pragma unroll
    for (int mt = 0; mt < 3; mt++) {
        int m0 = bm + wm + mt * 16 + gid;
#pragma unroll
        for (int nt = 0; nt < 4; nt++) {
            int n0 = bn + wn + nt * 8 + 2 * tig;
            float bx = bias ? bias[n0] : 0.f;
            float by = bias ? bias[n0 + 1] : 0.f;
            *(float2*)&C[(size_t)m0 * N + n0] =
                make_float2(acc[mt][nt][0] + bx, acc[mt][nt][1] + by);
            *(float2*)&C[(size_t)(m0 + 8) * N + n0] =
                make_float2(acc[mt][nt][2] + bx, acc[mt][nt][3] + by);
        }
    }
}
#define HG_SMEM (2 * STG)

// ---------------- K3: rel bias tables ---------------------------------------
__global__ void __launch_bounds__(256) rel_tab2_kernel(const float* __restrict__ rph,
                                                       const float* __restrict__ rpw) {
    __shared__ float Qs[GH * 68];
    __shared__ float Rs[GH * 68];
    const int pos = blockIdx.x;
    const int head = blockIdx.y;
    const int which = blockIdx.z;
    const int tid = threadIdx.x;

    for (int i = tid; i < GH * HD; i += 256) {
        int r = i >> 6, c = i & 63;
        int t = which ? (r * GH + pos) : (pos * GH + r);
        Qs[r * 68 + c] = g_qkv[(size_t)t * (3 * DIM) + head * HD + c];
    }
    const float* rp = which ? rpw : rph;
    for (int i = tid; i < GH * HD; i += 256) {
        int k = i >> 6, c = i & 63;
        Rs[k * 68 + c] = rp[(pos - k + GH - 1) * HD + c];
    }
    __syncthreads();

    const int tx = tid & 15, ty = tid >> 4;
    u64 acc[3][3];
#pragma unroll
    for (int i = 0; i < 3; i++)
#pragma unroll
        for (int j = 0; j < 3; j++) acc[i][j] = 0ull;

    for (int c = 0; c < HD; c += 4) {
        ulonglong2 q[3], r[3];
#pragma unroll
        for (int i = 0; i < 3; i++) q[i] = *(const ulonglong2*)&Qs[(ty * 3 + i) * 68 + c];
#pragma unroll
        for (int j = 0; j < 3; j++) r[j] = *(const ulonglong2*)&Rs[(tx * 3 + j) * 68 + c];
#pragma unroll
        for (int i = 0; i < 3; i++)
#pragma unroll
            for (int j = 0; j < 3; j++) {
                ffma2(acc[i][j], q[i].x, r[j].x);
                ffma2(acc[i][j], q[i].y, r[j].y);
            }
    }

    float* outp = which ? g_relw : g_relh;
#pragma unroll
    for (int i = 0; i < 3; i++) {
        int row = ty * 3 + i;
        int t = which ? (row * GH + pos) : (pos * GH + row);
#pragma unroll
        for (int j = 0; j < 3; j++) {
            float lo, hi;
            unpack2f(acc[i][j], lo, hi);
            outp[((size_t)head * HW + t) * GH + tx * 3 + j] = lo + hi;
        }
    }
}

// ---------------- K3b: split K and transposed V into bf16 hi/lo -------------
__global__ void __launch_bounds__(256) kv_prep_kernel() {
    __shared__ float vs[64 * 65];
    const int kt0 = blockIdx.x * 64;
    const int head = blockIdx.y;
    const int tid = threadIdx.x;

    for (int i = tid; i < 64 * 64; i += 256) {
        int r = i >> 6, c = i & 63;
        const float* src = &g_qkv[(size_t)(kt0 + r) * (3 * DIM) + head * HD + c];
        float kv = src[DIM];
        __nv_bfloat16 kh = __float2bfloat16(kv);
        size_t ko = ((size_t)head * HW + kt0 + r) * HD + c;
        g_kh[ko] = kh;
        g_kl[ko] = __float2bfloat16(kv - __bfloat162float(kh));
        vs[r * 65 + c] = src[2 * DIM];
    }
    __syncthreads();
    for (int i = tid; i < 64 * 64; i += 256) {
        int d = i >> 6, k = i & 63;
        float v = vs[k * 65 + d];
        __nv_bfloat16 vh = __float2bfloat16(v);
        size_t vo = ((size_t)head * HD + d) * HW + kt0 + k;
        g_vh[vo] = vh;
        g_vl[vo] = __float2bfloat16(v - __bfloat162float(vh));
    }
}

// ---------------- K4: pipelined split-KV mma.sync flash attention -----------
#define ROWB   144            // 72 bf16 = 144 bytes per padded row
#define ARR_SZ (64 * ROWB)    // 9216
#define SB_KLO ARR_SZ
#define SB_V   (2 * ARR_SZ)
#define SB_VLO (3 * ARR_SZ)
#define BUF_SZ (4 * ARR_SZ)   // 36864
#define SM_RH  (3 * BUF_SZ)                 // 110592
#define SM_RW  (SM_RH + 128 * GH * 4)       // +24576
#define SM_TOT (SM_RW + 128 * GH * 4)       // 159744 (156KB) -> 1 CTA/SM

__device__ __forceinline__ void copy_kv_async(uint32_t dstb, int head, int kt0) {
    const int tid = threadIdx.x;   // 256 threads
    const char* khb = (const char*)(g_kh + ((size_t)head * HW + kt0) * HD);
    const char* klb = (const char*)(g_kl + ((size_t)head * HW + kt0) * HD);
#pragma unroll
    for (int it = 0; it < 2; it++) {
        int i = tid + it * 256;
        int r = i >> 3, c = i & 7;
        uint32_t d = r * ROWB + c * 16;
        cp16(dstb + d, khb + i * 16);
        cp16(dstb + SB_KLO + d, klb + i * 16);
    }
    const char* vhb = (const char*)(g_vh + (size_t)head * HD * HW + kt0);
    const char* vlb = (const char*)(g_vl + (size_t)head * HD * HW + kt0);
#pragma unroll
    for (int it = 0; it < 2; it++) {
        int i = tid + it * 256;
        int dr = i >> 3, c = i & 7;
        uint32_t d = dr * ROWB + c * 16;
        size_t go = (size_t)dr * (HW * 2) + c * 16;
        cp16(dstb + SB_V + d, vhb + go);
        cp16(dstb + SB_VLO + d, vlb + go);
    }
    CP_COMMIT();
}

__device__ __forceinline__ void s_mma_tile(float S[8][4], uint32_t kb,
                                           const uint32_t qhi[4][4],
                                           const uint32_t qlo[4][4],
                                           uint32_t lmoff) {
#pragma unroll
    for (int j = 0; j < 8; j++) {
#pragma unroll
        for (int i = 0; i < 4; i++) S[j][i] = 0.f;
        uint32_t base = kb + (uint32_t)j * (8 * ROWB) + lmoff;
#pragma unroll
        for (int s = 0; s < 4; s++) {
            uint32_t bh0, bh1, bl0, bl1;
            ldsm2(bh0, bh1, base + s * 32);
            ldsm2(bl0, bl1, base + SB_KLO + s * 32);
            mma16816(S[j], qhi[s], bh0, bh1);
            mma16816(S[j], qlo[s], bh0, bh1);
            mma16816(S[j], qhi[s], bl0, bl1);
        }
    }
}

__global__ void __launch_bounds__(256) attn_mma_kernel() {
    extern __shared__ char smc[];
    const uint32_t smb = smem_to_u32(smc);
    const int tid = threadIdx.x, lane = tid & 31, warp = tid >> 5;   // 8 warps
    const int gid = lane >> 2, tig = lane & 3;
    const int head = blockIdx.y;
    const int qt0 = blockIdx.x * 128;
    const int zs = blockIdx.z;
    const int T0 = zs * NTT;

    copy_kv_async(smb, head, T0 * 64);
    copy_kv_async(smb + BUF_SZ, head, (T0 + 1) * 64);

    float* Rh = (float*)(smc + SM_RH);
    float* Rw = (float*)(smc + SM_RW);
    {
        const float4* sH = (const float4*)&g_relh[((size_t)head * HW + qt0) * GH];
        const float4* sW = (const float4*)&g_relw[((size_t)head * HW + qt0) * GH];
        float4* dH = (float4*)Rh;
        float4* dW = (float4*)Rw;
        for (int i = tid; i < 128 * GH / 4; i += 256) { dH[i] = sH[i]; dW[i] = sW[i]; }
    }

    uint32_t qhi[4][4], qlo[4][4];
    {
        const float* q0 = &g_qkv[(size_t)(qt0 + warp * 16 + gid) * (3 * DIM) + head * HD];
        const float* q1 = q0 + (size_t)8 * (3 * DIM);
#pragma unroll
        for (int s = 0; s < 4; s++) {
            int c = 16 * s + 2 * tig;
            float2 v;
            v = *(const float2*)&q0[c];
            split2(QK_SCALE * v.x, QK_SCALE * v.y, qhi[s][0], qlo[s][0]);
            v = *(const float2*)&q1[c];
            split2(QK_SCALE * v.x, QK_SCALE * v.y, qhi[s][1], qlo[s][1]);
            v = *(const float2*)&q0[c + 8];
            split2(QK_SCALE * v.x, QK_SCALE * v.y, qhi[s][2], qlo[s][2]);
            v = *(const float2*)&q1[c + 8];
            split2(QK_SCALE * v.x, QK_SCALE * v.y, qhi[s][3], qlo[s][3]);
        }
    }

    const uint32_t lmoff = (uint32_t)((lane & 7) * ROWB + (lane & 8) * 2);

    CP_WAIT1();            // buf0 complete (buf1 in flight)
    __syncthreads();

    float Scur[8][4], Snext[8][4];
    s_mma_tile(Scur, smb, qhi, qlo, lmoff);

    float Oacc[8][4];
#pragma unroll
    for (int j = 0; j < 8; j++)
#pragma unroll
        for (int i = 0; i < 4; i++) Oacc[j][i] = 0.f;
    float rs0 = 0.f, rs1 = 0.f;

    const float* rh0 = &Rh[(warp * 16 + gid) * GH];
    const float* rh1 = rh0 + 8 * GH;
    const float* rw0 = &Rw[(warp * 16 + gid) * GH];
    const float* rw1 = rw0 + 8 * GH;

    for (int tt = 0; tt < NTT; tt++) {
        const int kt0 = (T0 + tt) * 64;
        __syncthreads();   // all warps done reading buf((tt-1)%3) from PV(tt-1)
        if (tt + 2 < NTT)
            copy_kv_async(smb + (uint32_t)((tt + 2) % 3) * BUF_SZ, head, (T0 + tt + 2) * 64);
        if (tt + 1 < NTT) {
            if (tt + 2 < NTT) { CP_WAIT1(); } else { CP_WAIT0(); }
            __syncthreads();   // buf(tt+1) visible to all warps
            s_mma_tile(Snext, smb + (uint32_t)((tt + 1) % 3) * BUF_SZ, qhi, qlo, lmoff);
        }

        // softmax on Scur (tile tt) — results are a full iteration old
#pragma unroll
        for (int j = 0; j < 8; j++) {
            int k0 = kt0 + 8 * j + 2 * tig;
            int hk0 = k0 / GH, wk0 = k0 - hk0 * GH;
            int k1 = k0 + 1;
            int hk1 = k1 / GH, wk1 = k1 - hk1 * GH;
            float e0 = __expf(Scur[j][0] + rh0[hk0] + rw0[wk0]);
            float e1 = __expf(Scur[j][1] + rh0[hk1] + rw0[wk1]);
            float e2 = __expf(Scur[j][2] + rh1[hk0] + rw1[wk0]);
            float e3 = __expf(Scur[j][3] + rh1[hk1] + rw1[wk1]);
            rs0 += e0 + e1;
            rs1 += e2 + e3;
            Scur[j][0] = e0; Scur[j][1] = e1; Scur[j][2] = e2; Scur[j][3] = e3;
        }

        uint32_t phi[4][4], plo[4][4];
#pragma unroll
        for (int s = 0; s < 4; s++) {
            split2(Scur[2 * s][0],     Scur[2 * s][1],     phi[s][0], plo[s][0]);
            split2(Scur[2 * s][2],     Scur[2 * s][3],     phi[s][1], plo[s][1]);
            split2(Scur[2 * s + 1][0], Scur[2 * s + 1][1], phi[s][2], plo[s][2]);
            split2(Scur[2 * s + 1][2], Scur[2 * s + 1][3], phi[s][3], plo[s][3]);
        }

        const uint32_t vb = smb + (uint32_t)(tt % 3) * BUF_SZ + SB_V;
#pragma unroll
        for (int j = 0; j < 8; j++) {
            uint32_t base = vb + (uint32_t)j * (8 * ROWB) + lmoff;
#pragma unroll
            for (int s = 0; s < 4; s++) {
                uint32_t vh0, vh1, vl0, vl1;
                ldsm2(vh0, vh1, base + s * 32);
                ldsm2(vl0, vl1, base + ARR_SZ + s * 32);
                mma16816(Oacc[j], phi[s], vh0, vh1);
                mma16816(Oacc[j], plo[s], vh0, vh1);
                mma16816(Oacc[j], phi[s], vl0, vl1);
            }
        }

        if (tt + 1 < NTT) {
#pragma unroll
            for (int j = 0; j < 8; j++)
#pragma unroll
                for (int i = 0; i < 4; i++) Scur[j][i] = Snext[j][i];
        }
    }

    // partial row-sums + unnormalized partial O to gmem
    rs0 += __shfl_xor_sync(0xffffffffu, rs0, 1);
    rs0 += __shfl_xor_sync(0xffffffffu, rs0, 2);
    rs1 += __shfl_xor_sync(0xffffffffu, rs1, 1);
    rs1 += __shfl_xor_sync(0xffffffffu, rs1, 2);

    const int row0 = qt0 + warp * 16 + gid;
    if (tig == 0) {
        g_lpart[(size_t)zs * NH * HW + (size_t)head * HW + row0] = rs0;
        g_lpart[(size_t)zs * NH * HW + (size_t)head * HW + row0 + 8] = rs1;
    }
    float* op = g_opart + (size_t)zs * HW * DIM;
    const size_t r0 = (size_t)row0 * DIM + head * HD;
    const size_t r1 = r0 + (size_t)8 * DIM;
#pragma unroll
    for (int j = 0; j < 8; j++) {
        int c = 8 * j + 2 * tig;
        *(float2*)&op[r0 + c] = make_float2(Oacc[j][0], Oacc[j][1]);
        *(float2*)&op[r1 + c] = make_float2(Oacc[j][2], Oacc[j][3]);
    }
}

// ---------------- K4b: combine split-KV partials -> bf16 hi/lo --------------
__global__ void __launch_bounds__(256) combine_kernel() {
    int idx = blockIdx.x * 256 + threadIdx.x;   // 2 cols per thread
    if (idx >= HW * DIM / 2) return;
    int row = idx / (DIM / 2);
    int cc = (idx - row * (DIM / 2)) * 2;
    int head = cc >> 6;
    float l = g_lpart[(size_t)head * HW + row]
            + g_lpart[(size_t)NH * HW + (size_t)head * HW + row];
    float inv = 1.f / l;
    size_t o = (size_t)row * DIM + cc;
    float2 o0 = *(const float2*)&g_opart[o];
    float2 o1 = *(const float2*)&g_opart[(size_t)HW * DIM + o];
    uint32_t h, lo;
    split2((o0.x + o1.x) * inv, (o0.y + o1.y) * inv, h, lo);
    *(uint32_t*)&g_oph[o] = h;
    *(uint32_t*)&g_opl[o] = lo;
}

// ---------------- launch -----------------------------------------------------
extern "C" void kernel_launch(void* const* d_in, const int* in_sizes, int n_in,
                              void* d_out, int out_size) {
    const float* x     = (const float*)d_in[0];
    const float* Wqkv  = (const float*)d_in[1];
    const float* bqkv  = (const float*)d_in[2];
    const float* FacTu = (const float*)d_in[3];
    const float* FacTv = (const float*)d_in[4];
    const float* qF    = (const float*)d_in[5];
    const float* vF    = (const float*)d_in[6];
    const float* rph   = (const float*)d_in[7];
    const float* rpw   = (const float*)d_in[8];
    const float* Wproj = (const float*)d_in[9];
    const float* bproj = (const float*)d_in[10];
    float* out = (float*)d_out;

    void *pQkv, *pXh, *pXl, *pOph, *pOpl, *pWqT_h, *pWqT_l, *pWpT_h, *pWpT_l;
    cudaGetSymbolAddress(&pQkv, g_qkv);
    cudaGetSymbolAddress(&pXh, g_xh);
    cudaGetSymbolAddress(&pXl, g_xl);
    cudaGetSymbolAddress(&pOph, g_oph);
    cudaGetSymbolAddress(&pOpl, g_opl);
    cudaGetSymbolAddress(&pWqT_h, g_wqkvT_h);
    cudaGetSymbolAddress(&pWqT_l, g_wqkvT_l);
    cudaGetSymbolAddress(&pWpT_h, g_wprojT_h);
    cudaGetSymbolAddress(&pWpT_l, g_wprojT_l);

    cudaFuncSetAttribute(attn_mma_kernel,
                         cudaFuncAttributeMaxDynamicSharedMemorySize, (int)SM_TOT);
    cudaFuncSetAttribute(hgemm_bf16,
                         cudaFuncAttributeMaxDynamicSharedMemorySize, (int)HG_SMEM);

    fact_small_kernel<<<(DIM * RANK * 2 + 255) / 256, 256>>>(FacTu, qF, vF);
    xsplit_kernel<<<(HW * DIM / 4 + 255) / 256, 256>>>(x);

    {   // Wqkv (+delta) -> transposed split
        dim3 grid((3 * DIM) / 32, DIM / 32);
        wsplit_kernel<<<grid, 256>>>(Wqkv, FacTv,
                                     (__nv_bfloat16*)pWqT_h, (__nv_bfloat16*)pWqT_l,
                                     3 * DIM, 1);
    }
    {   // Wproj -> transposed split
        dim3 grid(DIM / 32, DIM / 32);
        wsplit_kernel<<<grid, 256>>>(Wproj, FacTv,
                                     (__nv_bfloat16*)pWpT_h, (__nv_bfloat16*)pWpT_l,
                                     DIM, 0);
    }
    {   // qkv = x @ Weff + bqkv (HMMA, 96-row tiles)
        dim3 grid((3 * DIM) / 128, HW / 96);
        hgemm_bf16<<<grid, 256, HG_SMEM>>>((const __nv_bfloat16*)pXh,
                                           (const __nv_bfloat16*)pXl,
                                           (const __nv_bfloat16*)pWqT_h,
                                           (const __nv_bfloat16*)pWqT_l,
                                           bqkv, (float*)pQkv, HW, 3 * DIM, DIM);
    }
    {   // rel-pos tables
        dim3 grid(GH, NH, 2);
        rel_tab2_kernel<<<grid, 256>>>(rph, rpw);
    }
    {   // bf16 split K / transposed V
        dim3 grid(HW / 64, NH);
        kv_prep_kernel<<<grid, 256>>>();
    }
    {   // pipelined split-KV tensor-core attention
        dim3 grid(HW / 128, NH, KSPLIT);
        attn_mma_kernel<<<grid, 256, SM_TOT>>>();
    }
    {   // combine partials
        combine_kernel<<<(HW * DIM / 2 + 255) / 256, 256>>>();
    }
    {   // out = opre @ Wproj + bproj (HMMA, 96-row tiles)
        dim3 grid(DIM / 128, HW / 96);
        hgemm_bf16<<<grid, 256, HG_SMEM>>>((const __nv_bfloat16*)pOph,
                                           (const __nv_bfloat16*)pOpl,
                                           (const __nv_bfloat16*)pWpT_h,
                                           (const __nv_bfloat16*)pWpT_l,
                                           bproj, out, HW, DIM, DIM);
    }
}

// round 11
// speedup vs baseline: 1.3808x; 1.0697x over previous
#include <cuda_runtime.h>
#include <cuda_bf16.h>
#include <cstdint>

#define DIM   768
#define NH    12
#define HD    64
#define GH    48           // grid H = W
#define HW    2304         // 48*48
#define RANK  32
#define QK_SCALE 0.125f    // 64^-0.5
#define LOG2E 1.4426950408889634f
#define QSCL (QK_SCALE * LOG2E)
#define FACT_S 1.0f
#define NT    36           // kv tiles of 64
#define KSPLIT 2
#define NTT   (NT / KSPLIT)  // 18 tiles per split

typedef unsigned long long u64;

// ---------------- packed helpers --------------------------------------------
__device__ __forceinline__ u64 pack2f(float a, float b) {
    u64 r;
    asm("mov.b64 %0, {%1, %2};" : "=l"(r)
        : "r"(__float_as_uint(a)), "r"(__float_as_uint(b)));
    return r;
}
__device__ __forceinline__ void unpack2f(u64 v, float& a, float& b) {
    unsigned x, y;
    asm("mov.b64 {%0, %1}, %2;" : "=r"(x), "=r"(y) : "l"(v));
    a = __uint_as_float(x);
    b = __uint_as_float(y);
}
__device__ __forceinline__ void ffma2(u64& d, u64 a, u64 b) {
    asm("fma.rn.f32x2 %0, %1, %2, %0;" : "+l"(d) : "l"(a), "l"(b));
}
__device__ __forceinline__ uint32_t cvt_bf16x2(float a, float b) {
    uint32_t r;
    asm("cvt.rn.bf16x2.f32 %0, %1, %2;" : "=r"(r) : "f"(b), "f"(a));
    return r;
}
__device__ __forceinline__ void split2(float a, float b, uint32_t& hi, uint32_t& lo) {
    uint32_t h = cvt_bf16x2(a, b);
    float ra = __uint_as_float(h << 16);
    float rb = __uint_as_float(h & 0xffff0000u);
    hi = h;
    lo = cvt_bf16x2(a - ra, b - rb);
}
__device__ __forceinline__ float ex2f(float x) {
    float y;
    asm("ex2.approx.f32 %0, %1;" : "=f"(y) : "f"(x));
    return y;
}

// ---------------- mma / ldmatrix / cp.async helpers --------------------------
__device__ __forceinline__ void mma16816(float c[4], const uint32_t a[4],
                                         uint32_t b0, uint32_t b1) {
    asm volatile(
        "mma.sync.aligned.m16n8k16.row.col.f32.bf16.bf16.f32 "
        "{%0,%1,%2,%3}, {%4,%5,%6,%7}, {%8,%9}, {%0,%1,%2,%3};"
        : "+f"(c[0]), "+f"(c[1]), "+f"(c[2]), "+f"(c[3])
        : "r"(a[0]), "r"(a[1]), "r"(a[2]), "r"(a[3]), "r"(b0), "r"(b1));
}
__device__ __forceinline__ void ldsm4(uint32_t r[4], uint32_t addr) {
    asm volatile("ldmatrix.sync.aligned.m8n8.x4.shared.b16 {%0,%1,%2,%3}, [%4];"
                 : "=r"(r[0]), "=r"(r[1]), "=r"(r[2]), "=r"(r[3]) : "r"(addr));
}
__device__ __forceinline__ uint32_t smem_to_u32(const void* smem_ptr) {
    uint32_t addr;
    asm("{ .reg .u64 tmp; cvta.to.shared.u64 tmp, %1; cvt.u32.u64 %0, tmp; }"
        : "=r"(addr) : "l"(smem_ptr));
    return addr;
}
__device__ __forceinline__ void cp16(uint32_t dst, const void* src) {
    asm volatile("cp.async.cg.shared.global [%0], [%1], 16;"
                 :: "r"(dst), "l"(src));
}
#define CP_COMMIT() asm volatile("cp.async.commit_group;" ::: "memory")
#define CP_WAIT0()  asm volatile("cp.async.wait_group 0;" ::: "memory")
#define CP_WAIT1()  asm volatile("cp.async.wait_group 1;" ::: "memory")

// ---------------- device scratch (no allocations allowed) ------------------
__device__ float g_A1[DIM * RANK];
__device__ float g_A2[DIM * RANK];
__device__ float g_qkv[HW * 3 * DIM];
__device__ float g_relh[NH * HW * GH];   // pre-scaled by LOG2E
__device__ float g_relw[NH * HW * GH];   // pre-scaled by LOG2E
// split-KV partials
__device__ __align__(16) float g_opart[KSPLIT * HW * DIM];
__device__ float g_lpart[KSPLIT * NH * HW];
// pre-split inputs / intermediates
__device__ __align__(16) __nv_bfloat16 g_xh[HW * DIM];
__device__ __align__(16) __nv_bfloat16 g_xl[HW * DIM];
__device__ __align__(16) __nv_bfloat16 g_oph[HW * DIM];
__device__ __align__(16) __nv_bfloat16 g_opl[HW * DIM];
// pre-split transposed weights: [N][K] bf16 hi/lo
__device__ __align__(16) __nv_bfloat16 g_wqkvT_h[3 * DIM * DIM];
__device__ __align__(16) __nv_bfloat16 g_wqkvT_l[3 * DIM * DIM];
__device__ __align__(16) __nv_bfloat16 g_wprojT_h[DIM * DIM];
__device__ __align__(16) __nv_bfloat16 g_wprojT_l[DIM * DIM];
// bf16 split K [head][key][dim] and transposed V [head][dim][key]
__device__ __align__(16) __nv_bfloat16 g_kh[NH * HW * HD];
__device__ __align__(16) __nv_bfloat16 g_kl[NH * HW * HD];
__device__ __align__(16) __nv_bfloat16 g_vh[NH * HD * HW];
__device__ __align__(16) __nv_bfloat16 g_vl[NH * HD * HW];

// ---------------- K0: A1 = FacTu @ q_FacTs, A2 = FacTu @ v_FacTs -----------
__global__ void fact_small_kernel(const float* __restrict__ FacTu,
                                  const float* __restrict__ qF,
                                  const float* __restrict__ vF) {
    int idx = blockIdx.x * 256 + threadIdx.x;
    if (idx >= DIM * RANK * 2) return;
    int which = idx / (DIM * RANK);
    int rem = idx - which * (DIM * RANK);
    int i = rem / RANK, r = rem - (rem / RANK) * RANK;
    const float* F = which ? vF : qF;
    float s = 0.f;
#pragma unroll
    for (int k = 0; k < RANK; k++) s += FacTu[i * RANK + k] * F[k * RANK + r];
    (which ? g_A2 : g_A1)[i * RANK + r] = s;
}

// ---------------- K0b: split x into bf16 hi/lo ------------------------------
__global__ void __launch_bounds__(256) xsplit_kernel(const float* __restrict__ x) {
    int idx = blockIdx.x * 256 + threadIdx.x;
    if (idx >= HW * DIM / 4) return;
    float4 v = *(const float4*)&x[idx * 4];
    uint32_t h0, l0, h1, l1;
    split2(v.x, v.y, h0, l0);
    split2(v.z, v.w, h1, l1);
    *(uint2*)&g_xh[idx * 4] = make_uint2(h0, h1);
    *(uint2*)&g_xl[idx * 4] = make_uint2(l0, l1);
}

// ---------------- K1: transpose + low-rank fold + bf16 split ---------------
__global__ void __launch_bounds__(256)
wsplit_kernel(const float* __restrict__ W, const float* __restrict__ FacTv,
              __nv_bfloat16* __restrict__ WTh, __nv_bfloat16* __restrict__ WTl,
              int NJ, int mode) {
    __shared__ float tile[32 * 33];
    const int tid = threadIdx.x;
    const int j0 = blockIdx.x * 32;
    const int i0 = blockIdx.y * 32;

    {
        const int j = tid & 31;
        const int ib = tid >> 5;
        const float* Aarr = nullptr;
        int jj = j0 + j;
        if (mode) {
            if (jj < DIM) Aarr = g_A1;
            else if (jj >= 2 * DIM) { Aarr = g_A2; jj -= 2 * DIM; }
        }
#pragma unroll
        for (int it = 0; it < 4; it++) {
            int il = ib + it * 8;
            int i = i0 + il;
            float w = W[(size_t)i * NJ + j0 + j];
            if (Aarr) {
                float s = 0.f;
#pragma unroll
                for (int r = 0; r < RANK; r++)
                    s += Aarr[i * RANK + r] * FacTv[r * DIM + jj];
                w += FACT_S * s;
            }
            tile[il * 33 + j] = w;
        }
    }
    __syncthreads();
    {
        const int i = tid & 31;
        const int jb = tid >> 5;
#pragma unroll
        for (int it = 0; it < 4; it++) {
            int jl = jb + it * 8;
            float v = tile[i * 33 + jl];
            __nv_bfloat16 h = __float2bfloat16(v);
            size_t o = (size_t)(j0 + jl) * DIM + i0 + i;
            WTh[o] = h;
            WTl[o] = __float2bfloat16(v - __bfloat162float(h));
        }
    }
}

// ---------------- K2: HMMA GEMM (96x128 tile, all-bf16, cp.async) -----------
#define GS 40                 // smem row stride in bf16 (80B)
#define A_CH 384              // cp16 chunks per A array (96 rows * 4)
#define B_CH 512              // cp16 chunks per B array (128 rows * 4)
#define AARR 7680             // bytes per A array (96*80)
#define BARR 10240            // bytes per B array (128*80)
#define STG  35840            // bytes per stage (2*AARR + 2*BARR)
__global__ void __launch_bounds__(256)
hgemm_bf16(const __nv_bfloat16* __restrict__ Ah_,
           const __nv_bfloat16* __restrict__ Al_,
           const __nv_bfloat16* __restrict__ Bh_,
           const __nv_bfloat16* __restrict__ Bl_,
           const float* __restrict__ bias, float* __restrict__ C,
           int M, int N, int K) {
    extern __shared__ __align__(16) char gsm[];
    const uint32_t smb = smem_to_u32(gsm);
    const int tid = threadIdx.x, lane = tid & 31, warp = tid >> 5;
    const int wm = (warp >> 2) * 48, wn = (warp & 3) * 32;
    const int bm = blockIdx.y * 96, bn = blockIdx.x * 128;

#define GB_ISSUE(k0) do { \
        _Pragma("unroll") \
        for (int t = 0; t < 7; t++) { \
            int i = tid + t * 256; \
            const __nv_bfloat16* gptr; uint32_t soff; int j, grow; \
            if (i < A_CH) { gptr = Ah_; soff = 0; j = i; grow = bm; } \
            else if (i < 2 * A_CH) { gptr = Al_; soff = AARR; j = i - A_CH; grow = bm; } \
            else if (i < 2 * A_CH + B_CH) { gptr = Bh_; soff = 2 * AARR; j = i - 2 * A_CH; grow = bn; } \
            else { gptr = Bl_; soff = 2 * AARR + BARR; j = i - 2 * A_CH - B_CH; grow = bn; } \
            int row = j >> 2, c = j & 3; \
            grow += row; \
            const char* src = (const char*)&gptr[(size_t)grow * K + (k0)] + c * 16; \
            cp16(sb + soff + row * 80 + c * 16, src); \
        } \
        CP_COMMIT(); \
    } while (0)

    float acc[3][4][4];
#pragma unroll
    for (int a = 0; a < 3; a++)
#pragma unroll
        for (int b = 0; b < 4; b++)
#pragma unroll
            for (int c = 0; c < 4; c++) acc[a][b][c] = 0.f;

    {
        uint32_t sb = smb;
        GB_ISSUE(0);
    }

    const uint32_t aoff = (uint32_t)((lane & 15) * GS + ((lane >> 4) << 3)) * 2;
    const uint32_t boff = (uint32_t)(((lane & 7) + ((lane & 16) >> 1)) * GS + (lane & 8)) * 2;

    const int NKT = K / 32;
    for (int kt = 0; kt < NKT; kt++) {
        CP_WAIT0();
        __syncthreads();
        if (kt + 1 < NKT) {
            uint32_t sb = smb + (uint32_t)((kt + 1) & 1) * STG;
            GB_ISSUE((kt + 1) * 32);
        }
        const uint32_t cb = smb + (uint32_t)(kt & 1) * STG;
        const uint32_t sAh = cb, sAl = cb + AARR;
        const uint32_t sBh = cb + 2 * AARR, sBl = cb + 2 * AARR + BARR;

#pragma unroll
        for (int ks = 0; ks < 2; ks++) {
            uint32_t ah[3][4], al[3][4];
#pragma unroll
            for (int mt = 0; mt < 3; mt++) {
                uint32_t off = (uint32_t)(wm + mt * 16) * (GS * 2) + (uint32_t)ks * 32 + aoff;
                ldsm4(ah[mt], sAh + off);
                ldsm4(al[mt], sAl + off);
            }
            uint32_t bh[2][4], bl[2][4];
#pragma unroll
            for (int nt = 0; nt < 2; nt++) {
                uint32_t off = (uint32_t)(wn + nt * 16) * (GS * 2) + (uint32_t)ks * 32 + boff;
                ldsm4(bh[nt], sBh + off);
                ldsm4(bl[nt], sBl + off);
            }
#pragma unroll
            for (int mt = 0; mt < 3; mt++)
#pragma unroll
                for (int nt = 0; nt < 4; nt++) {
                    uint32_t b0h = bh[nt >> 1][(nt & 1) * 2];
                    uint32_t b1h = bh[nt >> 1][(nt & 1) * 2 + 1];
                    uint32_t b0l = bl[nt >> 1][(nt & 1) * 2];
                    uint32_t b1l = bl[nt >> 1][(nt & 1) * 2 + 1];
                    mma16816(acc[mt][nt], ah[mt], b0h, b1h);
                    mma16816(acc[mt][nt], al[mt], b0h, b1h);
                    mma16816(acc[mt][nt], ah[mt], b0l, b1l);
                }
        }
        __syncthreads();
    }

    const int gid = lane >> 2, tig = lane & 3;
#pragma unroll
    for (int mt = 0; mt < 3; mt++) {
        int m0 = bm + wm + mt * 16 + gid;
#pragma unroll
        for (int nt = 0; nt < 4; nt++) {
            int n0 = bn + wn + nt * 8 + 2 * tig;
            float bx = bias ? bias[n0] : 0.f;
            float by = bias ? bias[n0 + 1] : 0.f;
            *(float2*)&C[(size_t)m0 * N + n0] =
                make_float2(acc[mt][nt][0] + bx, acc[mt][nt][1] + by);
            *(float2*)&C[(size_t)(m0 + 8) * N + n0] =
                make_float2(acc[mt][nt][2] + bx, acc[mt][nt][3] + by);
        }
    }
}
#define HG_SMEM (2 * STG)

// ---------------- K3: rel bias tables (pre-scaled by LOG2E) -----------------
__global__ void __launch_bounds__(256) rel_tab2_kernel(const float* __restrict__ rph,
                                                       const float* __restrict__ rpw) {
    __shared__ float Qs[GH * 68];
    __shared__ float Rs[GH * 68];
    const int pos = blockIdx.x;
    const int head = blockIdx.y;
    const int which = blockIdx.z;
    const int tid = threadIdx.x;

    for (int i = tid; i < GH * HD; i += 256) {
        int r = i >> 6, c = i & 63;
        int t = which ? (r * GH + pos) : (pos * GH + r);
        Qs[r * 68 + c] = g_qkv[(size_t)t * (3 * DIM) + head * HD + c];
    }
    const float* rp = which ? rpw : rph;
    for (int i = tid; i < GH * HD; i += 256) {
        int k = i >> 6, c = i & 63;
        Rs[k * 68 + c] = rp[(pos - k + GH - 1) * HD + c];
    }
    __syncthreads();

    const int tx = tid & 15, ty = tid >> 4;
    u64 acc[3][3];
#pragma unroll
    for (int i = 0; i < 3; i++)
#pragma unroll
        for (int j = 0; j < 3; j++) acc[i][j] = 0ull;

    for (int c = 0; c < HD; c += 4) {
        ulonglong2 q[3], r[3];
#pragma unroll
        for (int i = 0; i < 3; i++) q[i] = *(const ulonglong2*)&Qs[(ty * 3 + i) * 68 + c];
#pragma unroll
        for (int j = 0; j < 3; j++) r[j] = *(const ulonglong2*)&Rs[(tx * 3 + j) * 68 + c];
#pragma unroll
        for (int i = 0; i < 3; i++)
#pragma unroll
            for (int j = 0; j < 3; j++) {
                ffma2(acc[i][j], q[i].x, r[j].x);
                ffma2(acc[i][j], q[i].y, r[j].y);
            }
    }

    float* outp = which ? g_relw : g_relh;
#pragma unroll
    for (int i = 0; i < 3; i++) {
        int row = ty * 3 + i;
        int t = which ? (row * GH + pos) : (pos * GH + row);
#pragma unroll
        for (int j = 0; j < 3; j++) {
            float lo, hi;
            unpack2f(acc[i][j], lo, hi);
            outp[((size_t)head * HW + t) * GH + tx * 3 + j] = (lo + hi) * LOG2E;
        }
    }
}

// ---------------- K3b: split K and transposed V into bf16 hi/lo -------------
__global__ void __launch_bounds__(256) kv_prep_kernel() {
    __shared__ float vs[64 * 65];
    const int kt0 = blockIdx.x * 64;
    const int head = blockIdx.y;
    const int tid = threadIdx.x;

    for (int i = tid; i < 64 * 64; i += 256) {
        int r = i >> 6, c = i & 63;
        const float* src = &g_qkv[(size_t)(kt0 + r) * (3 * DIM) + head * HD + c];
        float kv = src[DIM];
        __nv_bfloat16 kh = __float2bfloat16(kv);
        size_t ko = ((size_t)head * HW + kt0 + r) * HD + c;
        g_kh[ko] = kh;
        g_kl[ko] = __float2bfloat16(kv - __bfloat162float(kh));
        vs[r * 65 + c] = src[2 * DIM];
    }
    __syncthreads();
    for (int i = tid; i < 64 * 64; i += 256) {
        int d = i >> 6, k = i & 63;
        float v = vs[k * 65 + d];
        __nv_bfloat16 vh = __float2bfloat16(v);
        size_t vo = ((size_t)head * HD + d) * HW + kt0 + k;
        g_vh[vo] = vh;
        g_vl[vo] = __float2bfloat16(v - __bfloat162float(vh));
    }
}

// ---------------- K4: pipelined split-KV mma.sync flash attention -----------
// Quad-buffered KV, single __syncthreads per tile, ldsm4, hk-select bias.
#define ROWB   144            // 72 bf16 = 144 bytes per padded row
#define ARR_SZ (64 * ROWB)    // 9216
#define SB_KLO ARR_SZ
#define SB_V   (2 * ARR_SZ)
#define SB_VLO (3 * ARR_SZ)
#define BUF_SZ (4 * ARR_SZ)   // 36864
#define SM_RH  (4 * BUF_SZ)                 // 147456
#define SM_RW  (SM_RH + 128 * GH * 4)       // +24576
#define SM_TOT (SM_RW + 128 * GH * 4)       // 196608 (192KB) -> 1 CTA/SM

__device__ __forceinline__ void copy_kv_async(uint32_t dstb, int head, int kt0) {
    const int tid = threadIdx.x;   // 256 threads
    const char* khb = (const char*)(g_kh + ((size_t)head * HW + kt0) * HD);
    const char* klb = (const char*)(g_kl + ((size_t)head * HW + kt0) * HD);
#pragma unroll
    for (int it = 0; it < 2; it++) {
        int i = tid + it * 256;
        int r = i >> 3, c = i & 7;
        uint32_t d = r * ROWB + c * 16;
        cp16(dstb + d, khb + i * 16);
        cp16(dstb + SB_KLO + d, klb + i * 16);
    }
    const char* vhb = (const char*)(g_vh + (size_t)head * HD * HW + kt0);
    const char* vlb = (const char*)(g_vl + (size_t)head * HD * HW + kt0);
#pragma unroll
    for (int it = 0; it < 2; it++) {
        int i = tid + it * 256;
        int dr = i >> 3, c = i & 7;
        uint32_t d = dr * ROWB + c * 16;
        size_t go = (size_t)dr * (HW * 2) + c * 16;
        cp16(dstb + SB_V + d, vhb + go);
        cp16(dstb + SB_VLO + d, vlb + go);
    }
    CP_COMMIT();
}

__device__ __forceinline__ void s_mma_tile(float S[8][4], uint32_t kb,
                                           const uint32_t qhi[4][4],
                                           const uint32_t qlo[4][4],
                                           uint32_t lm4off) {
#pragma unroll
    for (int j = 0; j < 8; j++) {
#pragma unroll
        for (int i = 0; i < 4; i++) S[j][i] = 0.f;
        uint32_t base = kb + (uint32_t)j * (8 * ROWB) + lm4off;
#pragma unroll
        for (int s = 0; s < 4; s += 2) {
            uint32_t bh[4], bl[4];
            ldsm4(bh, base + s * 32);
            ldsm4(bl, base + SB_KLO + s * 32);
            mma16816(S[j], qhi[s], bh[0], bh[1]);
            mma16816(S[j], qlo[s], bh[0], bh[1]);
            mma16816(S[j], qhi[s], bl[0], bl[1]);
            mma16816(S[j], qhi[s + 1], bh[2], bh[3]);
            mma16816(S[j], qlo[s + 1], bh[2], bh[3]);
            mma16816(S[j], qhi[s + 1], bl[2], bl[3]);
        }
    }
}

__global__ void __launch_bounds__(256) attn_mma_kernel() {
    extern __shared__ char smc[];
    const uint32_t smb = smem_to_u32(smc);
    const int tid = threadIdx.x, lane = tid & 31, warp = tid >> 5;   // 8 warps
    const int gid = lane >> 2, tig = lane & 3;
    const int head = blockIdx.y;
    const int qt0 = blockIdx.x * 128;
    const int zs = blockIdx.z;
    const int T0 = zs * NTT;

    copy_kv_async(smb, head, T0 * 64);
    copy_kv_async(smb + BUF_SZ, head, (T0 + 1) * 64);
    copy_kv_async(smb + 2 * BUF_SZ, head, (T0 + 2) * 64);

    float* Rh = (float*)(smc + SM_RH);
    float* Rw = (float*)(smc + SM_RW);
    {
        const float4* sH = (const float4*)&g_relh[((size_t)head * HW + qt0) * GH];
        const float4* sW = (const float4*)&g_relw[((size_t)head * HW + qt0) * GH];
        float4* dH = (float4*)Rh;
        float4* dW = (float4*)Rw;
        for (int i = tid; i < 128 * GH / 4; i += 256) { dH[i] = sH[i]; dW[i] = sW[i]; }
    }

    uint32_t qhi[4][4], qlo[4][4];
    {
        const float* q0 = &g_qkv[(size_t)(qt0 + warp * 16 + gid) * (3 * DIM) + head * HD];
        const float* q1 = q0 + (size_t)8 * (3 * DIM);
#pragma unroll
        for (int s = 0; s < 4; s++) {
            int c = 16 * s + 2 * tig;
            float2 v;
            v = *(const float2*)&q0[c];
            split2(QSCL * v.x, QSCL * v.y, qhi[s][0], qlo[s][0]);
            v = *(const float2*)&q1[c];
            split2(QSCL * v.x, QSCL * v.y, qhi[s][1], qlo[s][1]);
            v = *(const float2*)&q0[c + 8];
            split2(QSCL * v.x, QSCL * v.y, qhi[s][2], qlo[s][2]);
            v = *(const float2*)&q1[c + 8];
            split2(QSCL * v.x, QSCL * v.y, qhi[s][3], qlo[s][3]);
        }
    }

    const uint32_t lm4off = (uint32_t)((lane & 7) * ROWB + (lane >> 3) * 16);

    CP_WAIT1();            // bufs 0,1 locally complete (buf2 in flight)
    __syncthreads();       // bufs 0,1 + Rh/Rw visible to all warps

    float Scur[8][4], Snext[8][4];
    s_mma_tile(Scur, smb, qhi, qlo, lm4off);

    float Oacc[8][4];
#pragma unroll
    for (int j = 0; j < 8; j++)
#pragma unroll
        for (int i = 0; i < 4; i++) Oacc[j][i] = 0.f;
    float rs0 = 0.f, rs1 = 0.f;

    const float* rh0 = &Rh[(warp * 16 + gid) * GH];
    const float* rh1 = rh0 + 8 * GH;
    const float* rw0 = &Rw[(warp * 16 + gid) * GH];
    const float* rw1 = rw0 + 8 * GH;

    for (int tt = 0; tt < NTT; tt++) {
        const int kt0 = (T0 + tt) * 64;
        __syncthreads();   // buf(tt+1) visible; buf((tt-1)&3) free for reuse
        if (tt + 3 < NTT)
            copy_kv_async(smb + (uint32_t)((tt + 3) & 3) * BUF_SZ, head, (T0 + tt + 3) * 64);
        if (tt + 1 < NTT)
            s_mma_tile(Snext, smb + (uint32_t)((tt + 1) & 3) * BUF_SZ, qhi, qlo, lm4off);

        // softmax on Scur: hk takes exactly 2 values per tile (kt0 mod 48 in {0,16,32})
        {
            const int hkA = kt0 / GH;
            const int kbd = (hkA + 1) * GH;       // first key with hk = hkA+1
            const int sub0 = hkA * GH, sub1 = sub0 + GH;
            const float rhA0 = rh0[hkA], rhB0 = rh0[hkA + 1];
            const float rhA1 = rh1[hkA], rhB1 = rh1[hkA + 1];
#pragma unroll
            for (int j = 0; j < 8; j++) {
                int k0 = kt0 + 8 * j + 2 * tig;
                int k1 = k0 + 1;
                bool c0 = k0 < kbd, c1 = k1 < kbd;
                int wk0 = k0 - (c0 ? sub0 : sub1);
                int wk1 = k1 - (c1 ? sub0 : sub1);
                float b00 = (c0 ? rhA0 : rhB0) + rw0[wk0];
                float b01 = (c1 ? rhA0 : rhB0) + rw0[wk1];
                float b10 = (c0 ? rhA1 : rhB1) + rw1[wk0];
                float b11 = (c1 ? rhA1 : rhB1) + rw1[wk1];
                float e0 = ex2f(Scur[j][0] + b00);
                float e1 = ex2f(Scur[j][1] + b01);
                float e2 = ex2f(Scur[j][2] + b10);
                float e3 = ex2f(Scur[j][3] + b11);
                rs0 += e0 + e1;
                rs1 += e2 + e3;
                Scur[j][0] = e0; Scur[j][1] = e1; Scur[j][2] = e2; Scur[j][3] = e3;
            }
        }

        uint32_t phi[4][4], plo[4][4];
#pragma unroll
        for (int s = 0; s < 4; s++) {
            split2(Scur[2 * s][0],     Scur[2 * s][1],     phi[s][0], plo[s][0]);
            split2(Scur[2 * s][2],     Scur[2 * s][3],     phi[s][1], plo[s][1]);
            split2(Scur[2 * s + 1][0], Scur[2 * s + 1][1], phi[s][2], plo[s][2]);
            split2(Scur[2 * s + 1][2], Scur[2 * s + 1][3], phi[s][3], plo[s][3]);
        }

        const uint32_t vb = smb + (uint32_t)(tt & 3) * BUF_SZ + SB_V;
#pragma unroll
        for (int j = 0; j < 8; j++) {
            uint32_t base = vb + (uint32_t)j * (8 * ROWB) + lm4off;
#pragma unroll
            for (int s = 0; s < 4; s += 2) {
                uint32_t vh[4], vl[4];
                ldsm4(vh, base + s * 32);
                ldsm4(vl, base + ARR_SZ + s * 32);
                mma16816(Oacc[j], phi[s], vh[0], vh[1]);
                mma16816(Oacc[j], plo[s], vh[0], vh[1]);
                mma16816(Oacc[j], phi[s], vl[0], vl[1]);
                mma16816(Oacc[j], phi[s + 1], vh[2], vh[3]);
                mma16816(Oacc[j], plo[s + 1], vh[2], vh[3]);
                mma16816(Oacc[j], phi[s + 1], vl[2], vl[3]);
            }
        }

        if (tt + 3 < NTT) { CP_WAIT1(); } else { CP_WAIT0(); }   // buf(tt+2) locally done

        if (tt + 1 < NTT) {
#pragma unroll
            for (int j = 0; j < 8; j++)
#pragma unroll
                for (int i = 0; i < 4; i++) Scur[j][i] = Snext[j][i];
        }
    }

    // partial row-sums + unnormalized partial O to gmem
    rs0 += __shfl_xor_sync(0xffffffffu, rs0, 1);
    rs0 += __shfl_xor_sync(0xffffffffu, rs0, 2);
    rs1 += __shfl_xor_sync(0xffffffffu, rs1, 1);
    rs1 += __shfl_xor_sync(0xffffffffu, rs1, 2);

    const int row0 = qt0 + warp * 16 + gid;
    if (tig == 0) {
        g_lpart[(size_t)zs * NH * HW + (size_t)head * HW + row0] = rs0;
        g_lpart[(size_t)zs * NH * HW + (size_t)head * HW + row0 + 8] = rs1;
    }
    float* op = g_opart + (size_t)zs * HW * DIM;
    const size_t r0 = (size_t)row0 * DIM + head * HD;
    const size_t r1 = r0 + (size_t)8 * DIM;
#pragma unroll
    for (int j = 0; j < 8; j++) {
        int c = 8 * j + 2 * tig;
        *(float2*)&op[r0 + c] = make_float2(Oacc[j][0], Oacc[j][1]);
        *(float2*)&op[r1 + c] = make_float2(Oacc[j][2], Oacc[j][3]);
    }
}

// ---------------- K4b: combine split-KV partials -> bf16 hi/lo --------------
__global__ void __launch_bounds__(256) combine_kernel() {
    int idx = blockIdx.x * 256 + threadIdx.x;   // 2 cols per thread
    if (idx >= HW * DIM / 2) return;
    int row = idx / (DIM / 2);
    int cc = (idx - row * (DIM / 2)) * 2;
    int head = cc >> 6;
    float l = g_lpart[(size_t)head * HW + row]
            + g_lpart[(size_t)NH * HW + (size_t)head * HW + row];
    float inv = 1.f / l;
    size_t o = (size_t)row * DIM + cc;
    float2 o0 = *(const float2*)&g_opart[o];
    float2 o1 = *(const float2*)&g_opart[(size_t)HW * DIM + o];
    uint32_t h, lo;
    split2((o0.x + o1.x) * inv, (o0.y + o1.y) * inv, h, lo);
    *(uint32_t*)&g_oph[o] = h;
    *(uint32_t*)&g_opl[o] = lo;
}

// ---------------- launch -----------------------------------------------------
extern "C" void kernel_launch(void* const* d_in, const int* in_sizes, int n_in,
                              void* d_out, int out_size) {
    const float* x     = (const float*)d_in[0];
    const float* Wqkv  = (const float*)d_in[1];
    const float* bqkv  = (const float*)d_in[2];
    const float* FacTu = (const float*)d_in[3];
    const float* FacTv = (const float*)d_in[4];
    const float* qF    = (const float*)d_in[5];
    const float* vF    = (const float*)d_in[6];
    const float* rph   = (const float*)d_in[7];
    const float* rpw   = (const float*)d_in[8];
    const float* Wproj = (const float*)d_in[9];
    const float* bproj = (const float*)d_in[10];
    float* out = (float*)d_out;

    void *pQkv, *pXh, *pXl, *pOph, *pOpl, *pWqT_h, *pWqT_l, *pWpT_h, *pWpT_l;
    cudaGetSymbolAddress(&pQkv, g_qkv);
    cudaGetSymbolAddress(&pXh, g_xh);
    cudaGetSymbolAddress(&pXl, g_xl);
    cudaGetSymbolAddress(&pOph, g_oph);
    cudaGetSymbolAddress(&pOpl, g_opl);
    cudaGetSymbolAddress(&pWqT_h, g_wqkvT_h);
    cudaGetSymbolAddress(&pWqT_l, g_wqkvT_l);
    cudaGetSymbolAddress(&pWpT_h, g_wprojT_h);
    cudaGetSymbolAddress(&pWpT_l, g_wprojT_l);

    cudaFuncSetAttribute(attn_mma_kernel,
                         cudaFuncAttributeMaxDynamicSharedMemorySize, (int)SM_TOT);
    cudaFuncSetAttribute(hgemm_bf16,
                         cudaFuncAttributeMaxDynamicSharedMemorySize, (int)HG_SMEM);

    fact_small_kernel<<<(DIM * RANK * 2 + 255) / 256, 256>>>(FacTu, qF, vF);
    xsplit_kernel<<<(HW * DIM / 4 + 255) / 256, 256>>>(x);

    {   // Wqkv (+delta) -> transposed split
        dim3 grid((3 * DIM) / 32, DIM / 32);
        wsplit_kernel<<<grid, 256>>>(Wqkv, FacTv,
                                     (__nv_bfloat16*)pWqT_h, (__nv_bfloat16*)pWqT_l,
                                     3 * DIM, 1);
    }
    {   // Wproj -> transposed split
        dim3 grid(DIM / 32, DIM / 32);
        wsplit_kernel<<<grid, 256>>>(Wproj, FacTv,
                                     (__nv_bfloat16*)pWpT_h, (__nv_bfloat16*)pWpT_l,
                                     DIM, 0);
    }
    {   // qkv = x @ Weff + bqkv (HMMA, 96-row tiles)
        dim3 grid((3 * DIM) / 128, HW / 96);
        hgemm_bf16<<<grid, 256, HG_SMEM>>>((const __nv_bfloat16*)pXh,
                                           (const __nv_bfloat16*)pXl,
                                           (const __nv_bfloat16*)pWqT_h,
                                           (const __nv_bfloat16*)pWqT_l,
                                           bqkv, (float*)pQkv, HW, 3 * DIM, DIM);
    }
    {   // rel-pos tables (pre-scaled by log2e)
        dim3 grid(GH, NH, 2);
        rel_tab2_kernel<<<grid, 256>>>(rph, rpw);
    }
    {   // bf16 split K / transposed V
        dim3 grid(HW / 64, NH);
        kv_prep_kernel<<<grid, 256>>>();
    }
    {   // pipelined split-KV tensor-core attention
        dim3 grid(HW / 128, NH, KSPLIT);
        attn_mma_kernel<<<grid, 256, SM_TOT>>>();
    }
    {   // combine partials
        combine_kernel<<<(HW * DIM / 2 + 255) / 256, 256>>>();
    }
    {   // out = opre @ Wproj + bproj (HMMA, 96-row tiles)
        dim3 grid(DIM / 128, HW / 96);
        hgemm_bf16<<<grid, 256, HG_SMEM>>>((const __nv_bfloat16*)pOph,
                                           (const __nv_bfloat16*)pOpl,
                                           (const __nv_bfloat16*)pWpT_h,
                                           (const __nv_bfloat16*)pWpT_l,
                                           bproj, out, HW, DIM, DIM);
    }
}

// round 12
// speedup vs baseline: 1.6208x; 1.1738x over previous
#include <cuda_runtime.h>
#include <cuda_fp16.h>
#include <cstdint>

#define DIM   768
#define NH    12
#define HD    64
#define GH    48           // grid H = W
#define HW    2304         // 48*48
#define RANK  32
#define QK_SCALE 0.125f    // 64^-0.5
#define LOG2E 1.4426950408889634f
#define QSCL (QK_SCALE * LOG2E)
#define FACT_S 1.0f
#define NT    36           // kv tiles of 64
#define KSPLIT 2
#define NTT   (NT / KSPLIT)  // 18 tiles per split

typedef unsigned long long u64;

// ---------------- packed helpers --------------------------------------------
__device__ __forceinline__ void unpack2f(u64 v, float& a, float& b) {
    unsigned x, y;
    asm("mov.b64 {%0, %1}, %2;" : "=r"(x), "=r"(y) : "l"(v));
    a = __uint_as_float(x);
    b = __uint_as_float(y);
}
__device__ __forceinline__ void ffma2(u64& d, u64 a, u64 b) {
    asm("fma.rn.f32x2 %0, %1, %2, %0;" : "+l"(d) : "l"(a), "l"(b));
}
// fp16 split: hi = f16x2(a,b) (a in low half), lo = f16x2 of residuals
__device__ __forceinline__ void split2h(float a, float b, uint32_t& hi, uint32_t& lo) {
    uint32_t h;
    asm("cvt.rn.f16x2.f32 %0, %1, %2;" : "=r"(h) : "f"(b), "f"(a));
    float ra, rb;
    asm("{\n\t.reg .f16 x, y;\n\tmov.b32 {x, y}, %2;\n\t"
        "cvt.f32.f16 %0, x;\n\tcvt.f32.f16 %1, y;\n\t}"
        : "=f"(ra), "=f"(rb) : "r"(h));
    hi = h;
    asm("cvt.rn.f16x2.f32 %0, %1, %2;" : "=r"(lo) : "f"(b - rb), "f"(a - ra));
}
__device__ __forceinline__ float ex2f(float x) {
    float y;
    asm("ex2.approx.f32 %0, %1;" : "=f"(y) : "f"(x));
    return y;
}

// ---------------- mma / ldmatrix / cp.async helpers --------------------------
__device__ __forceinline__ void mma16816(float c[4], const uint32_t a[4],
                                         uint32_t b0, uint32_t b1) {
    asm volatile(
        "mma.sync.aligned.m16n8k16.row.col.f32.f16.f16.f32 "
        "{%0,%1,%2,%3}, {%4,%5,%6,%7}, {%8,%9}, {%0,%1,%2,%3};"
        : "+f"(c[0]), "+f"(c[1]), "+f"(c[2]), "+f"(c[3])
        : "r"(a[0]), "r"(a[1]), "r"(a[2]), "r"(a[3]), "r"(b0), "r"(b1));
}
__device__ __forceinline__ void ldsm4(uint32_t r[4], uint32_t addr) {
    asm volatile("ldmatrix.sync.aligned.m8n8.x4.shared.b16 {%0,%1,%2,%3}, [%4];"
                 : "=r"(r[0]), "=r"(r[1]), "=r"(r[2]), "=r"(r[3]) : "r"(addr));
}
__device__ __forceinline__ uint32_t smem_to_u32(const void* smem_ptr) {
    uint32_t addr;
    asm("{ .reg .u64 tmp; cvta.to.shared.u64 tmp, %1; cvt.u32.u64 %0, tmp; }"
        : "=r"(addr) : "l"(smem_ptr));
    return addr;
}
__device__ __forceinline__ void cp16(uint32_t dst, const void* src) {
    asm volatile("cp.async.cg.shared.global [%0], [%1], 16;"
                 :: "r"(dst), "l"(src));
}
#define CP_COMMIT() asm volatile("cp.async.commit_group;" ::: "memory")
#define CP_WAIT0()  asm volatile("cp.async.wait_group 0;" ::: "memory")
#define CP_WAIT1()  asm volatile("cp.async.wait_group 1;" ::: "memory")

// ---------------- device scratch (no allocations allowed) ------------------
__device__ float g_A1[DIM * RANK];
__device__ float g_A2[DIM * RANK];
__device__ float g_qkv[HW * 3 * DIM];
__device__ float g_relh[NH * HW * GH];   // pre-scaled by LOG2E
__device__ float g_relw[NH * HW * GH];   // pre-scaled by LOG2E
// split-KV partials
__device__ __align__(16) float g_opart[KSPLIT * HW * DIM];
__device__ float g_lpart[KSPLIT * NH * HW];
// pre-split inputs / intermediates (fp16)
__device__ __align__(16) __half g_xh[HW * DIM];
__device__ __align__(16) __half g_xl[HW * DIM];
__device__ __align__(16) __half g_oph[HW * DIM];
__device__ __align__(16) __half g_opl[HW * DIM];
// transposed weights [N][K] fp16 (hi only — 2-pass drops B residual)
__device__ __align__(16) __half g_wqkvT_h[3 * DIM * DIM];
__device__ __align__(16) __half g_wprojT_h[DIM * DIM];
// fp16 K [head][key][dim] and transposed V [head][dim][key] (hi only)
__device__ __align__(16) __half g_kh[NH * HW * HD];
__device__ __align__(16) __half g_vh[NH * HD * HW];

// ---------------- K0: A1 = FacTu @ q_FacTs, A2 = FacTu @ v_FacTs -----------
__global__ void fact_small_kernel(const float* __restrict__ FacTu,
                                  const float* __restrict__ qF,
                                  const float* __restrict__ vF) {
    int idx = blockIdx.x * 256 + threadIdx.x;
    if (idx >= DIM * RANK * 2) return;
    int which = idx / (DIM * RANK);
    int rem = idx - which * (DIM * RANK);
    int i = rem / RANK, r = rem - (rem / RANK) * RANK;
    const float* F = which ? vF : qF;
    float s = 0.f;
#pragma unroll
    for (int k = 0; k < RANK; k++) s += FacTu[i * RANK + k] * F[k * RANK + r];
    (which ? g_A2 : g_A1)[i * RANK + r] = s;
}

// ---------------- K0b: split x into fp16 hi/lo ------------------------------
__global__ void __launch_bounds__(256) xsplit_kernel(const float* __restrict__ x) {
    int idx = blockIdx.x * 256 + threadIdx.x;
    if (idx >= HW * DIM / 4) return;
    float4 v = *(const float4*)&x[idx * 4];
    uint32_t h0, l0, h1, l1;
    split2h(v.x, v.y, h0, l0);
    split2h(v.z, v.w, h1, l1);
    *(uint2*)&g_xh[idx * 4] = make_uint2(h0, h1);
    *(uint2*)&g_xl[idx * 4] = make_uint2(l0, l1);
}

// ---------------- K1: transpose + low-rank fold + fp16 (hi only) -----------
__global__ void __launch_bounds__(256)
wsplit_kernel(const float* __restrict__ W, const float* __restrict__ FacTv,
              __half* __restrict__ WTh, int NJ, int mode) {
    __shared__ float tile[32 * 33];
    const int tid = threadIdx.x;
    const int j0 = blockIdx.x * 32;
    const int i0 = blockIdx.y * 32;

    {
        const int j = tid & 31;
        const int ib = tid >> 5;
        const float* Aarr = nullptr;
        int jj = j0 + j;
        if (mode) {
            if (jj < DIM) Aarr = g_A1;
            else if (jj >= 2 * DIM) { Aarr = g_A2; jj -= 2 * DIM; }
        }
#pragma unroll
        for (int it = 0; it < 4; it++) {
            int il = ib + it * 8;
            int i = i0 + il;
            float w = W[(size_t)i * NJ + j0 + j];
            if (Aarr) {
                float s = 0.f;
#pragma unroll
                for (int r = 0; r < RANK; r++)
                    s += Aarr[i * RANK + r] * FacTv[r * DIM + jj];
                w += FACT_S * s;
            }
            tile[il * 33 + j] = w;
        }
    }
    __syncthreads();
    {
        const int i = tid & 31;
        const int jb = tid >> 5;
#pragma unroll
        for (int it = 0; it < 4; it++) {
            int jl = jb + it * 8;
            WTh[(size_t)(j0 + jl) * DIM + i0 + i] = __float2half_rn(tile[i * 33 + jl]);
        }
    }
}

// ---------------- K2: HMMA GEMM fp16 2-pass (96x128 tile, cp.async) ---------
// C = (Ah+Al) @ Bh^T + bias.  A hi/lo [M][K], B hi [N][K]. K%32==0, M%96==0.
#define GS 40                 // smem row stride in f16 (80B)
#define A_CH 384              // cp16 chunks per A array (96 rows * 4)
#define AARR 7680             // bytes per A array (96*80)
#define BARR 10240            // bytes per B array (128*80)
#define STG  25600            // bytes per stage (2*AARR + BARR)
__global__ void __launch_bounds__(256)
hgemm_f16(const __half* __restrict__ Ah_,
          const __half* __restrict__ Al_,
          const __half* __restrict__ Bh_,
          const float* __restrict__ bias, float* __restrict__ C,
          int M, int N, int K) {
    extern __shared__ __align__(16) char gsm[];
    const uint32_t smb = smem_to_u32(gsm);
    const int tid = threadIdx.x, lane = tid & 31, warp = tid >> 5;
    const int wm = (warp >> 2) * 48, wn = (warp & 3) * 32;
    const int bm = blockIdx.y * 96, bn = blockIdx.x * 128;

#define GB_ISSUE(k0) do { \
        _Pragma("unroll") \
        for (int t = 0; t < 5; t++) { \
            int i = tid + t * 256; \
            const __half* gptr; uint32_t soff; int j, grow; \
            if (i < A_CH) { gptr = Ah_; soff = 0; j = i; grow = bm; } \
            else if (i < 2 * A_CH) { gptr = Al_; soff = AARR; j = i - A_CH; grow = bm; } \
            else { gptr = Bh_; soff = 2 * AARR; j = i - 2 * A_CH; grow = bn; } \
            int row = j >> 2, c = j & 3; \
            grow += row; \
            const char* src = (const char*)&gptr[(size_t)grow * K + (k0)] + c * 16; \
            cp16(sb + soff + row * 80 + c * 16, src); \
        } \
        CP_COMMIT(); \
    } while (0)

    float acc[3][4][4];
#pragma unroll
    for (int a = 0; a < 3; a++)
#pragma unroll
        for (int b = 0; b < 4; b++)
#pragma unroll
            for (int c = 0; c < 4; c++) acc[a][b][c] = 0.f;

    {
        uint32_t sb = smb;
        GB_ISSUE(0);
    }

    const uint32_t aoff = (uint32_t)((lane & 15) * GS + ((lane >> 4) << 3)) * 2;
    const uint32_t boff = (uint32_t)(((lane & 7) + ((lane & 16) >> 1)) * GS + (lane & 8)) * 2;

    const int NKT = K / 32;
    for (int kt = 0; kt < NKT; kt++) {
        CP_WAIT0();
        __syncthreads();
        if (kt + 1 < NKT) {
            uint32_t sb = smb + (uint32_t)((kt + 1) & 1) * STG;
            GB_ISSUE((kt + 1) * 32);
        }
        const uint32_t cb = smb + (uint32_t)(kt & 1) * STG;
        const uint32_t sAh = cb, sAl = cb + AARR, sBh = cb + 2 * AARR;

#pragma unroll
        for (int ks = 0; ks < 2; ks++) {
            uint32_t ah[3][4], al[3][4];
#pragma unroll
            for (int mt = 0; mt < 3; mt++) {
                uint32_t off = (uint32_t)(wm + mt * 16) * (GS * 2) + (uint32_t)ks * 32 + aoff;
                ldsm4(ah[mt], sAh + off);
                ldsm4(al[mt], sAl + off);
            }
            uint32_t bh[2][4];
#pragma unroll
            for (int nt = 0; nt < 2; nt++) {
                uint32_t off = (uint32_t)(wn + nt * 16) * (GS * 2) + (uint32_t)ks * 32 + boff;
                ldsm4(bh[nt], sBh + off);
            }
#pragma unroll
            for (int mt = 0; mt < 3; mt++)
#pragma unroll
                for (int nt = 0; nt < 4; nt++) {
                    uint32_t b0h = bh[nt >> 1][(nt & 1) * 2];
                    uint32_t b1h = bh[nt >> 1][(nt & 1) * 2 + 1];
                    mma16816(acc[mt][nt], ah[mt], b0h, b1h);
                    mma16816(acc[mt][nt], al[mt], b0h, b1h);
                }
        }
        __syncthreads();
    }

    const int gid = lane >> 2, tig = lane & 3;
#pragma unroll
    for (int mt = 0; mt < 3; mt++) {
        int m0 = bm + wm + mt * 16 + gid;
#pragma unroll
        for (int nt = 0; nt < 4; nt++) {
            int n0 = bn + wn + nt * 8 + 2 * tig;
            float bx = bias ? bias[n0] : 0.f;
            float by = bias ? bias[n0 + 1] : 0.f;
            *(float2*)&C[(size_t)m0 * N + n0] =
                make_float2(acc[mt][nt][0] + bx, acc[mt][nt][1] + by);
            *(float2*)&C[(size_t)(m0 + 8) * N + n0] =
                make_float2(acc[mt][nt][2] + bx, acc[mt][nt][3] + by);
        }
    }
}
#define HG_SMEM (2 * STG)

// ---------------- K3: rel bias tables (pre-scaled by LOG2E) -----------------
__global__ void __launch_bounds__(256) rel_tab2_kernel(const float* __restrict__ rph,
                                                       const float* __restrict__ rpw) {
    __shared__ float Qs[GH * 68];
    __shared__ float Rs[GH * 68];
    const int pos = blockIdx.x;
    const int head = blockIdx.y;
    const int which = blockIdx.z;
    const int tid = threadIdx.x;

    for (int i = tid; i < GH * HD; i += 256) {
        int r = i >> 6, c = i & 63;
        int t = which ? (r * GH + pos) : (pos * GH + r);
        Qs[r * 68 + c] = g_qkv[(size_t)t * (3 * DIM) + head * HD + c];
    }
    const float* rp = which ? rpw : rph;
    for (int i = tid; i < GH * HD; i += 256) {
        int k = i >> 6, c = i & 63;
        Rs[k * 68 + c] = rp[(pos - k + GH - 1) * HD + c];
    }
    __syncthreads();

    const int tx = tid & 15, ty = tid >> 4;
    u64 acc[3][3];
#pragma unroll
    for (int i = 0; i < 3; i++)
#pragma unroll
        for (int j = 0; j < 3; j++) acc[i][j] = 0ull;

    for (int c = 0; c < HD; c += 4) {
        ulonglong2 q[3], r[3];
#pragma unroll
        for (int i = 0; i < 3; i++) q[i] = *(const ulonglong2*)&Qs[(ty * 3 + i) * 68 + c];
#pragma unroll
        for (int j = 0; j < 3; j++) r[j] = *(const ulonglong2*)&Rs[(tx * 3 + j) * 68 + c];
#pragma unroll
        for (int i = 0; i < 3; i++)
#pragma unroll
            for (int j = 0; j < 3; j++) {
                ffma2(acc[i][j], q[i].x, r[j].x);
                ffma2(acc[i][j], q[i].y, r[j].y);
            }
    }

    float* outp = which ? g_relw : g_relh;
#pragma unroll
    for (int i = 0; i < 3; i++) {
        int row = ty * 3 + i;
        int t = which ? (row * GH + pos) : (pos * GH + row);
#pragma unroll
        for (int j = 0; j < 3; j++) {
            float lo, hi;
            unpack2f(acc[i][j], lo, hi);
            outp[((size_t)head * HW + t) * GH + tx * 3 + j] = (lo + hi) * LOG2E;
        }
    }
}

// ---------------- K3b: K and transposed V to fp16 (hi only) -----------------
__global__ void __launch_bounds__(256) kv_prep_kernel() {
    __shared__ float vs[64 * 65];
    const int kt0 = blockIdx.x * 64;
    const int head = blockIdx.y;
    const int tid = threadIdx.x;

    for (int i = tid; i < 64 * 64; i += 256) {
        int r = i >> 6, c = i & 63;
        const float* src = &g_qkv[(size_t)(kt0 + r) * (3 * DIM) + head * HD + c];
        g_kh[((size_t)head * HW + kt0 + r) * HD + c] = __float2half_rn(src[DIM]);
        vs[r * 65 + c] = src[2 * DIM];
    }
    __syncthreads();
    for (int i = tid; i < 64 * 64; i += 256) {
        int d = i >> 6, k = i & 63;
        g_vh[((size_t)head * HD + d) * HW + kt0 + k] = __float2half_rn(vs[k * 65 + d]);
    }
}

// ---------------- K4: pipelined split-KV fp16 2-pass flash attention --------
#define ROWB   144            // 72 f16 = 144 bytes per padded row
#define ARR_SZ (64 * ROWB)    // 9216
#define SB_V   ARR_SZ
#define BUF_SZ (2 * ARR_SZ)   // 18432 (K + V)
#define SM_RH  (4 * BUF_SZ)                 // 73728
#define SM_RW  (SM_RH + 128 * GH * 4)       // +24576
#define SM_TOT (SM_RW + 128 * GH * 4)       // 122880 (120KB) -> 1 CTA/SM

__device__ __forceinline__ void copy_kv_async(uint32_t dstb, int head, int kt0) {
    const int tid = threadIdx.x;   // 256 threads
    const char* khb = (const char*)(g_kh + ((size_t)head * HW + kt0) * HD);
#pragma unroll
    for (int it = 0; it < 2; it++) {
        int i = tid + it * 256;
        int r = i >> 3, c = i & 7;
        cp16(dstb + r * ROWB + c * 16, khb + i * 16);
    }
    const char* vhb = (const char*)(g_vh + (size_t)head * HD * HW + kt0);
#pragma unroll
    for (int it = 0; it < 2; it++) {
        int i = tid + it * 256;
        int dr = i >> 3, c = i & 7;
        cp16(dstb + SB_V + dr * ROWB + c * 16, vhb + (size_t)dr * (HW * 2) + c * 16);
    }
    CP_COMMIT();
}

__device__ __forceinline__ void s_mma_tile(float S[8][4], uint32_t kb,
                                           const uint32_t qhi[4][4],
                                           const uint32_t qlo[4][4],
                                           uint32_t lm4off) {
#pragma unroll
    for (int j = 0; j < 8; j++) {
#pragma unroll
        for (int i = 0; i < 4; i++) S[j][i] = 0.f;
        uint32_t base = kb + (uint32_t)j * (8 * ROWB) + lm4off;
#pragma unroll
        for (int s = 0; s < 4; s += 2) {
            uint32_t bh[4];
            ldsm4(bh, base + s * 32);
            mma16816(S[j], qhi[s], bh[0], bh[1]);
            mma16816(S[j], qlo[s], bh[0], bh[1]);
            mma16816(S[j], qhi[s + 1], bh[2], bh[3]);
            mma16816(S[j], qlo[s + 1], bh[2], bh[3]);
        }
    }
}

__global__ void __launch_bounds__(256) attn_mma_kernel() {
    extern __shared__ char smc[];
    const uint32_t smb = smem_to_u32(smc);
    const int tid = threadIdx.x, lane = tid & 31, warp = tid >> 5;   // 8 warps
    const int gid = lane >> 2, tig = lane & 3;
    const int head = blockIdx.y;
    const int qt0 = blockIdx.x * 128;
    const int zs = blockIdx.z;
    const int T0 = zs * NTT;

    copy_kv_async(smb, head, T0 * 64);
    copy_kv_async(smb + BUF_SZ, head, (T0 + 1) * 64);
    copy_kv_async(smb + 2 * BUF_SZ, head, (T0 + 2) * 64);

    float* Rh = (float*)(smc + SM_RH);
    float* Rw = (float*)(smc + SM_RW);
    {
        const float4* sH = (const float4*)&g_relh[((size_t)head * HW + qt0) * GH];
        const float4* sW = (const float4*)&g_relw[((size_t)head * HW + qt0) * GH];
        float4* dH = (float4*)Rh;
        float4* dW = (float4*)Rw;
        for (int i = tid; i < 128 * GH / 4; i += 256) { dH[i] = sH[i]; dW[i] = sW[i]; }
    }

    uint32_t qhi[4][4], qlo[4][4];
    {
        const float* q0 = &g_qkv[(size_t)(qt0 + warp * 16 + gid) * (3 * DIM) + head * HD];
        const float* q1 = q0 + (size_t)8 * (3 * DIM);
#pragma unroll
        for (int s = 0; s < 4; s++) {
            int c = 16 * s + 2 * tig;
            float2 v;
            v = *(const float2*)&q0[c];
            split2h(QSCL * v.x, QSCL * v.y, qhi[s][0], qlo[s][0]);
            v = *(const float2*)&q1[c];
            split2h(QSCL * v.x, QSCL * v.y, qhi[s][1], qlo[s][1]);
            v = *(const float2*)&q0[c + 8];
            split2h(QSCL * v.x, QSCL * v.y, qhi[s][2], qlo[s][2]);
            v = *(const float2*)&q1[c + 8];
            split2h(QSCL * v.x, QSCL * v.y, qhi[s][3], qlo[s][3]);
        }
    }

    const uint32_t lm4off = (uint32_t)((lane & 7) * ROWB + (lane >> 3) * 16);

    CP_WAIT1();            // bufs 0,1 locally complete (buf2 in flight)
    __syncthreads();       // bufs 0,1 + Rh/Rw visible to all warps

    float Scur[8][4], Snext[8][4];
    s_mma_tile(Scur, smb, qhi, qlo, lm4off);

    float Oacc[8][4];
#pragma unroll
    for (int j = 0; j < 8; j++)
#pragma unroll
        for (int i = 0; i < 4; i++) Oacc[j][i] = 0.f;
    float rs0 = 0.f, rs1 = 0.f;

    const float* rh0 = &Rh[(warp * 16 + gid) * GH];
    const float* rh1 = rh0 + 8 * GH;
    const float* rw0 = &Rw[(warp * 16 + gid) * GH];
    const float* rw1 = rw0 + 8 * GH;

    for (int tt = 0; tt < NTT; tt++) {
        const int kt0 = (T0 + tt) * 64;
        __syncthreads();   // buf(tt+1) visible; buf((tt-1)&3) free for reuse
        if (tt + 3 < NTT)
            copy_kv_async(smb + (uint32_t)((tt + 3) & 3) * BUF_SZ, head, (T0 + tt + 3) * 64);
        if (tt + 1 < NTT)
            s_mma_tile(Snext, smb + (uint32_t)((tt + 1) & 3) * BUF_SZ, qhi, qlo, lm4off);

        // softmax on Scur: hk takes exactly 2 values per tile
        {
            const int hkA = kt0 / GH;
            const int kbd = (hkA + 1) * GH;
            const int sub0 = hkA * GH, sub1 = sub0 + GH;
            const float rhA0 = rh0[hkA], rhB0 = rh0[hkA + 1];
            const float rhA1 = rh1[hkA], rhB1 = rh1[hkA + 1];
#pragma unroll
            for (int j = 0; j < 8; j++) {
                int k0 = kt0 + 8 * j + 2 * tig;
                int k1 = k0 + 1;
                bool c0 = k0 < kbd, c1 = k1 < kbd;
                int wk0 = k0 - (c0 ? sub0 : sub1);
                int wk1 = k1 - (c1 ? sub0 : sub1);
                float b00 = (c0 ? rhA0 : rhB0) + rw0[wk0];
                float b01 = (c1 ? rhA0 : rhB0) + rw0[wk1];
                float b10 = (c0 ? rhA1 : rhB1) + rw1[wk0];
                float b11 = (c1 ? rhA1 : rhB1) + rw1[wk1];
                float e0 = ex2f(Scur[j][0] + b00);
                float e1 = ex2f(Scur[j][1] + b01);
                float e2 = ex2f(Scur[j][2] + b10);
                float e3 = ex2f(Scur[j][3] + b11);
                rs0 += e0 + e1;
                rs1 += e2 + e3;
                Scur[j][0] = e0; Scur[j][1] = e1; Scur[j][2] = e2; Scur[j][3] = e3;
            }
        }

        uint32_t phi[4][4], plo[4][4];
#pragma unroll
        for (int s = 0; s < 4; s++) {
            split2h(Scur[2 * s][0],     Scur[2 * s][1],     phi[s][0], plo[s][0]);
            split2h(Scur[2 * s][2],     Scur[2 * s][3],     phi[s][1], plo[s][1]);
            split2h(Scur[2 * s + 1][0], Scur[2 * s + 1][1], phi[s][2], plo[s][2]);
            split2h(Scur[2 * s + 1][2], Scur[2 * s + 1][3], phi[s][3], plo[s][3]);
        }

        const uint32_t vb = smb + (uint32_t)(tt & 3) * BUF_SZ + SB_V;
#pragma unroll
        for (int j = 0; j < 8; j++) {
            uint32_t base = vb + (uint32_t)j * (8 * ROWB) + lm4off;
#pragma unroll
            for (int s = 0; s < 4; s += 2) {
                uint32_t vh[4];
                ldsm4(vh, base + s * 32);
                mma16816(Oacc[j], phi[s], vh[0], vh[1]);
                mma16816(Oacc[j], plo[s], vh[0], vh[1]);
                mma16816(Oacc[j], phi[s + 1], vh[2], vh[3]);
                mma16816(Oacc[j], plo[s + 1], vh[2], vh[3]);
            }
        }

        if (tt + 3 < NTT) { CP_WAIT1(); } else { CP_WAIT0(); }   // buf(tt+2) locally done

        if (tt + 1 < NTT) {
#pragma unroll
            for (int j = 0; j < 8; j++)
#pragma unroll
                for (int i = 0; i < 4; i++) Scur[j][i] = Snext[j][i];
        }
    }

    // partial row-sums + unnormalized partial O to gmem
    rs0 += __shfl_xor_sync(0xffffffffu, rs0, 1);
    rs0 += __shfl_xor_sync(0xffffffffu, rs0, 2);
    rs1 += __shfl_xor_sync(0xffffffffu, rs1, 1);
    rs1 += __shfl_xor_sync(0xffffffffu, rs1, 2);

    const int row0 = qt0 + warp * 16 + gid;
    if (tig == 0) {
        g_lpart[(size_t)zs * NH * HW + (size_t)head * HW + row0] = rs0;
        g_lpart[(size_t)zs * NH * HW + (size_t)head * HW + row0 + 8] = rs1;
    }
    float* op = g_opart + (size_t)zs * HW * DIM;
    const size_t r0 = (size_t)row0 * DIM + head * HD;
    const size_t r1 = r0 + (size_t)8 * DIM;
#pragma unroll
    for (int j = 0; j < 8; j++) {
        int c = 8 * j + 2 * tig;
        *(float2*)&op[r0 + c] = make_float2(Oacc[j][0], Oacc[j][1]);
        *(float2*)&op[r1 + c] = make_float2(Oacc[j][2], Oacc[j][3]);
    }
}

// ---------------- K4b: combine split-KV partials -> fp16 hi/lo --------------
__global__ void __launch_bounds__(256) combine_kernel() {
    int idx = blockIdx.x * 256 + threadIdx.x;   // 2 cols per thread
    if (idx >= HW * DIM / 2) return;
    int row = idx / (DIM / 2);
    int cc = (idx - row * (DIM / 2)) * 2;
    int head = cc >> 6;
    float l = g_lpart[(size_t)head * HW + row]
            + g_lpart[(size_t)NH * HW + (size_t)head * HW + row];
    float inv = 1.f / l;
    size_t o = (size_t)row * DIM + cc;
    float2 o0 = *(const float2*)&g_opart[o];
    float2 o1 = *(const float2*)&g_opart[(size_t)HW * DIM + o];
    uint32_t h, lo;
    split2h((o0.x + o1.x) * inv, (o0.y + o1.y) * inv, h, lo);
    *(uint32_t*)&g_oph[o] = h;
    *(uint32_t*)&g_opl[o] = lo;
}

// ---------------- launch -----------------------------------------------------
extern "C" void kernel_launch(void* const* d_in, const int* in_sizes, int n_in,
                              void* d_out, int out_size) {
    const float* x     = (const float*)d_in[0];
    const float* Wqkv  = (const float*)d_in[1];
    const float* bqkv  = (const float*)d_in[2];
    const float* FacTu = (const float*)d_in[3];
    const float* FacTv = (const float*)d_in[4];
    const float* qF    = (const float*)d_in[5];
    const float* vF    = (const float*)d_in[6];
    const float* rph   = (const float*)d_in[7];
    const float* rpw   = (const float*)d_in[8];
    const float* Wproj = (const float*)d_in[9];
    const float* bproj = (const float*)d_in[10];
    float* out = (float*)d_out;

    void *pQkv, *pXh, *pXl, *pOph, *pOpl, *pWqT_h, *pWpT_h;
    cudaGetSymbolAddress(&pQkv, g_qkv);
    cudaGetSymbolAddress(&pXh, g_xh);
    cudaGetSymbolAddress(&pXl, g_xl);
    cudaGetSymbolAddress(&pOph, g_oph);
    cudaGetSymbolAddress(&pOpl, g_opl);
    cudaGetSymbolAddress(&pWqT_h, g_wqkvT_h);
    cudaGetSymbolAddress(&pWpT_h, g_wprojT_h);

    cudaFuncSetAttribute(attn_mma_kernel,
                         cudaFuncAttributeMaxDynamicSharedMemorySize, (int)SM_TOT);
    cudaFuncSetAttribute(hgemm_f16,
                         cudaFuncAttributeMaxDynamicSharedMemorySize, (int)HG_SMEM);

    fact_small_kernel<<<(DIM * RANK * 2 + 255) / 256, 256>>>(FacTu, qF, vF);
    xsplit_kernel<<<(HW * DIM / 4 + 255) / 256, 256>>>(x);

    {   // Wqkv (+delta) -> transposed fp16
        dim3 grid((3 * DIM) / 32, DIM / 32);
        wsplit_kernel<<<grid, 256>>>(Wqkv, FacTv, (__half*)pWqT_h, 3 * DIM, 1);
    }
    {   // Wproj -> transposed fp16
        dim3 grid(DIM / 32, DIM / 32);
        wsplit_kernel<<<grid, 256>>>(Wproj, FacTv, (__half*)pWpT_h, DIM, 0);
    }
    {   // qkv = x @ Weff + bqkv (fp16 2-pass HMMA)
        dim3 grid((3 * DIM) / 128, HW / 96);
        hgemm_f16<<<grid, 256, HG_SMEM>>>((const __half*)pXh, (const __half*)pXl,
                                          (const __half*)pWqT_h,
                                          bqkv, (float*)pQkv, HW, 3 * DIM, DIM);
    }
    {   // rel-pos tables (pre-scaled by log2e)
        dim3 grid(GH, NH, 2);
        rel_tab2_kernel<<<grid, 256>>>(rph, rpw);
    }
    {   // fp16 K / transposed V
        dim3 grid(HW / 64, NH);
        kv_prep_kernel<<<grid, 256>>>();
    }
    {   // pipelined split-KV fp16 2-pass attention
        dim3 grid(HW / 128, NH, KSPLIT);
        attn_mma_kernel<<<grid, 256, SM_TOT>>>();
    }
    {   // combine partials
        combine_kernel<<<(HW * DIM / 2 + 255) / 256, 256>>>();
    }
    {   // out = opre @ Wproj + bproj (fp16 2-pass HMMA)
        dim3 grid(DIM / 128, HW / 96);
        hgemm_f16<<<grid, 256, HG_SMEM>>>((const __half*)pOph, (const __half*)pOpl,
                                          (const __half*)pWpT_h,
                                          bproj, out, HW, DIM, DIM);
    }
}

// round 13
// speedup vs baseline: 1.6817x; 1.0376x over previous
#include <cuda_runtime.h>
#include <cuda_fp16.h>
#include <cstdint>

#define DIM   768
#define NH    12
#define HD    64
#define GH    48           // grid H = W
#define HW    2304         // 48*48
#define RANK  32
#define QK_SCALE 0.125f    // 64^-0.5
#define LOG2E 1.4426950408889634f
#define QSCL (QK_SCALE * LOG2E)
#define FACT_S 1.0f
#define NT    36           // kv tiles of 64
#define KSPLIT 2
#define NTT   (NT / KSPLIT)  // 18 tiles per split

typedef unsigned long long u64;

// ---------------- packed helpers --------------------------------------------
__device__ __forceinline__ void unpack2f(u64 v, float& a, float& b) {
    unsigned x, y;
    asm("mov.b64 {%0, %1}, %2;" : "=r"(x), "=r"(y) : "l"(v));
    a = __uint_as_float(x);
    b = __uint_as_float(y);
}
__device__ __forceinline__ void ffma2(u64& d, u64 a, u64 b) {
    asm("fma.rn.f32x2 %0, %1, %2, %0;" : "+l"(d) : "l"(a), "l"(b));
}
// fp16x2 pack (a in low half)
__device__ __forceinline__ uint32_t cvth2(float a, float b) {
    uint32_t h;
    asm("cvt.rn.f16x2.f32 %0, %1, %2;" : "=r"(h) : "f"(b), "f"(a));
    return h;
}
// fp16 split: hi = f16x2(a,b), lo = f16x2 of residuals
__device__ __forceinline__ void split2h(float a, float b, uint32_t& hi, uint32_t& lo) {
    uint32_t h = cvth2(a, b);
    float ra, rb;
    asm("{\n\t.reg .f16 x, y;\n\tmov.b32 {x, y}, %2;\n\t"
        "cvt.f32.f16 %0, x;\n\tcvt.f32.f16 %1, y;\n\t}"
        : "=f"(ra), "=f"(rb) : "r"(h));
    hi = h;
    lo = cvth2(a - ra, b - rb);
}
__device__ __forceinline__ float ex2f(float x) {
    float y;
    asm("ex2.approx.f32 %0, %1;" : "=f"(y) : "f"(x));
    return y;
}

// ---------------- mma / ldmatrix / cp.async helpers --------------------------
__device__ __forceinline__ void mma16816(float c[4], const uint32_t a[4],
                                         uint32_t b0, uint32_t b1) {
    asm volatile(
        "mma.sync.aligned.m16n8k16.row.col.f32.f16.f16.f32 "
        "{%0,%1,%2,%3}, {%4,%5,%6,%7}, {%8,%9}, {%0,%1,%2,%3};"
        : "+f"(c[0]), "+f"(c[1]), "+f"(c[2]), "+f"(c[3])
        : "r"(a[0]), "r"(a[1]), "r"(a[2]), "r"(a[3]), "r"(b0), "r"(b1));
}
__device__ __forceinline__ void ldsm4(uint32_t r[4], uint32_t addr) {
    asm volatile("ldmatrix.sync.aligned.m8n8.x4.shared.b16 {%0,%1,%2,%3}, [%4];"
                 : "=r"(r[0]), "=r"(r[1]), "=r"(r[2]), "=r"(r[3]) : "r"(addr));
}
__device__ __forceinline__ uint32_t smem_to_u32(const void* smem_ptr) {
    uint32_t addr;
    asm("{ .reg .u64 tmp; cvta.to.shared.u64 tmp, %1; cvt.u32.u64 %0, tmp; }"
        : "=r"(addr) : "l"(smem_ptr));
    return addr;
}
__device__ __forceinline__ void cp16(uint32_t dst, const void* src) {
    asm volatile("cp.async.cg.shared.global [%0], [%1], 16;"
                 :: "r"(dst), "l"(src));
}
#define CP_COMMIT() asm volatile("cp.async.commit_group;" ::: "memory")
#define CP_WAIT0()  asm volatile("cp.async.wait_group 0;" ::: "memory")
#define CP_WAIT1()  asm volatile("cp.async.wait_group 1;" ::: "memory")

// ---------------- device scratch (no allocations allowed) ------------------
__device__ float g_A1[DIM * RANK];
__device__ float g_A2[DIM * RANK];
__device__ float g_qkv[HW * 3 * DIM];    // only Q columns (n<768) are written
__device__ float g_relh[NH * HW * GH];   // pre-scaled by LOG2E
__device__ float g_relw[NH * HW * GH];   // pre-scaled by LOG2E
// split-KV partials
__device__ __align__(16) float g_opart[KSPLIT * HW * DIM];
__device__ float g_lpart[KSPLIT * NH * HW];
// pre-split inputs / intermediates (fp16)
__device__ __align__(16) __half g_xh[HW * DIM];
__device__ __align__(16) __half g_xl[HW * DIM];
__device__ __align__(16) __half g_oph[HW * DIM];
__device__ __align__(16) __half g_opl[HW * DIM];
// transposed weights [N][K] fp16 (hi only)
__device__ __align__(16) __half g_wqkvT_h[3 * DIM * DIM];
__device__ __align__(16) __half g_wprojT_h[DIM * DIM];
// fp16 K [head][key][dim] and transposed V [head][dim][key]
__device__ __align__(16) __half g_kh[NH * HW * HD];
__device__ __align__(16) __half g_vh[NH * HD * HW];

// ---------------- K0: A1 = FacTu @ q_FacTs, A2 = FacTu @ v_FacTs -----------
__global__ void fact_small_kernel(const float* __restrict__ FacTu,
                                  const float* __restrict__ qF,
                                  const float* __restrict__ vF) {
    int idx = blockIdx.x * 256 + threadIdx.x;
    if (idx >= DIM * RANK * 2) return;
    int which = idx / (DIM * RANK);
    int rem = idx - which * (DIM * RANK);
    int i = rem / RANK, r = rem - (rem / RANK) * RANK;
    const float* F = which ? vF : qF;
    float s = 0.f;
#pragma unroll
    for (int k = 0; k < RANK; k++) s += FacTu[i * RANK + k] * F[k * RANK + r];
    (which ? g_A2 : g_A1)[i * RANK + r] = s;
}

// ---------------- K0b: split x into fp16 hi/lo ------------------------------
__global__ void __launch_bounds__(256) xsplit_kernel(const float* __restrict__ x) {
    int idx = blockIdx.x * 256 + threadIdx.x;
    if (idx >= HW * DIM / 4) return;
    float4 v = *(const float4*)&x[idx * 4];
    uint32_t h0, l0, h1, l1;
    split2h(v.x, v.y, h0, l0);
    split2h(v.z, v.w, h1, l1);
    *(uint2*)&g_xh[idx * 4] = make_uint2(h0, h1);
    *(uint2*)&g_xl[idx * 4] = make_uint2(l0, l1);
}

// ---------------- K1: transpose + low-rank fold + fp16 (hi only) -----------
__global__ void __launch_bounds__(256)
wsplit_kernel(const float* __restrict__ W, const float* __restrict__ FacTv,
              __half* __restrict__ WTh, int NJ, int mode) {
    __shared__ float tile[32 * 33];
    const int tid = threadIdx.x;
    const int j0 = blockIdx.x * 32;
    const int i0 = blockIdx.y * 32;

    {
        const int j = tid & 31;
        const int ib = tid >> 5;
        const float* Aarr = nullptr;
        int jj = j0 + j;
        if (mode) {
            if (jj < DIM) Aarr = g_A1;
            else if (jj >= 2 * DIM) { Aarr = g_A2; jj -= 2 * DIM; }
        }
#pragma unroll
        for (int it = 0; it < 4; it++) {
            int il = ib + it * 8;
            int i = i0 + il;
            float w = W[(size_t)i * NJ + j0 + j];
            if (Aarr) {
                float s = 0.f;
#pragma unroll
                for (int r = 0; r < RANK; r++)
                    s += Aarr[i * RANK + r] * FacTv[r * DIM + jj];
                w += FACT_S * s;
            }
            tile[il * 33 + j] = w;
        }
    }
    __syncthreads();
    {
        const int i = tid & 31;
        const int jb = tid >> 5;
#pragma unroll
        for (int it = 0; it < 4; it++) {
            int jl = jb + it * 8;
            WTh[(size_t)(j0 + jl) * DIM + i0 + i] = __float2half_rn(tile[i * 33 + jl]);
        }
    }
}

// ---------------- K2: HMMA GEMM fp16 2-pass (96x128, cp.async, 2 CTA/SM) ----
// mode 0: C[M][N] fp32 everywhere.
// mode 1 (qkv): n<DIM -> C fp32 (Q); DIM..2*DIM -> g_kh fp16; >=2*DIM -> g_vh fp16 (transposed).
#define GS 40                 // smem row stride in f16 (80B)
#define A_CH 384              // cp16 chunks per A array (96 rows * 4)
#define AARR 7680             // bytes per A array (96*80)
#define BARR 10240            // bytes per B array (128*80)
#define STG  25600            // bytes per stage (2*AARR + BARR)
__global__ void __launch_bounds__(256, 2)
hgemm_f16(const __half* __restrict__ Ah_,
          const __half* __restrict__ Al_,
          const __half* __restrict__ Bh_,
          const float* __restrict__ bias, float* __restrict__ C,
          int M, int N, int K, int mode) {
    extern __shared__ __align__(16) char gsm[];
    const uint32_t smb = smem_to_u32(gsm);
    const int tid = threadIdx.x, lane = tid & 31, warp = tid >> 5;
    const int wm = (warp >> 2) * 48, wn = (warp & 3) * 32;
    const int bm = blockIdx.y * 96, bn = blockIdx.x * 128;

#define GB_ISSUE(k0) do { \
        _Pragma("unroll") \
        for (int t = 0; t < 5; t++) { \
            int i = tid + t * 256; \
            const __half* gptr; uint32_t soff; int j, grow; \
            if (i < A_CH) { gptr = Ah_; soff = 0; j = i; grow = bm; } \
            else if (i < 2 * A_CH) { gptr = Al_; soff = AARR; j = i - A_CH; grow = bm; } \
            else { gptr = Bh_; soff = 2 * AARR; j = i - 2 * A_CH; grow = bn; } \
            int row = j >> 2, c = j & 3; \
            grow += row; \
            const char* src = (const char*)&gptr[(size_t)grow * K + (k0)] + c * 16; \
            cp16(sb + soff + row * 80 + c * 16, src); \
        } \
        CP_COMMIT(); \
    } while (0)

    float acc[3][4][4];
#pragma unroll
    for (int a = 0; a < 3; a++)
#pragma unroll
        for (int b = 0; b < 4; b++)
#pragma unroll
            for (int c = 0; c < 4; c++) acc[a][b][c] = 0.f;

    {
        uint32_t sb = smb;
        GB_ISSUE(0);
    }

    const uint32_t aoff = (uint32_t)((lane & 15) * GS + ((lane >> 4) << 3)) * 2;
    const uint32_t boff = (uint32_t)(((lane & 7) + ((lane & 16) >> 1)) * GS + (lane & 8)) * 2;

    const int NKT = K / 32;
    for (int kt = 0; kt < NKT; kt++) {
        CP_WAIT0();
        __syncthreads();
        if (kt + 1 < NKT) {
            uint32_t sb = smb + (uint32_t)((kt + 1) & 1) * STG;
            GB_ISSUE((kt + 1) * 32);
        }
        const uint32_t cb = smb + (uint32_t)(kt & 1) * STG;
        const uint32_t sAh = cb, sAl = cb + AARR, sBh = cb + 2 * AARR;

#pragma unroll
        for (int ks = 0; ks < 2; ks++) {
            uint32_t ah[3][4], al[3][4];
#pragma unroll
            for (int mt = 0; mt < 3; mt++) {
                uint32_t off = (uint32_t)(wm + mt * 16) * (GS * 2) + (uint32_t)ks * 32 + aoff;
                ldsm4(ah[mt], sAh + off);
                ldsm4(al[mt], sAl + off);
            }
            uint32_t bh[2][4];
#pragma unroll
            for (int nt = 0; nt < 2; nt++) {
                uint32_t off = (uint32_t)(wn + nt * 16) * (GS * 2) + (uint32_t)ks * 32 + boff;
                ldsm4(bh[nt], sBh + off);
            }
#pragma unroll
            for (int mt = 0; mt < 3; mt++)
#pragma unroll
                for (int nt = 0; nt < 4; nt++) {
                    uint32_t b0h = bh[nt >> 1][(nt & 1) * 2];
                    uint32_t b1h = bh[nt >> 1][(nt & 1) * 2 + 1];
                    mma16816(acc[mt][nt], ah[mt], b0h, b1h);
                    mma16816(acc[mt][nt], al[mt], b0h, b1h);
                }
        }
        __syncthreads();
    }

    const int gid = lane >> 2, tig = lane & 3;
    const int region = (mode == 1) ? (bn / DIM) : 0;   // 0:Q/fp32  1:K  2:V
#pragma unroll
    for (int mt = 0; mt < 3; mt++) {
        int m0 = bm + wm + mt * 16 + gid;
#pragma unroll
        for (int nt = 0; nt < 4; nt++) {
            int n0 = bn + wn + nt * 8 + 2 * tig;
            float bx = bias ? bias[n0] : 0.f;
            float by = bias ? bias[n0 + 1] : 0.f;
            float v00 = acc[mt][nt][0] + bx, v01 = acc[mt][nt][1] + by;
            float v10 = acc[mt][nt][2] + bx, v11 = acc[mt][nt][3] + by;
            if (region == 0) {
                *(float2*)&C[(size_t)m0 * N + n0] = make_float2(v00, v01);
                *(float2*)&C[(size_t)(m0 + 8) * N + n0] = make_float2(v10, v11);
            } else if (region == 1) {       // K: g_kh[head][key=m][d] (d,d+1 contiguous)
                int nn = n0 - DIM;
                int head = nn >> 6, d = nn & 63;
                *(uint32_t*)&g_kh[((size_t)head * HW + m0) * HD + d] = cvth2(v00, v01);
                *(uint32_t*)&g_kh[((size_t)head * HW + m0 + 8) * HD + d] = cvth2(v10, v11);
            } else {                        // V: g_vh[head][d][key=m]
                int nn = n0 - 2 * DIM;
                int head = nn >> 6, d = nn & 63;
                __half* vb = g_vh + (size_t)head * HD * HW;
                vb[(size_t)d * HW + m0]           = __float2half_rn(v00);
                vb[(size_t)(d + 1) * HW + m0]     = __float2half_rn(v01);
                vb[(size_t)d * HW + m0 + 8]       = __float2half_rn(v10);
                vb[(size_t)(d + 1) * HW + m0 + 8] = __float2half_rn(v11);
            }
        }
    }
}
#define HG_SMEM (2 * STG)

// ---------------- K3: rel bias tables (pre-scaled by LOG2E) -----------------
__global__ void __launch_bounds__(256) rel_tab2_kernel(const float* __restrict__ rph,
                                                       const float* __restrict__ rpw) {
    __shared__ float Qs[GH * 68];
    __shared__ float Rs[GH * 68];
    const int pos = blockIdx.x;
    const int head = blockIdx.y;
    const int which = blockIdx.z;
    const int tid = threadIdx.x;

    for (int i = tid; i < GH * HD; i += 256) {
        int r = i >> 6, c = i & 63;
        int t = which ? (r * GH + pos) : (pos * GH + r);
        Qs[r * 68 + c] = g_qkv[(size_t)t * (3 * DIM) + head * HD + c];
    }
    const float* rp = which ? rpw : rph;
    for (int i = tid; i < GH * HD; i += 256) {
        int k = i >> 6, c = i & 63;
        Rs[k * 68 + c] = rp[(pos - k + GH - 1) * HD + c];
    }
    __syncthreads();

    const int tx = tid & 15, ty = tid >> 4;
    u64 acc[3][3];
#pragma unroll
    for (int i = 0; i < 3; i++)
#pragma unroll
        for (int j = 0; j < 3; j++) acc[i][j] = 0ull;

    for (int c = 0; c < HD; c += 4) {
        ulonglong2 q[3], r[3];
#pragma unroll
        for (int i = 0; i < 3; i++) q[i] = *(const ulonglong2*)&Qs[(ty * 3 + i) * 68 + c];
#pragma unroll
        for (int j = 0; j < 3; j++) r[j] = *(const ulonglong2*)&Rs[(tx * 3 + j) * 68 + c];
#pragma unroll
        for (int i = 0; i < 3; i++)
#pragma unroll
            for (int j = 0; j < 3; j++) {
                ffma2(acc[i][j], q[i].x, r[j].x);
                ffma2(acc[i][j], q[i].y, r[j].y);
            }
    }

    float* outp = which ? g_relw : g_relh;
#pragma unroll
    for (int i = 0; i < 3; i++) {
        int row = ty * 3 + i;
        int t = which ? (row * GH + pos) : (pos * GH + row);
#pragma unroll
        for (int j = 0; j < 3; j++) {
            float lo, hi;
            unpack2f(acc[i][j], lo, hi);
            outp[((size_t)head * HW + t) * GH + tx * 3 + j] = (lo + hi) * LOG2E;
        }
    }
}

// ---------------- K4: pipelined split-KV fp16 2-pass flash attention --------
#define ROWB   144            // 72 f16 = 144 bytes per padded row
#define ARR_SZ (64 * ROWB)    // 9216
#define SB_V   ARR_SZ
#define BUF_SZ (2 * ARR_SZ)   // 18432 (K + V)
#define SM_RH  (4 * BUF_SZ)                 // 73728
#define SM_RW  (SM_RH + 128 * GH * 4)       // +24576
#define SM_TOT (SM_RW + 128 * GH * 4)       // 122880 (120KB) -> 1 CTA/SM

__device__ __forceinline__ void copy_kv_async(uint32_t dstb, int head, int kt0) {
    const int tid = threadIdx.x;   // 256 threads
    const char* khb = (const char*)(g_kh + ((size_t)head * HW + kt0) * HD);
#pragma unroll
    for (int it = 0; it < 2; it++) {
        int i = tid + it * 256;
        int r = i >> 3, c = i & 7;
        cp16(dstb + r * ROWB + c * 16, khb + i * 16);
    }
    const char* vhb = (const char*)(g_vh + (size_t)head * HD * HW + kt0);
#pragma unroll
    for (int it = 0; it < 2; it++) {
        int i = tid + it * 256;
        int dr = i >> 3, c = i & 7;
        cp16(dstb + SB_V + dr * ROWB + c * 16, vhb + (size_t)dr * (HW * 2) + c * 16);
    }
    CP_COMMIT();
}

__device__ __forceinline__ void s_mma_tile(float S[8][4], uint32_t kb,
                                           const uint32_t qhi[4][4],
                                           const uint32_t qlo[4][4],
                                           uint32_t lm4off) {
#pragma unroll
    for (int j = 0; j < 8; j++) {
#pragma unroll
        for (int i = 0; i < 4; i++) S[j][i] = 0.f;
        uint32_t base = kb + (uint32_t)j * (8 * ROWB) + lm4off;
#pragma unroll
        for (int s = 0; s < 4; s += 2) {
            uint32_t bh[4];
            ldsm4(bh, base + s * 32);
            mma16816(S[j], qhi[s], bh[0], bh[1]);
            mma16816(S[j], qlo[s], bh[0], bh[1]);
            mma16816(S[j], qhi[s + 1], bh[2], bh[3]);
            mma16816(S[j], qlo[s + 1], bh[2], bh[3]);
        }
    }
}

__global__ void __launch_bounds__(256) attn_mma_kernel() {
    extern __shared__ char smc[];
    const uint32_t smb = smem_to_u32(smc);
    const int tid = threadIdx.x, lane = tid & 31, warp = tid >> 5;   // 8 warps
    const int gid = lane >> 2, tig = lane & 3;
    const int head = blockIdx.y;
    const int qt0 = blockIdx.x * 128;
    const int zs = blockIdx.z;
    const int T0 = zs * NTT;

    copy_kv_async(smb, head, T0 * 64);
    copy_kv_async(smb + BUF_SZ, head, (T0 + 1) * 64);
    copy_kv_async(smb + 2 * BUF_SZ, head, (T0 + 2) * 64);

    float* Rh = (float*)(smc + SM_RH);
    float* Rw = (float*)(smc + SM_RW);
    {
        const float4* sH = (const float4*)&g_relh[((size_t)head * HW + qt0) * GH];
        const float4* sW = (const float4*)&g_relw[((size_t)head * HW + qt0) * GH];
        float4* dH = (float4*)Rh;
        float4* dW = (float4*)Rw;
        for (int i = tid; i < 128 * GH / 4; i += 256) { dH[i] = sH[i]; dW[i] = sW[i]; }
    }

    uint32_t qhi[4][4], qlo[4][4];
    {
        const float* q0 = &g_qkv[(size_t)(qt0 + warp * 16 + gid) * (3 * DIM) + head * HD];
        const float* q1 = q0 + (size_t)8 * (3 * DIM);
#pragma unroll
        for (int s = 0; s < 4; s++) {
            int c = 16 * s + 2 * tig;
            float2 v;
            v = *(const float2*)&q0[c];
            split2h(QSCL * v.x, QSCL * v.y, qhi[s][0], qlo[s][0]);
            v = *(const float2*)&q1[c];
            split2h(QSCL * v.x, QSCL * v.y, qhi[s][1], qlo[s][1]);
            v = *(const float2*)&q0[c + 8];
            split2h(QSCL * v.x, QSCL * v.y, qhi[s][2], qlo[s][2]);
            v = *(const float2*)&q1[c + 8];
            split2h(QSCL * v.x, QSCL * v.y, qhi[s][3], qlo[s][3]);
        }
    }

    const uint32_t lm4off = (uint32_t)((lane & 7) * ROWB + (lane >> 3) * 16);

    CP_WAIT1();            // bufs 0,1 locally complete (buf2 in flight)
    __syncthreads();       // bufs 0,1 + Rh/Rw visible to all warps

    float Scur[8][4], Snext[8][4];
    s_mma_tile(Scur, smb, qhi, qlo, lm4off);

    float Oacc[8][4];
#pragma unroll
    for (int j = 0; j < 8; j++)
#pragma unroll
        for (int i = 0; i < 4; i++) Oacc[j][i] = 0.f;
    float rs0 = 0.f, rs1 = 0.f;

    const float* rh0 = &Rh[(warp * 16 + gid) * GH];
    const float* rh1 = rh0 + 8 * GH;
    const float* rw0 = &Rw[(warp * 16 + gid) * GH];
    const float* rw1 = rw0 + 8 * GH;

    for (int tt = 0; tt < NTT; tt++) {
        const int kt0 = (T0 + tt) * 64;
        __syncthreads();   // buf(tt+1) visible; buf((tt-1)&3) free for reuse
        if (tt + 3 < NTT)
            copy_kv_async(smb + (uint32_t)((tt + 3) & 3) * BUF_SZ, head, (T0 + tt + 3) * 64);
        if (tt + 1 < NTT)
            s_mma_tile(Snext, smb + (uint32_t)((tt + 1) & 3) * BUF_SZ, qhi, qlo, lm4off);

        // softmax on Scur: hk takes exactly 2 values per tile
        {
            const int hkA = kt0 / GH;
            const int kbd = (hkA + 1) * GH;
            const int sub0 = hkA * GH, sub1 = sub0 + GH;
            const float rhA0 = rh0[hkA], rhB0 = rh0[hkA + 1];
            const float rhA1 = rh1[hkA], rhB1 = rh1[hkA + 1];
#pragma unroll
            for (int j = 0; j < 8; j++) {
                int k0 = kt0 + 8 * j + 2 * tig;
                int k1 = k0 + 1;
                bool c0 = k0 < kbd, c1 = k1 < kbd;
                int wk0 = k0 - (c0 ? sub0 : sub1);
                int wk1 = k1 - (c1 ? sub0 : sub1);
                float b00 = (c0 ? rhA0 : rhB0) + rw0[wk0];
                float b01 = (c1 ? rhA0 : rhB0) + rw0[wk1];
                float b10 = (c0 ? rhA1 : rhB1) + rw1[wk0];
                float b11 = (c1 ? rhA1 : rhB1) + rw1[wk1];
                float e0 = ex2f(Scur[j][0] + b00);
                float e1 = ex2f(Scur[j][1] + b01);
                float e2 = ex2f(Scur[j][2] + b10);
                float e3 = ex2f(Scur[j][3] + b11);
                rs0 += e0 + e1;
                rs1 += e2 + e3;
                Scur[j][0] = e0; Scur[j][1] = e1; Scur[j][2] = e2; Scur[j][3] = e3;
            }
        }

        uint32_t phi[4][4], plo[4][4];
#pragma unroll
        for (int s = 0; s < 4; s++) {
            split2h(Scur[2 * s][0],     Scur[2 * s][1],     phi[s][0], plo[s][0]);
            split2h(Scur[2 * s][2],     Scur[2 * s][3],     phi[s][1], plo[s][1]);
            split2h(Scur[2 * s + 1][0], Scur[2 * s + 1][1], phi[s][2], plo[s][2]);
            split2h(Scur[2 * s + 1][2], Scur[2 * s + 1][3], phi[s][3], plo[s][3]);
        }

        const uint32_t vb = smb + (uint32_t)(tt & 3) * BUF_SZ + SB_V;
#pragma unroll
        for (int j = 0; j < 8; j++) {
            uint32_t base = vb + (uint32_t)j * (8 * ROWB) + lm4off;
#pragma unroll
            for (int s = 0; s < 4; s += 2) {
                uint32_t vh[4];
                ldsm4(vh, base + s * 32);
                mma16816(Oacc[j], phi[s], vh[0], vh[1]);
                mma16816(Oacc[j], plo[s], vh[0], vh[1]);
                mma16816(Oacc[j], phi[s + 1], vh[2], vh[3]);
                mma16816(Oacc[j], plo[s + 1], vh[2], vh[3]);
            }
        }

        if (tt + 3 < NTT) { CP_WAIT1(); } else { CP_WAIT0(); }   // buf(tt+2) locally done

        if (tt + 1 < NTT) {
#pragma unroll
            for (int j = 0; j < 8; j++)
#pragma unroll
                for (int i = 0; i < 4; i++) Scur[j][i] = Snext[j][i];
        }
    }

    // partial row-sums + unnormalized partial O to gmem
    rs0 += __shfl_xor_sync(0xffffffffu, rs0, 1);
    rs0 += __shfl_xor_sync(0xffffffffu, rs0, 2);
    rs1 += __shfl_xor_sync(0xffffffffu, rs1, 1);
    rs1 += __shfl_xor_sync(0xffffffffu, rs1, 2);

    const int row0 = qt0 + warp * 16 + gid;
    if (tig == 0) {
        g_lpart[(size_t)zs * NH * HW + (size_t)head * HW + row0] = rs0;
        g_lpart[(size_t)zs * NH * HW + (size_t)head * HW + row0 + 8] = rs1;
    }
    float* op = g_opart + (size_t)zs * HW * DIM;
    const size_t r0 = (size_t)row0 * DIM + head * HD;
    const size_t r1 = r0 + (size_t)8 * DIM;
#pragma unroll
    for (int j = 0; j < 8; j++) {
        int c = 8 * j + 2 * tig;
        *(float2*)&op[r0 + c] = make_float2(Oacc[j][0], Oacc[j][1]);
        *(float2*)&op[r1 + c] = make_float2(Oacc[j][2], Oacc[j][3]);
    }
}

// ---------------- K4b: combine split-KV partials -> fp16 hi/lo --------------
__global__ void __launch_bounds__(256) combine_kernel() {
    int idx = blockIdx.x * 256 + threadIdx.x;   // 2 cols per thread
    if (idx >= HW * DIM / 2) return;
    int row = idx / (DIM / 2);
    int cc = (idx - row * (DIM / 2)) * 2;
    int head = cc >> 6;
    float l = g_lpart[(size_t)head * HW + row]
            + g_lpart[(size_t)NH * HW + (size_t)head * HW + row];
    float inv = 1.f / l;
    size_t o = (size_t)row * DIM + cc;
    float2 o0 = *(const float2*)&g_opart[o];
    float2 o1 = *(const float2*)&g_opart[(size_t)HW * DIM + o];
    uint32_t h, lo;
    split2h((o0.x + o1.x) * inv, (o0.y + o1.y) * inv, h, lo);
    *(uint32_t*)&g_oph[o] = h;
    *(uint32_t*)&g_opl[o] = lo;
}

// ---------------- launch -----------------------------------------------------
extern "C" void kernel_launch(void* const* d_in, const int* in_sizes, int n_in,
                              void* d_out, int out_size) {
    const float* x     = (const float*)d_in[0];
    const float* Wqkv  = (const float*)d_in[1];
    const float* bqkv  = (const float*)d_in[2];
    const float* FacTu = (const float*)d_in[3];
    const float* FacTv = (const float*)d_in[4];
    const float* qF    = (const float*)d_in[5];
    const float* vF    = (const float*)d_in[6];
    const float* rph   = (const float*)d_in[7];
    const float* rpw   = (const float*)d_in[8];
    const float* Wproj = (const float*)d_in[9];
    const float* bproj = (const float*)d_in[10];
    float* out = (float*)d_out;

    void *pQkv, *pXh, *pXl, *pOph, *pOpl, *pWqT_h, *pWpT_h;
    cudaGetSymbolAddress(&pQkv, g_qkv);
    cudaGetSymbolAddress(&pXh, g_xh);
    cudaGetSymbolAddress(&pXl, g_xl);
    cudaGetSymbolAddress(&pOph, g_oph);
    cudaGetSymbolAddress(&pOpl, g_opl);
    cudaGetSymbolAddress(&pWqT_h, g_wqkvT_h);
    cudaGetSymbolAddress(&pWpT_h, g_wprojT_h);

    cudaFuncSetAttribute(attn_mma_kernel,
                         cudaFuncAttributeMaxDynamicSharedMemorySize, (int)SM_TOT);
    cudaFuncSetAttribute(hgemm_f16,
                         cudaFuncAttributeMaxDynamicSharedMemorySize, (int)HG_SMEM);

    fact_small_kernel<<<(DIM * RANK * 2 + 255) / 256, 256>>>(FacTu, qF, vF);
    xsplit_kernel<<<(HW * DIM / 4 + 255) / 256, 256>>>(x);

    {   // Wqkv (+delta) -> transposed fp16
        dim3 grid((3 * DIM) / 32, DIM / 32);
        wsplit_kernel<<<grid, 256>>>(Wqkv, FacTv, (__half*)pWqT_h, 3 * DIM, 1);
    }
    {   // Wproj -> transposed fp16
        dim3 grid(DIM / 32, DIM / 32);
        wsplit_kernel<<<grid, 256>>>(Wproj, FacTv, (__half*)pWpT_h, DIM, 0);
    }
    {   // qkv GEMM, fused K/V fp16 epilogue (mode 1)
        dim3 grid((3 * DIM) / 128, HW / 96);
        hgemm_f16<<<grid, 256, HG_SMEM>>>((const __half*)pXh, (const __half*)pXl,
                                          (const __half*)pWqT_h,
                                          bqkv, (float*)pQkv, HW, 3 * DIM, DIM, 1);
    }
    {   // rel-pos tables (pre-scaled by log2e)
        dim3 grid(GH, NH, 2);
        rel_tab2_kernel<<<grid, 256>>>(rph, rpw);
    }
    {   // pipelined split-KV fp16 2-pass attention
        dim3 grid(HW / 128, NH, KSPLIT);
        attn_mma_kernel<<<grid, 256, SM_TOT>>>();
    }
    {   // combine partials
        combine_kernel<<<(HW * DIM / 2 + 255) / 256, 256>>>();
    }
    {   // out = opre @ Wproj + bproj (mode 0)
        dim3 grid(DIM / 128, HW / 96);
        hgemm_f16<<<grid, 256, HG_SMEM>>>((const __half*)pOph, (const __half*)pOpl,
                                          (const __half*)pWpT_h,
                                          bproj, out, HW, DIM, DIM, 0);
    }
}

// round 14
// speedup vs baseline: 2.0177x; 1.1998x over previous
#include <cuda_runtime.h>
#include <cuda_fp16.h>
#include <cstdint>

#define DIM   768
#define NH    12
#define HD    64
#define GH    48           // grid H = W
#define HW    2304         // 48*48
#define RANK  32
#define QK_SCALE 0.125f    // 64^-0.5
#define LOG2E 1.4426950408889634f
#define QSCL (QK_SCALE * LOG2E)
#define FACT_S 1.0f
#define NT    36           // kv tiles of 64
#define KSPLIT 2
#define NTT   (NT / KSPLIT)  // 18 tiles per split

typedef unsigned long long u64;

// ---------------- packed helpers --------------------------------------------
__device__ __forceinline__ void unpack2f(u64 v, float& a, float& b) {
    unsigned x, y;
    asm("mov.b64 {%0, %1}, %2;" : "=r"(x), "=r"(y) : "l"(v));
    a = __uint_as_float(x);
    b = __uint_as_float(y);
}
__device__ __forceinline__ void ffma2(u64& d, u64 a, u64 b) {
    asm("fma.rn.f32x2 %0, %1, %2, %0;" : "+l"(d) : "l"(a), "l"(b));
}
// fp16x2 pack (a in low half)
__device__ __forceinline__ uint32_t cvth2(float a, float b) {
    uint32_t h;
    asm("cvt.rn.f16x2.f32 %0, %1, %2;" : "=r"(h) : "f"(b), "f"(a));
    return h;
}
// fp16 split: hi = f16x2(a,b), lo = f16x2 of residuals
__device__ __forceinline__ void split2h(float a, float b, uint32_t& hi, uint32_t& lo) {
    uint32_t h = cvth2(a, b);
    float ra, rb;
    asm("{\n\t.reg .f16 x, y;\n\tmov.b32 {x, y}, %2;\n\t"
        "cvt.f32.f16 %0, x;\n\tcvt.f32.f16 %1, y;\n\t}"
        : "=f"(ra), "=f"(rb) : "r"(h));
    hi = h;
    lo = cvth2(a - ra, b - rb);
}
__device__ __forceinline__ float ex2f(float x) {
    float y;
    asm("ex2.approx.f32 %0, %1;" : "=f"(y) : "f"(x));
    return y;
}

// ---------------- mma / ldmatrix / cp.async helpers --------------------------
__device__ __forceinline__ void mma16816(float c[4], const uint32_t a[4],
                                         uint32_t b0, uint32_t b1) {
    asm volatile(
        "mma.sync.aligned.m16n8k16.row.col.f32.f16.f16.f32 "
        "{%0,%1,%2,%3}, {%4,%5,%6,%7}, {%8,%9}, {%0,%1,%2,%3};"
        : "+f"(c[0]), "+f"(c[1]), "+f"(c[2]), "+f"(c[3])
        : "r"(a[0]), "r"(a[1]), "r"(a[2]), "r"(a[3]), "r"(b0), "r"(b1));
}
__device__ __forceinline__ void ldsm4(uint32_t r[4], uint32_t addr) {
    asm volatile("ldmatrix.sync.aligned.m8n8.x4.shared.b16 {%0,%1,%2,%3}, [%4];"
                 : "=r"(r[0]), "=r"(r[1]), "=r"(r[2]), "=r"(r[3]) : "r"(addr));
}
__device__ __forceinline__ uint32_t smem_to_u32(const void* smem_ptr) {
    uint32_t addr;
    asm("{ .reg .u64 tmp; cvta.to.shared.u64 tmp, %1; cvt.u32.u64 %0, tmp; }"
        : "=r"(addr) : "l"(smem_ptr));
    return addr;
}
__device__ __forceinline__ void cp16(uint32_t dst, const void* src) {
    asm volatile("cp.async.cg.shared.global [%0], [%1], 16;"
                 :: "r"(dst), "l"(src));
}
#define CP_COMMIT() asm volatile("cp.async.commit_group;" ::: "memory")
#define CP_WAIT0()  asm volatile("cp.async.wait_group 0;" ::: "memory")
#define CP_WAIT1()  asm volatile("cp.async.wait_group 1;" ::: "memory")

// ---------------- device scratch (no allocations allowed) ------------------
__device__ float g_A1[DIM * RANK];
__device__ float g_A2[DIM * RANK];
__device__ float g_qkv[HW * 3 * DIM];    // only Q columns (n<768) are written
__device__ float g_relh[NH * HW * GH];   // pre-scaled by LOG2E
__device__ float g_relw[NH * HW * GH];   // pre-scaled by LOG2E
// split-KV partials
__device__ __align__(16) float g_opart[KSPLIT * HW * DIM];
__device__ float g_lpart[KSPLIT * NH * HW];
// pre-split inputs / intermediates (fp16)
__device__ __align__(16) __half g_xh[HW * DIM];
__device__ __align__(16) __half g_xl[HW * DIM];
__device__ __align__(16) __half g_oph[HW * DIM];
__device__ __align__(16) __half g_opl[HW * DIM];
// transposed weights [N][K] fp16 (hi only)
__device__ __align__(16) __half g_wqkvT_h[3 * DIM * DIM];
__device__ __align__(16) __half g_wprojT_h[DIM * DIM];
// fp16 K [head][key][dim] and transposed V [head][dim][key]
__device__ __align__(16) __half g_kh[NH * HW * HD];
__device__ __align__(16) __half g_vh[NH * HD * HW];

// ---------------- K0: A1 = FacTu @ q_FacTs, A2 = FacTu @ v_FacTs -----------
__global__ void fact_small_kernel(const float* __restrict__ FacTu,
                                  const float* __restrict__ qF,
                                  const float* __restrict__ vF) {
    int idx = blockIdx.x * 256 + threadIdx.x;
    if (idx >= DIM * RANK * 2) return;
    int which = idx / (DIM * RANK);
    int rem = idx - which * (DIM * RANK);
    int i = rem / RANK, r = rem - (rem / RANK) * RANK;
    const float* F = which ? vF : qF;
    float s = 0.f;
#pragma unroll
    for (int k = 0; k < RANK; k++) s += FacTu[i * RANK + k] * F[k * RANK + r];
    (which ? g_A2 : g_A1)[i * RANK + r] = s;
}

// ---------------- K0b: split x into fp16 hi/lo ------------------------------
__global__ void __launch_bounds__(256) xsplit_kernel(const float* __restrict__ x) {
    int idx = blockIdx.x * 256 + threadIdx.x;
    if (idx >= HW * DIM / 4) return;
    float4 v = *(const float4*)&x[idx * 4];
    uint32_t h0, l0, h1, l1;
    split2h(v.x, v.y, h0, l0);
    split2h(v.z, v.w, h1, l1);
    *(uint2*)&g_xh[idx * 4] = make_uint2(h0, h1);
    *(uint2*)&g_xl[idx * 4] = make_uint2(l0, l1);
}

// ---------------- K1: transpose + low-rank fold + fp16 (hi only) -----------
__global__ void __launch_bounds__(256)
wsplit_kernel(const float* __restrict__ W, const float* __restrict__ FacTv,
              __half* __restrict__ WTh, int NJ, int mode) {
    __shared__ float tile[32 * 33];
    const int tid = threadIdx.x;
    const int j0 = blockIdx.x * 32;
    const int i0 = blockIdx.y * 32;

    {
        const int j = tid & 31;
        const int ib = tid >> 5;
        const float* Aarr = nullptr;
        int jj = j0 + j;
        if (mode) {
            if (jj < DIM) Aarr = g_A1;
            else if (jj >= 2 * DIM) { Aarr = g_A2; jj -= 2 * DIM; }
        }
#pragma unroll
        for (int it = 0; it < 4; it++) {
            int il = ib + it * 8;
            int i = i0 + il;
            float w = W[(size_t)i * NJ + j0 + j];
            if (Aarr) {
                float s = 0.f;
#pragma unroll
                for (int r = 0; r < RANK; r++)
                    s += Aarr[i * RANK + r] * FacTv[r * DIM + jj];
                w += FACT_S * s;
            }
            tile[il * 33 + j] = w;
        }
    }
    __syncthreads();
    {
        const int i = tid & 31;
        const int jb = tid >> 5;
#pragma unroll
        for (int it = 0; it < 4; it++) {
            int jl = jb + it * 8;
            WTh[(size_t)(j0 + jl) * DIM + i0 + i] = __float2half_rn(tile[i * 33 + jl]);
        }
    }
}

// ---------------- K2: HMMA GEMM fp16 2-pass (96x128, cp.async, 2 CTA/SM) ----
#define GS 40                 // smem row stride in f16 (80B)
#define A_CH 384              // cp16 chunks per A array (96 rows * 4)
#define AARR 7680             // bytes per A array (96*80)
#define BARR 10240            // bytes per B array (128*80)
#define STG  25600            // bytes per stage (2*AARR + BARR)
__global__ void __launch_bounds__(256, 2)
hgemm_f16(const __half* __restrict__ Ah_,
          const __half* __restrict__ Al_,
          const __half* __restrict__ Bh_,
          const float* __restrict__ bias, float* __restrict__ C,
          int M, int N, int K, int mode) {
    extern __shared__ __align__(16) char gsm[];
    const uint32_t smb = smem_to_u32(gsm);
    const int tid = threadIdx.x, lane = tid & 31, warp = tid >> 5;
    const int wm = (warp >> 2) * 48, wn = (warp & 3) * 32;
    const int bm = blockIdx.y * 96, bn = blockIdx.x * 128;

#define GB_ISSUE(k0) do { \
        _Pragma("unroll") \
        for (int t = 0; t < 5; t++) { \
            int i = tid + t * 256; \
            const __half* gptr; uint32_t soff; int j, grow; \
            if (i < A_CH) { gptr = Ah_; soff = 0; j = i; grow = bm; } \
            else if (i < 2 * A_CH) { gptr = Al_; soff = AARR; j = i - A_CH; grow = bm; } \
            else { gptr = Bh_; soff = 2 * AARR; j = i - 2 * A_CH; grow = bn; } \
            int row = j >> 2, c = j & 3; \
            grow += row; \
            const char* src = (const char*)&gptr[(size_t)grow * K + (k0)] + c * 16; \
            cp16(sb + soff + row * 80 + c * 16, src); \
        } \
        CP_COMMIT(); \
    } while (0)

    float acc[3][4][4];
#pragma unroll
    for (int a = 0; a < 3; a++)
#pragma unroll
        for (int b = 0; b < 4; b++)
#pragma unroll
            for (int c = 0; c < 4; c++) acc[a][b][c] = 0.f;

    {
        uint32_t sb = smb;
        GB_ISSUE(0);
    }

    const uint32_t aoff = (uint32_t)((lane & 15) * GS + ((lane >> 4) << 3)) * 2;
    const uint32_t boff = (uint32_t)(((lane & 7) + ((lane & 16) >> 1)) * GS + (lane & 8)) * 2;

    const int NKT = K / 32;
    for (int kt = 0; kt < NKT; kt++) {
        CP_WAIT0();
        __syncthreads();
        if (kt + 1 < NKT) {
            uint32_t sb = smb + (uint32_t)((kt + 1) & 1) * STG;
            GB_ISSUE((kt + 1) * 32);
        }
        const uint32_t cb = smb + (uint32_t)(kt & 1) * STG;
        const uint32_t sAh = cb, sAl = cb + AARR, sBh = cb + 2 * AARR;

#pragma unroll
        for (int ks = 0; ks < 2; ks++) {
            uint32_t ah[3][4], al[3][4];
#pragma unroll
            for (int mt = 0; mt < 3; mt++) {
                uint32_t off = (uint32_t)(wm + mt * 16) * (GS * 2) + (uint32_t)ks * 32 + aoff;
                ldsm4(ah[mt], sAh + off);
                ldsm4(al[mt], sAl + off);
            }
            uint32_t bh[2][4];
#pragma unroll
            for (int nt = 0; nt < 2; nt++) {
                uint32_t off = (uint32_t)(wn + nt * 16) * (GS * 2) + (uint32_t)ks * 32 + boff;
                ldsm4(bh[nt], sBh + off);
            }
#pragma unroll
            for (int mt = 0; mt < 3; mt++)
#pragma unroll
                for (int nt = 0; nt < 4; nt++) {
                    uint32_t b0h = bh[nt >> 1][(nt & 1) * 2];
                    uint32_t b1h = bh[nt >> 1][(nt & 1) * 2 + 1];
                    mma16816(acc[mt][nt], ah[mt], b0h, b1h);
                    mma16816(acc[mt][nt], al[mt], b0h, b1h);
                }
        }
        __syncthreads();
    }

    const int gid = lane >> 2, tig = lane & 3;
    const int region = (mode == 1) ? (bn / DIM) : 0;   // 0:Q/fp32  1:K  2:V
#pragma unroll
    for (int mt = 0; mt < 3; mt++) {
        int m0 = bm + wm + mt * 16 + gid;
#pragma unroll
        for (int nt = 0; nt < 4; nt++) {
            int n0 = bn + wn + nt * 8 + 2 * tig;
            float bx = bias ? bias[n0] : 0.f;
            float by = bias ? bias[n0 + 1] : 0.f;
            float v00 = acc[mt][nt][0] + bx, v01 = acc[mt][nt][1] + by;
            float v10 = acc[mt][nt][2] + bx, v11 = acc[mt][nt][3] + by;
            if (region == 0) {
                *(float2*)&C[(size_t)m0 * N + n0] = make_float2(v00, v01);
                *(float2*)&C[(size_t)(m0 + 8) * N + n0] = make_float2(v10, v11);
            } else if (region == 1) {       // K: g_kh[head][key=m][d]
                int nn = n0 - DIM;
                int head = nn >> 6, d = nn & 63;
                *(uint32_t*)&g_kh[((size_t)head * HW + m0) * HD + d] = cvth2(v00, v01);
                *(uint32_t*)&g_kh[((size_t)head * HW + m0 + 8) * HD + d] = cvth2(v10, v11);
            } else {                        // V: g_vh[head][d][key=m]
                int nn = n0 - 2 * DIM;
                int head = nn >> 6, d = nn & 63;
                __half* vb = g_vh + (size_t)head * HD * HW;
                vb[(size_t)d * HW + m0]           = __float2half_rn(v00);
                vb[(size_t)(d + 1) * HW + m0]     = __float2half_rn(v01);
                vb[(size_t)d * HW + m0 + 8]       = __float2half_rn(v10);
                vb[(size_t)(d + 1) * HW + m0 + 8] = __float2half_rn(v11);
            }
        }
    }
}
#define HG_SMEM (2 * STG)

// ---------------- K3: rel bias tables (pre-scaled by LOG2E) -----------------
__global__ void __launch_bounds__(256) rel_tab2_kernel(const float* __restrict__ rph,
                                                       const float* __restrict__ rpw) {
    __shared__ float Qs[GH * 68];
    __shared__ float Rs[GH * 68];
    const int pos = blockIdx.x;
    const int head = blockIdx.y;
    const int which = blockIdx.z;
    const int tid = threadIdx.x;

    for (int i = tid; i < GH * HD; i += 256) {
        int r = i >> 6, c = i & 63;
        int t = which ? (r * GH + pos) : (pos * GH + r);
        Qs[r * 68 + c] = g_qkv[(size_t)t * (3 * DIM) + head * HD + c];
    }
    const float* rp = which ? rpw : rph;
    for (int i = tid; i < GH * HD; i += 256) {
        int k = i >> 6, c = i & 63;
        Rs[k * 68 + c] = rp[(pos - k + GH - 1) * HD + c];
    }
    __syncthreads();

    const int tx = tid & 15, ty = tid >> 4;
    u64 acc[3][3];
#pragma unroll
    for (int i = 0; i < 3; i++)
#pragma unroll
        for (int j = 0; j < 3; j++) acc[i][j] = 0ull;

    for (int c = 0; c < HD; c += 4) {
        ulonglong2 q[3], r[3];
#pragma unroll
        for (int i = 0; i < 3; i++) q[i] = *(const ulonglong2*)&Qs[(ty * 3 + i) * 68 + c];
#pragma unroll
        for (int j = 0; j < 3; j++) r[j] = *(const ulonglong2*)&Rs[(tx * 3 + j) * 68 + c];
#pragma unroll
        for (int i = 0; i < 3; i++)
#pragma unroll
            for (int j = 0; j < 3; j++) {
                ffma2(acc[i][j], q[i].x, r[j].x);
                ffma2(acc[i][j], q[i].y, r[j].y);
            }
    }

    float* outp = which ? g_relw : g_relh;
#pragma unroll
    for (int i = 0; i < 3; i++) {
        int row = ty * 3 + i;
        int t = which ? (row * GH + pos) : (pos * GH + row);
#pragma unroll
        for (int j = 0; j < 3; j++) {
            float lo, hi;
            unpack2f(acc[i][j], lo, hi);
            outp[((size_t)head * HW + t) * GH + tx * 3 + j] = (lo + hi) * LOG2E;
        }
    }
}

// ---------------- K4: pipelined split-KV fp16 single-pass flash attention ---
#define ROWB   144            // 72 f16 = 144 bytes per padded row
#define ARR_SZ (64 * ROWB)    // 9216
#define SB_V   ARR_SZ
#define BUF_SZ (2 * ARR_SZ)   // 18432 (K + V)
#define SM_RH  (4 * BUF_SZ)                 // 73728
#define SM_RW  (SM_RH + 128 * GH * 4)       // +24576
#define SM_TOT (SM_RW + 128 * GH * 4)       // 122880 (120KB) -> 1 CTA/SM

__device__ __forceinline__ void copy_kv_async(uint32_t dstb, int head, int kt0) {
    const int tid = threadIdx.x;   // 256 threads
    const char* khb = (const char*)(g_kh + ((size_t)head * HW + kt0) * HD);
#pragma unroll
    for (int it = 0; it < 2; it++) {
        int i = tid + it * 256;
        int r = i >> 3, c = i & 7;
        cp16(dstb + r * ROWB + c * 16, khb + i * 16);
    }
    const char* vhb = (const char*)(g_vh + (size_t)head * HD * HW + kt0);
#pragma unroll
    for (int it = 0; it < 2; it++) {
        int i = tid + it * 256;
        int dr = i >> 3, c = i & 7;
        cp16(dstb + SB_V + dr * ROWB + c * 16, vhb + (size_t)dr * (HW * 2) + c * 16);
    }
    CP_COMMIT();
}

__device__ __forceinline__ void s_mma_tile(float S[8][4], uint32_t kb,
                                           const uint32_t qhi[4][4],
                                           uint32_t lm4off) {
#pragma unroll
    for (int j = 0; j < 8; j++) {
#pragma unroll
        for (int i = 0; i < 4; i++) S[j][i] = 0.f;
        uint32_t base = kb + (uint32_t)j * (8 * ROWB) + lm4off;
#pragma unroll
        for (int s = 0; s < 4; s += 2) {
            uint32_t bh[4];
            ldsm4(bh, base + s * 32);
            mma16816(S[j], qhi[s], bh[0], bh[1]);
            mma16816(S[j], qhi[s + 1], bh[2], bh[3]);
        }
    }
}

__global__ void __launch_bounds__(256) attn_mma_kernel() {
    extern __shared__ char smc[];
    const uint32_t smb = smem_to_u32(smc);
    const int tid = threadIdx.x, lane = tid & 31, warp = tid >> 5;   // 8 warps
    const int gid = lane >> 2, tig = lane & 3;
    const int head = blockIdx.y;
    const int qt0 = blockIdx.x * 128;
    const int zs = blockIdx.z;
    const int T0 = zs * NTT;

    copy_kv_async(smb, head, T0 * 64);
    copy_kv_async(smb + BUF_SZ, head, (T0 + 1) * 64);
    copy_kv_async(smb + 2 * BUF_SZ, head, (T0 + 2) * 64);

    float* Rh = (float*)(smc + SM_RH);
    float* Rw = (float*)(smc + SM_RW);
    {
        const float4* sH = (const float4*)&g_relh[((size_t)head * HW + qt0) * GH];
        const float4* sW = (const float4*)&g_relw[((size_t)head * HW + qt0) * GH];
        float4* dH = (float4*)Rh;
        float4* dW = (float4*)Rw;
        for (int i = tid; i < 128 * GH / 4; i += 256) { dH[i] = sH[i]; dW[i] = sW[i]; }
    }

    uint32_t qhi[4][4];
    {
        const float* q0 = &g_qkv[(size_t)(qt0 + warp * 16 + gid) * (3 * DIM) + head * HD];
        const float* q1 = q0 + (size_t)8 * (3 * DIM);
#pragma unroll
        for (int s = 0; s < 4; s++) {
            int c = 16 * s + 2 * tig;
            float2 v;
            v = *(const float2*)&q0[c];
            qhi[s][0] = cvth2(QSCL * v.x, QSCL * v.y);
            v = *(const float2*)&q1[c];
            qhi[s][1] = cvth2(QSCL * v.x, QSCL * v.y);
            v = *(const float2*)&q0[c + 8];
            qhi[s][2] = cvth2(QSCL * v.x, QSCL * v.y);
            v = *(const float2*)&q1[c + 8];
            qhi[s][3] = cvth2(QSCL * v.x, QSCL * v.y);
        }
    }

    const uint32_t lm4off = (uint32_t)((lane & 7) * ROWB + (lane >> 3) * 16);

    CP_WAIT1();            // bufs 0,1 locally complete (buf2 in flight)
    __syncthreads();       // bufs 0,1 + Rh/Rw visible to all warps

    float Scur[8][4], Snext[8][4];
    s_mma_tile(Scur, smb, qhi, lm4off);

    float Oacc[8][4];
#pragma unroll
    for (int j = 0; j < 8; j++)
#pragma unroll
        for (int i = 0; i < 4; i++) Oacc[j][i] = 0.f;
    float rs0 = 0.f, rs1 = 0.f;

    const float* rh0 = &Rh[(warp * 16 + gid) * GH];
    const float* rh1 = rh0 + 8 * GH;
    const float* rw0 = &Rw[(warp * 16 + gid) * GH];
    const float* rw1 = rw0 + 8 * GH;

    for (int tt = 0; tt < NTT; tt++) {
        const int kt0 = (T0 + tt) * 64;
        __syncthreads();   // buf(tt+1) visible; buf((tt-1)&3) free for reuse
        if (tt + 3 < NTT)
            copy_kv_async(smb + (uint32_t)((tt + 3) & 3) * BUF_SZ, head, (T0 + tt + 3) * 64);
        if (tt + 1 < NTT)
            s_mma_tile(Snext, smb + (uint32_t)((tt + 1) & 3) * BUF_SZ, qhi, lm4off);

        // softmax on Scur: hk takes exactly 2 values per tile
        {
            const int hkA = kt0 / GH;
            const int kbd = (hkA + 1) * GH;
            const int sub0 = hkA * GH, sub1 = sub0 + GH;
            const float rhA0 = rh0[hkA], rhB0 = rh0[hkA + 1];
            const float rhA1 = rh1[hkA], rhB1 = rh1[hkA + 1];
#pragma unroll
            for (int j = 0; j < 8; j++) {
                int k0 = kt0 + 8 * j + 2 * tig;
                int k1 = k0 + 1;
                bool c0 = k0 < kbd, c1 = k1 < kbd;
                int wk0 = k0 - (c0 ? sub0 : sub1);
                int wk1 = k1 - (c1 ? sub0 : sub1);
                float b00 = (c0 ? rhA0 : rhB0) + rw0[wk0];
                float b01 = (c1 ? rhA0 : rhB0) + rw0[wk1];
                float b10 = (c0 ? rhA1 : rhB1) + rw1[wk0];
                float b11 = (c1 ? rhA1 : rhB1) + rw1[wk1];
                float e0 = ex2f(Scur[j][0] + b00);
                float e1 = ex2f(Scur[j][1] + b01);
                float e2 = ex2f(Scur[j][2] + b10);
                float e3 = ex2f(Scur[j][3] + b11);
                rs0 += e0 + e1;
                rs1 += e2 + e3;
                Scur[j][0] = e0; Scur[j][1] = e1; Scur[j][2] = e2; Scur[j][3] = e3;
            }
        }

        uint32_t phi[4][4];
#pragma unroll
        for (int s = 0; s < 4; s++) {
            phi[s][0] = cvth2(Scur[2 * s][0],     Scur[2 * s][1]);
            phi[s][1] = cvth2(Scur[2 * s][2],     Scur[2 * s][3]);
            phi[s][2] = cvth2(Scur[2 * s + 1][0], Scur[2 * s + 1][1]);
            phi[s][3] = cvth2(Scur[2 * s + 1][2], Scur[2 * s + 1][3]);
        }

        const uint32_t vb = smb + (uint32_t)(tt & 3) * BUF_SZ + SB_V;
#pragma unroll
        for (int j = 0; j < 8; j++) {
            uint32_t base = vb + (uint32_t)j * (8 * ROWB) + lm4off;
#pragma unroll
            for (int s = 0; s < 4; s += 2) {
                uint32_t vh[4];
                ldsm4(vh, base + s * 32);
                mma16816(Oacc[j], phi[s], vh[0], vh[1]);
                mma16816(Oacc[j], phi[s + 1], vh[2], vh[3]);
            }
        }

        if (tt + 3 < NTT) { CP_WAIT1(); } else { CP_WAIT0(); }   // buf(tt+2) locally done

        if (tt + 1 < NTT) {
#pragma unroll
            for (int j = 0; j < 8; j++)
#pragma unroll
                for (int i = 0; i < 4; i++) Scur[j][i] = Snext[j][i];
        }
    }

    // partial row-sums + unnormalized partial O to gmem
    rs0 += __shfl_xor_sync(0xffffffffu, rs0, 1);
    rs0 += __shfl_xor_sync(0xffffffffu, rs0, 2);
    rs1 += __shfl_xor_sync(0xffffffffu, rs1, 1);
    rs1 += __shfl_xor_sync(0xffffffffu, rs1, 2);

    const int row0 = qt0 + warp * 16 + gid;
    if (tig == 0) {
        g_lpart[(size_t)zs * NH * HW + (size_t)head * HW + row0] = rs0;
        g_lpart[(size_t)zs * NH * HW + (size_t)head * HW + row0 + 8] = rs1;
    }
    float* op = g_opart + (size_t)zs * HW * DIM;
    const size_t r0 = (size_t)row0 * DIM + head * HD;
    const size_t r1 = r0 + (size_t)8 * DIM;
#pragma unroll
    for (int j = 0; j < 8; j++) {
        int c = 8 * j + 2 * tig;
        *(float2*)&op[r0 + c] = make_float2(Oacc[j][0], Oacc[j][1]);
        *(float2*)&op[r1 + c] = make_float2(Oacc[j][2], Oacc[j][3]);
    }
}

// ---------------- K4b: combine split-KV partials -> fp16 hi/lo --------------
__global__ void __launch_bounds__(256) combine_kernel() {
    int idx = blockIdx.x * 256 + threadIdx.x;   // 2 cols per thread
    if (idx >= HW * DIM / 2) return;
    int row = idx / (DIM / 2);
    int cc = (idx - row * (DIM / 2)) * 2;
    int head = cc >> 6;
    float l = g_lpart[(size_t)head * HW + row]
            + g_lpart[(size_t)NH * HW + (size_t)head * HW + row];
    float inv = 1.f / l;
    size_t o = (size_t)row * DIM + cc;
    float2 o0 = *(const float2*)&g_opart[o];
    float2 o1 = *(const float2*)&g_opart[(size_t)HW * DIM + o];
    uint32_t h, lo;
    split2h((o0.x + o1.x) * inv, (o0.y + o1.y) * inv, h, lo);
    *(uint32_t*)&g_oph[o] = h;
    *(uint32_t*)&g_opl[o] = lo;
}

// ---------------- launch -----------------------------------------------------
extern "C" void kernel_launch(void* const* d_in, const int* in_sizes, int n_in,
                              void* d_out, int out_size) {
    const float* x     = (const float*)d_in[0];
    const float* Wqkv  = (const float*)d_in[1];
    const float* bqkv  = (const float*)d_in[2];
    const float* FacTu = (const float*)d_in[3];
    const float* FacTv = (const float*)d_in[4];
    const float* qF    = (const float*)d_in[5];
    const float* vF    = (const float*)d_in[6];
    const float* rph   = (const float*)d_in[7];
    const float* rpw   = (const float*)d_in[8];
    const float* Wproj = (const float*)d_in[9];
    const float* bproj = (const float*)d_in[10];
    float* out = (float*)d_out;

    void *pQkv, *pXh, *pXl, *pOph, *pOpl, *pWqT_h, *pWpT_h;
    cudaGetSymbolAddress(&pQkv, g_qkv);
    cudaGetSymbolAddress(&pXh, g_xh);
    cudaGetSymbolAddress(&pXl, g_xl);
    cudaGetSymbolAddress(&pOph, g_oph);
    cudaGetSymbolAddress(&pOpl, g_opl);
    cudaGetSymbolAddress(&pWqT_h, g_wqkvT_h);
    cudaGetSymbolAddress(&pWpT_h, g_wprojT_h);

    cudaFuncSetAttribute(attn_mma_kernel,
                         cudaFuncAttributeMaxDynamicSharedMemorySize, (int)SM_TOT);
    cudaFuncSetAttribute(hgemm_f16,
                         cudaFuncAttributeMaxDynamicSharedMemorySize, (int)HG_SMEM);

    fact_small_kernel<<<(DIM * RANK * 2 + 255) / 256, 256>>>(FacTu, qF, vF);
    xsplit_kernel<<<(HW * DIM / 4 + 255) / 256, 256>>>(x);

    {   // Wqkv (+delta) -> transposed fp16
        dim3 grid((3 * DIM) / 32, DIM / 32);
        wsplit_kernel<<<grid, 256>>>(Wqkv, FacTv, (__half*)pWqT_h, 3 * DIM, 1);
    }
    {   // Wproj -> transposed fp16
        dim3 grid(DIM / 32, DIM / 32);
        wsplit_kernel<<<grid, 256>>>(Wproj, FacTv, (__half*)pWpT_h, DIM, 0);
    }
    {   // qkv GEMM, fused K/V fp16 epilogue (mode 1)
        dim3 grid((3 * DIM) / 128, HW / 96);
        hgemm_f16<<<grid, 256, HG_SMEM>>>((const __half*)pXh, (const __half*)pXl,
                                          (const __half*)pWqT_h,
                                          bqkv, (float*)pQkv, HW, 3 * DIM, DIM, 1);
    }
    {   // rel-pos tables (pre-scaled by log2e)
        dim3 grid(GH, NH, 2);
        rel_tab2_kernel<<<grid, 256>>>(rph, rpw);
    }
    {   // pipelined split-KV fp16 single-pass attention
        dim3 grid(HW / 128, NH, KSPLIT);
        attn_mma_kernel<<<grid, 256, SM_TOT>>>();
    }
    {   // combine partials
        combine_kernel<<<(HW * DIM / 2 + 255) / 256, 256>>>();
    }
    {   // out = opre @ Wproj + bproj (mode 0)
        dim3 grid(DIM / 128, HW / 96);
        hgemm_f16<<<grid, 256, HG_SMEM>>>((const __half*)pOph, (const __half*)pOpl,
                                          (const __half*)pWpT_h,
                                          bproj, out, HW, DIM, DIM, 0);
    }
}

// round 15
// speedup vs baseline: 2.0365x; 1.0093x over previous
#include <cuda_runtime.h>
#include <cuda_fp16.h>
#include <cstdint>

#define DIM   768
#define NH    12
#define HD    64
#define GH    48           // grid H = W
#define HW    2304         // 48*48
#define RANK  32
#define QK_SCALE 0.125f    // 64^-0.5
#define LOG2E 1.4426950408889634f
#define QSCL (QK_SCALE * LOG2E)
#define FACT_S 1.0f
#define NT    36           // kv tiles of 64
#define KSPLIT 2
#define NTT   (NT / KSPLIT)  // 18 tiles per split

typedef unsigned long long u64;

// ---------------- packed helpers --------------------------------------------
__device__ __forceinline__ void unpack2f(u64 v, float& a, float& b) {
    unsigned x, y;
    asm("mov.b64 {%0, %1}, %2;" : "=r"(x), "=r"(y) : "l"(v));
    a = __uint_as_float(x);
    b = __uint_as_float(y);
}
__device__ __forceinline__ void ffma2(u64& d, u64 a, u64 b) {
    asm("fma.rn.f32x2 %0, %1, %2, %0;" : "+l"(d) : "l"(a), "l"(b));
}
// fp16x2 pack (a in low half)
__device__ __forceinline__ uint32_t cvth2(float a, float b) {
    uint32_t h;
    asm("cvt.rn.f16x2.f32 %0, %1, %2;" : "=r"(h) : "f"(b), "f"(a));
    return h;
}
// fp16 split: hi = f16x2(a,b), lo = f16x2 of residuals
__device__ __forceinline__ void split2h(float a, float b, uint32_t& hi, uint32_t& lo) {
    uint32_t h = cvth2(a, b);
    float ra, rb;
    asm("{\n\t.reg .f16 x, y;\n\tmov.b32 {x, y}, %2;\n\t"
        "cvt.f32.f16 %0, x;\n\tcvt.f32.f16 %1, y;\n\t}"
        : "=f"(ra), "=f"(rb) : "r"(h));
    hi = h;
    lo = cvth2(a - ra, b - rb);
}
// packed fp16 exp2
__device__ __forceinline__ uint32_t ex2h2(uint32_t x) {
    uint32_t y;
    asm("ex2.approx.f16x2 %0, %1;" : "=r"(y) : "r"(x));
    return y;
}
__device__ __forceinline__ float2 h2f2(uint32_t h) {
    float a, b;
    asm("{\n\t.reg .f16 x, y;\n\tmov.b32 {x, y}, %2;\n\t"
        "cvt.f32.f16 %0, x;\n\tcvt.f32.f16 %1, y;\n\t}"
        : "=f"(a), "=f"(b) : "r"(h));
    return make_float2(a, b);
}

// ---------------- mma / ldmatrix / cp.async helpers --------------------------
__device__ __forceinline__ void mma16816(float c[4], const uint32_t a[4],
                                         uint32_t b0, uint32_t b1) {
    asm volatile(
        "mma.sync.aligned.m16n8k16.row.col.f32.f16.f16.f32 "
        "{%0,%1,%2,%3}, {%4,%5,%6,%7}, {%8,%9}, {%0,%1,%2,%3};"
        : "+f"(c[0]), "+f"(c[1]), "+f"(c[2]), "+f"(c[3])
        : "r"(a[0]), "r"(a[1]), "r"(a[2]), "r"(a[3]), "r"(b0), "r"(b1));
}
__device__ __forceinline__ void ldsm4(uint32_t r[4], uint32_t addr) {
    asm volatile("ldmatrix.sync.aligned.m8n8.x4.shared.b16 {%0,%1,%2,%3}, [%4];"
                 : "=r"(r[0]), "=r"(r[1]), "=r"(r[2]), "=r"(r[3]) : "r"(addr));
}
__device__ __forceinline__ uint32_t smem_to_u32(const void* smem_ptr) {
    uint32_t addr;
    asm("{ .reg .u64 tmp; cvta.to.shared.u64 tmp, %1; cvt.u32.u64 %0, tmp; }"
        : "=r"(addr) : "l"(smem_ptr));
    return addr;
}
__device__ __forceinline__ void cp16(uint32_t dst, const void* src) {
    asm volatile("cp.async.cg.shared.global [%0], [%1], 16;"
                 :: "r"(dst), "l"(src));
}
#define CP_COMMIT() asm volatile("cp.async.commit_group;" ::: "memory")
#define CP_WAIT0()  asm volatile("cp.async.wait_group 0;" ::: "memory")
#define CP_WAIT1()  asm volatile("cp.async.wait_group 1;" ::: "memory")

// ---------------- device scratch (no allocations allowed) ------------------
__device__ float g_A1[DIM * RANK];
__device__ float g_A2[DIM * RANK];
__device__ float g_qkv[HW * 3 * DIM];    // only Q columns (n<768) are written
__device__ float g_relh[NH * HW * GH];   // pre-scaled by LOG2E
__device__ float g_relw[NH * HW * GH];   // pre-scaled by LOG2E
// split-KV partials
__device__ __align__(16) float g_opart[KSPLIT * HW * DIM];
__device__ float g_lpart[KSPLIT * NH * HW];
// pre-split inputs / intermediates (fp16)
__device__ __align__(16) __half g_xh[HW * DIM];
__device__ __align__(16) __half g_xl[HW * DIM];
__device__ __align__(16) __half g_oph[HW * DIM];
__device__ __align__(16) __half g_opl[HW * DIM];
// transposed weights [N][K] fp16 (hi only)
__device__ __align__(16) __half g_wqkvT_h[3 * DIM * DIM];
__device__ __align__(16) __half g_wprojT_h[DIM * DIM];
// fp16 K [head][key][dim] and transposed V [head][dim][key]
__device__ __align__(16) __half g_kh[NH * HW * HD];
__device__ __align__(16) __half g_vh[NH * HD * HW];

// ---------------- K0: A1 = FacTu @ q_FacTs, A2 = FacTu @ v_FacTs -----------
__global__ void fact_small_kernel(const float* __restrict__ FacTu,
                                  const float* __restrict__ qF,
                                  const float* __restrict__ vF) {
    int idx = blockIdx.x * 256 + threadIdx.x;
    if (idx >= DIM * RANK * 2) return;
    int which = idx / (DIM * RANK);
    int rem = idx - which * (DIM * RANK);
    int i = rem / RANK, r = rem - (rem / RANK) * RANK;
    const float* F = which ? vF : qF;
    float s = 0.f;
#pragma unroll
    for (int k = 0; k < RANK; k++) s += FacTu[i * RANK + k] * F[k * RANK + r];
    (which ? g_A2 : g_A1)[i * RANK + r] = s;
}

// ---------------- K0b: split x into fp16 hi/lo ------------------------------
__global__ void __launch_bounds__(256) xsplit_kernel(const float* __restrict__ x) {
    int idx = blockIdx.x * 256 + threadIdx.x;
    if (idx >= HW * DIM / 4) return;
    float4 v = *(const float4*)&x[idx * 4];
    uint32_t h0, l0, h1, l1;
    split2h(v.x, v.y, h0, l0);
    split2h(v.z, v.w, h1, l1);
    *(uint2*)&g_xh[idx * 4] = make_uint2(h0, h1);
    *(uint2*)&g_xl[idx * 4] = make_uint2(l0, l1);
}

// ---------------- K1: transpose + low-rank fold + fp16 (hi only) -----------
__global__ void __launch_bounds__(256)
wsplit_kernel(const float* __restrict__ W, const float* __restrict__ FacTv,
              __half* __restrict__ WTh, int NJ, int mode) {
    __shared__ float tile[32 * 33];
    const int tid = threadIdx.x;
    const int j0 = blockIdx.x * 32;
    const int i0 = blockIdx.y * 32;

    {
        const int j = tid & 31;
        const int ib = tid >> 5;
        const float* Aarr = nullptr;
        int jj = j0 + j;
        if (mode) {
            if (jj < DIM) Aarr = g_A1;
            else if (jj >= 2 * DIM) { Aarr = g_A2; jj -= 2 * DIM; }
        }
#pragma unroll
        for (int it = 0; it < 4; it++) {
            int il = ib + it * 8;
            int i = i0 + il;
            float w = W[(size_t)i * NJ + j0 + j];
            if (Aarr) {
                float s = 0.f;
#pragma unroll
                for (int r = 0; r < RANK; r++)
                    s += Aarr[i * RANK + r] * FacTv[r * DIM + jj];
                w += FACT_S * s;
            }
            tile[il * 33 + j] = w;
        }
    }
    __syncthreads();
    {
        const int i = tid & 31;
        const int jb = tid >> 5;
#pragma unroll
        for (int it = 0; it < 4; it++) {
            int jl = jb + it * 8;
            WTh[(size_t)(j0 + jl) * DIM + i0 + i] = __float2half_rn(tile[i * 33 + jl]);
        }
    }
}

// ---------------- K2: HMMA GEMM fp16 2-pass (96x128, cp.async, 2 CTA/SM) ----
#define GS 40                 // smem row stride in f16 (80B)
#define A_CH 384              // cp16 chunks per A array (96 rows * 4)
#define AARR 7680             // bytes per A array (96*80)
#define BARR 10240            // bytes per B array (128*80)
#define STG  25600            // bytes per stage (2*AARR + BARR)
__global__ void __launch_bounds__(256, 2)
hgemm_f16(const __half* __restrict__ Ah_,
          const __half* __restrict__ Al_,
          const __half* __restrict__ Bh_,
          const float* __restrict__ bias, float* __restrict__ C,
          int M, int N, int K, int mode) {
    extern __shared__ __align__(16) char gsm[];
    const uint32_t smb = smem_to_u32(gsm);
    const int tid = threadIdx.x, lane = tid & 31, warp = tid >> 5;
    const int wm = (warp >> 2) * 48, wn = (warp & 3) * 32;
    const int bm = blockIdx.y * 96, bn = blockIdx.x * 128;

#define GB_ISSUE(k0) do { \
        _Pragma("unroll") \
        for (int t = 0; t < 5; t++) { \
            int i = tid + t * 256; \
            const __half* gptr; uint32_t soff; int j, grow; \
            if (i < A_CH) { gptr = Ah_; soff = 0; j = i; grow = bm; } \
            else if (i < 2 * A_CH) { gptr = Al_; soff = AARR; j = i - A_CH; grow = bm; } \
            else { gptr = Bh_; soff = 2 * AARR; j = i - 2 * A_CH; grow = bn; } \
            int row = j >> 2, c = j & 3; \
            grow += row; \
            const char* src = (const char*)&gptr[(size_t)grow * K + (k0)] + c * 16; \
            cp16(sb + soff + row * 80 + c * 16, src); \
        } \
        CP_COMMIT(); \
    } while (0)

    float acc[3][4][4];
#pragma unroll
    for (int a = 0; a < 3; a++)
#pragma unroll
        for (int b = 0; b < 4; b++)
#pragma unroll
            for (int c = 0; c < 4; c++) acc[a][b][c] = 0.f;

    {
        uint32_t sb = smb;
        GB_ISSUE(0);
    }

    const uint32_t aoff = (uint32_t)((lane & 15) * GS + ((lane >> 4) << 3)) * 2;
    const uint32_t boff = (uint32_t)(((lane & 7) + ((lane & 16) >> 1)) * GS + (lane & 8)) * 2;

    const int NKT = K / 32;
    for (int kt = 0; kt < NKT; kt++) {
        CP_WAIT0();
        __syncthreads();
        if (kt + 1 < NKT) {
            uint32_t sb = smb + (uint32_t)((kt + 1) & 1) * STG;
            GB_ISSUE((kt + 1) * 32);
        }
        const uint32_t cb = smb + (uint32_t)(kt & 1) * STG;
        const uint32_t sAh = cb, sAl = cb + AARR, sBh = cb + 2 * AARR;

#pragma unroll
        for (int ks = 0; ks < 2; ks++) {
            uint32_t ah[3][4], al[3][4];
#pragma unroll
            for (int mt = 0; mt < 3; mt++) {
                uint32_t off = (uint32_t)(wm + mt * 16) * (GS * 2) + (uint32_t)ks * 32 + aoff;
                ldsm4(ah[mt], sAh + off);
                ldsm4(al[mt], sAl + off);
            }
            uint32_t bh[2][4];
#pragma unroll
            for (int nt = 0; nt < 2; nt++) {
                uint32_t off = (uint32_t)(wn + nt * 16) * (GS * 2) + (uint32_t)ks * 32 + boff;
                ldsm4(bh[nt], sBh + off);
            }
#pragma unroll
            for (int mt = 0; mt < 3; mt++)
#pragma unroll
                for (int nt = 0; nt < 4; nt++) {
                    uint32_t b0h = bh[nt >> 1][(nt & 1) * 2];
                    uint32_t b1h = bh[nt >> 1][(nt & 1) * 2 + 1];
                    mma16816(acc[mt][nt], ah[mt], b0h, b1h);
                    mma16816(acc[mt][nt], al[mt], b0h, b1h);
                }
        }
        __syncthreads();
    }

    const int gid = lane >> 2, tig = lane & 3;
    const int region = (mode == 1) ? (bn / DIM) : 0;   // 0:Q/fp32  1:K  2:V
#pragma unroll
    for (int mt = 0; mt < 3; mt++) {
        int m0 = bm + wm + mt * 16 + gid;
#pragma unroll
        for (int nt = 0; nt < 4; nt++) {
            int n0 = bn + wn + nt * 8 + 2 * tig;
            float bx = bias ? bias[n0] : 0.f;
            float by = bias ? bias[n0 + 1] : 0.f;
            float v00 = acc[mt][nt][0] + bx, v01 = acc[mt][nt][1] + by;
            float v10 = acc[mt][nt][2] + bx, v11 = acc[mt][nt][3] + by;
            if (region == 0) {
                *(float2*)&C[(size_t)m0 * N + n0] = make_float2(v00, v01);
                *(float2*)&C[(size_t)(m0 + 8) * N + n0] = make_float2(v10, v11);
            } else if (region == 1) {       // K: g_kh[head][key=m][d]
                int nn = n0 - DIM;
                int head = nn >> 6, d = nn & 63;
                *(uint32_t*)&g_kh[((size_t)head * HW + m0) * HD + d] = cvth2(v00, v01);
                *(uint32_t*)&g_kh[((size_t)head * HW + m0 + 8) * HD + d] = cvth2(v10, v11);
            } else {                        // V: g_vh[head][d][key=m]
                int nn = n0 - 2 * DIM;
                int head = nn >> 6, d = nn & 63;
                __half* vb = g_vh + (size_t)head * HD * HW;
                vb[(size_t)d * HW + m0]           = __float2half_rn(v00);
                vb[(size_t)(d + 1) * HW + m0]     = __float2half_rn(v01);
                vb[(size_t)d * HW + m0 + 8]       = __float2half_rn(v10);
                vb[(size_t)(d + 1) * HW + m0 + 8] = __float2half_rn(v11);
            }
        }
    }
}
#define HG_SMEM (2 * STG)

// ---------------- K3: rel bias tables (pre-scaled by LOG2E) -----------------
__global__ void __launch_bounds__(256) rel_tab2_kernel(const float* __restrict__ rph,
                                                       const float* __restrict__ rpw) {
    __shared__ float Qs[GH * 68];
    __shared__ float Rs[GH * 68];
    const int pos = blockIdx.x;
    const int head = blockIdx.y;
    const int which = blockIdx.z;
    const int tid = threadIdx.x;

    for (int i = tid; i < GH * HD; i += 256) {
        int r = i >> 6, c = i & 63;
        int t = which ? (r * GH + pos) : (pos * GH + r);
        Qs[r * 68 + c] = g_qkv[(size_t)t * (3 * DIM) + head * HD + c];
    }
    const float* rp = which ? rpw : rph;
    for (int i = tid; i < GH * HD; i += 256) {
        int k = i >> 6, c = i & 63;
        Rs[k * 68 + c] = rp[(pos - k + GH - 1) * HD + c];
    }
    __syncthreads();

    const int tx = tid & 15, ty = tid >> 4;
    u64 acc[3][3];
#pragma unroll
    for (int i = 0; i < 3; i++)
#pragma unroll
        for (int j = 0; j < 3; j++) acc[i][j] = 0ull;

    for (int c = 0; c < HD; c += 4) {
        ulonglong2 q[3], r[3];
#pragma unroll
        for (int i = 0; i < 3; i++) q[i] = *(const ulonglong2*)&Qs[(ty * 3 + i) * 68 + c];
#pragma unroll
        for (int j = 0; j < 3; j++) r[j] = *(const ulonglong2*)&Rs[(tx * 3 + j) * 68 + c];
#pragma unroll
        for (int i = 0; i < 3; i++)
#pragma unroll
            for (int j = 0; j < 3; j++) {
                ffma2(acc[i][j], q[i].x, r[j].x);
                ffma2(acc[i][j], q[i].y, r[j].y);
            }
    }

    float* outp = which ? g_relw : g_relh;
#pragma unroll
    for (int i = 0; i < 3; i++) {
        int row = ty * 3 + i;
        int t = which ? (row * GH + pos) : (pos * GH + row);
#pragma unroll
        for (int j = 0; j < 3; j++) {
            float lo, hi;
            unpack2f(acc[i][j], lo, hi);
            outp[((size_t)head * HW + t) * GH + tx * 3 + j] = (lo + hi) * LOG2E;
        }
    }
}

// ---------------- K4: pipelined split-KV fp16 single-pass flash attention ---
#define ROWB   144            // 72 f16 = 144 bytes per padded row
#define ARR_SZ (64 * ROWB)    // 9216
#define SB_V   ARR_SZ
#define BUF_SZ (2 * ARR_SZ)   // 18432 (K + V)
#define SM_RH  (4 * BUF_SZ)                 // 73728
#define SM_RW  (SM_RH + 128 * GH * 4)       // +24576
#define SM_TOT (SM_RW + 128 * GH * 4)       // 122880 (120KB) -> 1 CTA/SM

__device__ __forceinline__ void copy_kv_async(uint32_t dstb, int head, int kt0) {
    const int tid = threadIdx.x;   // 256 threads
    const char* khb = (const char*)(g_kh + ((size_t)head * HW + kt0) * HD);
#pragma unroll
    for (int it = 0; it < 2; it++) {
        int i = tid + it * 256;
        int r = i >> 3, c = i & 7;
        cp16(dstb + r * ROWB + c * 16, khb + i * 16);
    }
    const char* vhb = (const char*)(g_vh + (size_t)head * HD * HW + kt0);
#pragma unroll
    for (int it = 0; it < 2; it++) {
        int i = tid + it * 256;
        int dr = i >> 3, c = i & 7;
        cp16(dstb + SB_V + dr * ROWB + c * 16, vhb + (size_t)dr * (HW * 2) + c * 16);
    }
    CP_COMMIT();
}

__device__ __forceinline__ void s_mma_tile(float S[8][4], uint32_t kb,
                                           const uint32_t qhi[4][4],
                                           uint32_t lm4off) {
#pragma unroll
    for (int j = 0; j < 8; j++) {
#pragma unroll
        for (int i = 0; i < 4; i++) S[j][i] = 0.f;
        uint32_t base = kb + (uint32_t)j * (8 * ROWB) + lm4off;
#pragma unroll
        for (int s = 0; s < 4; s += 2) {
            uint32_t bh[4];
            ldsm4(bh, base + s * 32);
            mma16816(S[j], qhi[s], bh[0], bh[1]);
            mma16816(S[j], qhi[s + 1], bh[2], bh[3]);
        }
    }
}

// one attention tile: consume SC, prefetch SN, softmax (f16x2 exp), PV
__device__ __forceinline__ void tile_body(
    int tt, int T0, int head, float SC[8][4], float SN[8][4],
    const uint32_t qhi[4][4], uint32_t lm4off, uint32_t smb,
    const float* rh0, const float* rh1, const float* rw0, const float* rw1,
    int tig, float& rs0, float& rs1, float Oacc[8][4]) {
    const int kt0 = (T0 + tt) * 64;
    __syncthreads();   // buf(tt+1) visible; buf((tt-1)&3) free for reuse
    if (tt + 3 < NTT)
        copy_kv_async(smb + (uint32_t)((tt + 3) & 3) * BUF_SZ, head, (T0 + tt + 3) * 64);
    if (tt + 1 < NTT)
        s_mma_tile(SN, smb + (uint32_t)((tt + 1) & 3) * BUF_SZ, qhi, lm4off);

    // softmax on SC via packed fp16 ex2; phi produced directly
    uint32_t phi[4][4];
    {
        const int hkA = kt0 / GH;
        const int kbd = (hkA + 1) * GH;
        const int sub0 = hkA * GH, sub1 = sub0 + GH;
        const float rhA0 = rh0[hkA], rhB0 = rh0[hkA + 1];
        const float rhA1 = rh1[hkA], rhB1 = rh1[hkA + 1];
#pragma unroll
        for (int j = 0; j < 8; j++) {
            int k0 = kt0 + 8 * j + 2 * tig;
            int k1 = k0 + 1;
            bool c0 = k0 < kbd, c1 = k1 < kbd;
            int wk0 = k0 - (c0 ? sub0 : sub1);
            int wk1 = k1 - (c1 ? sub0 : sub1);
            float b00 = (c0 ? rhA0 : rhB0) + rw0[wk0];
            float b01 = (c1 ? rhA0 : rhB0) + rw0[wk1];
            float b10 = (c0 ? rhA1 : rhB1) + rw1[wk0];
            float b11 = (c1 ? rhA1 : rhB1) + rw1[wk1];
            uint32_t ea = ex2h2(cvth2(SC[j][0] + b00, SC[j][1] + b01));
            uint32_t eb = ex2h2(cvth2(SC[j][2] + b10, SC[j][3] + b11));
            float2 fa = h2f2(ea), fb = h2f2(eb);
            rs0 += fa.x + fa.y;
            rs1 += fb.x + fb.y;
            phi[j >> 1][(j & 1) * 2 + 0] = ea;
            phi[j >> 1][(j & 1) * 2 + 1] = eb;
        }
    }

    const uint32_t vb = smb + (uint32_t)(tt & 3) * BUF_SZ + SB_V;
#pragma unroll
    for (int j = 0; j < 8; j++) {
        uint32_t base = vb + (uint32_t)j * (8 * ROWB) + lm4off;
#pragma unroll
        for (int s = 0; s < 4; s += 2) {
            uint32_t vh[4];
            ldsm4(vh, base + s * 32);
            mma16816(Oacc[j], phi[s], vh[0], vh[1]);
            mma16816(Oacc[j], phi[s + 1], vh[2], vh[3]);
        }
    }

    if (tt + 3 < NTT) { CP_WAIT1(); } else { CP_WAIT0(); }   // buf(tt+2) locally done
}

__global__ void __launch_bounds__(256) attn_mma_kernel() {
    extern __shared__ char smc[];
    const uint32_t smb = smem_to_u32(smc);
    const int tid = threadIdx.x, lane = tid & 31, warp = tid >> 5;   // 8 warps
    const int gid = lane >> 2, tig = lane & 3;
    const int head = blockIdx.y;
    const int qt0 = blockIdx.x * 128;
    const int zs = blockIdx.z;
    const int T0 = zs * NTT;

    copy_kv_async(smb, head, T0 * 64);
    copy_kv_async(smb + BUF_SZ, head, (T0 + 1) * 64);
    copy_kv_async(smb + 2 * BUF_SZ, head, (T0 + 2) * 64);

    float* Rh = (float*)(smc + SM_RH);
    float* Rw = (float*)(smc + SM_RW);
    {
        const float4* sH = (const float4*)&g_relh[((size_t)head * HW + qt0) * GH];
        const float4* sW = (const float4*)&g_relw[((size_t)head * HW + qt0) * GH];
        float4* dH = (float4*)Rh;
        float4* dW = (float4*)Rw;
        for (int i = tid; i < 128 * GH / 4; i += 256) { dH[i] = sH[i]; dW[i] = sW[i]; }
    }

    uint32_t qhi[4][4];
    {
        const float* q0 = &g_qkv[(size_t)(qt0 + warp * 16 + gid) * (3 * DIM) + head * HD];
        const float* q1 = q0 + (size_t)8 * (3 * DIM);
#pragma unroll
        for (int s = 0; s < 4; s++) {
            int c = 16 * s + 2 * tig;
            float2 v;
            v = *(const float2*)&q0[c];
            qhi[s][0] = cvth2(QSCL * v.x, QSCL * v.y);
            v = *(const float2*)&q1[c];
            qhi[s][1] = cvth2(QSCL * v.x, QSCL * v.y);
            v = *(const float2*)&q0[c + 8];
            qhi[s][2] = cvth2(QSCL * v.x, QSCL * v.y);
            v = *(const float2*)&q1[c + 8];
            qhi[s][3] = cvth2(QSCL * v.x, QSCL * v.y);
        }
    }

    const uint32_t lm4off = (uint32_t)((lane & 7) * ROWB + (lane >> 3) * 16);

    CP_WAIT1();            // bufs 0,1 locally complete (buf2 in flight)
    __syncthreads();       // bufs 0,1 + Rh/Rw visible to all warps

    float Sa[8][4], Sb[8][4];
    s_mma_tile(Sa, smb, qhi, lm4off);

    float Oacc[8][4];
#pragma unroll
    for (int j = 0; j < 8; j++)
#pragma unroll
        for (int i = 0; i < 4; i++) Oacc[j][i] = 0.f;
    float rs0 = 0.f, rs1 = 0.f;

    const float* rh0 = &Rh[(warp * 16 + gid) * GH];
    const float* rh1 = rh0 + 8 * GH;
    const float* rw0 = &Rw[(warp * 16 + gid) * GH];
    const float* rw1 = rw0 + 8 * GH;

    // NTT even: unroll by 2 with role-swapped S buffers (no register copies)
    for (int tt = 0; tt < NTT; tt += 2) {
        tile_body(tt,     T0, head, Sa, Sb, qhi, lm4off, smb,
                  rh0, rh1, rw0, rw1, tig, rs0, rs1, Oacc);
        tile_body(tt + 1, T0, head, Sb, Sa, qhi, lm4off, smb,
                  rh0, rh1, rw0, rw1, tig, rs0, rs1, Oacc);
    }

    // partial row-sums + unnormalized partial O to gmem
    rs0 += __shfl_xor_sync(0xffffffffu, rs0, 1);
    rs0 += __shfl_xor_sync(0xffffffffu, rs0, 2);
    rs1 += __shfl_xor_sync(0xffffffffu, rs1, 1);
    rs1 += __shfl_xor_sync(0xffffffffu, rs1, 2);

    const int row0 = qt0 + warp * 16 + gid;
    if (tig == 0) {
        g_lpart[(size_t)zs * NH * HW + (size_t)head * HW + row0] = rs0;
        g_lpart[(size_t)zs * NH * HW + (size_t)head * HW + row0 + 8] = rs1;
    }
    float* op = g_opart + (size_t)zs * HW * DIM;
    const size_t r0 = (size_t)row0 * DIM + head * HD;
    const size_t r1 = r0 + (size_t)8 * DIM;
#pragma unroll
    for (int j = 0; j < 8; j++) {
        int c = 8 * j + 2 * tig;
        *(float2*)&op[r0 + c] = make_float2(Oacc[j][0], Oacc[j][1]);
        *(float2*)&op[r1 + c] = make_float2(Oacc[j][2], Oacc[j][3]);
    }
}

// ---------------- K4b: combine split-KV partials -> fp16 hi/lo --------------
__global__ void __launch_bounds__(256) combine_kernel() {
    int idx = blockIdx.x * 256 + threadIdx.x;   // 2 cols per thread
    if (idx >= HW * DIM / 2) return;
    int row = idx / (DIM / 2);
    int cc = (idx - row * (DIM / 2)) * 2;
    int head = cc >> 6;
    float l = g_lpart[(size_t)head * HW + row]
            + g_lpart[(size_t)NH * HW + (size_t)head * HW + row];
    float inv = 1.f / l;
    size_t o = (size_t)row * DIM + cc;
    float2 o0 = *(const float2*)&g_opart[o];
    float2 o1 = *(const float2*)&g_opart[(size_t)HW * DIM + o];
    uint32_t h, lo;
    split2h((o0.x + o1.x) * inv, (o0.y + o1.y) * inv, h, lo);
    *(uint32_t*)&g_oph[o] = h;
    *(uint32_t*)&g_opl[o] = lo;
}

// ---------------- launch -----------------------------------------------------
extern "C" void kernel_launch(void* const* d_in, const int* in_sizes, int n_in,
                              void* d_out, int out_size) {
    const float* x     = (const float*)d_in[0];
    const float* Wqkv  = (const float*)d_in[1];
    const float* bqkv  = (const float*)d_in[2];
    const float* FacTu = (const float*)d_in[3];
    const float* FacTv = (const float*)d_in[4];
    const float* qF    = (const float*)d_in[5];
    const float* vF    = (const float*)d_in[6];
    const float* rph   = (const float*)d_in[7];
    const float* rpw   = (const float*)d_in[8];
    const float* Wproj = (const float*)d_in[9];
    const float* bproj = (const float*)d_in[10];
    float* out = (float*)d_out;

    void *pQkv, *pXh, *pXl, *pOph, *pOpl, *pWqT_h, *pWpT_h;
    cudaGetSymbolAddress(&pQkv, g_qkv);
    cudaGetSymbolAddress(&pXh, g_xh);
    cudaGetSymbolAddress(&pXl, g_xl);
    cudaGetSymbolAddress(&pOph, g_oph);
    cudaGetSymbolAddress(&pOpl, g_opl);
    cudaGetSymbolAddress(&pWqT_h, g_wqkvT_h);
    cudaGetSymbolAddress(&pWpT_h, g_wprojT_h);

    cudaFuncSetAttribute(attn_mma_kernel,
                         cudaFuncAttributeMaxDynamicSharedMemorySize, (int)SM_TOT);
    cudaFuncSetAttribute(hgemm_f16,
                         cudaFuncAttributeMaxDynamicSharedMemorySize, (int)HG_SMEM);

    fact_small_kernel<<<(DIM * RANK * 2 + 255) / 256, 256>>>(FacTu, qF, vF);
    xsplit_kernel<<<(HW * DIM / 4 + 255) / 256, 256>>>(x);

    {   // Wqkv (+delta) -> transposed fp16
        dim3 grid((3 * DIM) / 32, DIM / 32);
        wsplit_kernel<<<grid, 256>>>(Wqkv, FacTv, (__half*)pWqT_h, 3 * DIM, 1);
    }
    {   // Wproj -> transposed fp16
        dim3 grid(DIM / 32, DIM / 32);
        wsplit_kernel<<<grid, 256>>>(Wproj, FacTv, (__half*)pWpT_h, DIM, 0);
    }
    {   // qkv GEMM, fused K/V fp16 epilogue (mode 1)
        dim3 grid((3 * DIM) / 128, HW / 96);
        hgemm_f16<<<grid, 256, HG_SMEM>>>((const __half*)pXh, (const __half*)pXl,
                                          (const __half*)pWqT_h,
                                          bqkv, (float*)pQkv, HW, 3 * DIM, DIM, 1);
    }
    {   // rel-pos tables (pre-scaled by log2e)
        dim3 grid(GH, NH, 2);
        rel_tab2_kernel<<<grid, 256>>>(rph, rpw);
    }
    {   // pipelined split-KV fp16 single-pass attention
        dim3 grid(HW / 128, NH, KSPLIT);
        attn_mma_kernel<<<grid, 256, SM_TOT>>>();
    }
    {   // combine partials
        combine_kernel<<<(HW * DIM / 2 + 255) / 256, 256>>>();
    }
    {   // out = opre @ Wproj + bproj (mode 0)
        dim3 grid(DIM / 128, HW / 96);
        hgemm_f16<<<grid, 256, HG_SMEM>>>((const __half*)pOph, (const __half*)pOpl,
                                          (const __half*)pWpT_h,
                                          bproj, out, HW, DIM, DIM, 0);
    }
}